// round 2
// baseline (speedup 1.0000x reference)
#include <cuda_runtime.h>
#include <math.h>

// Problem constants
#define B_   8
#define T_   1024
#define C_   768
#define H_   12
#define HD_  64
#define M_   (B_ * T_)      // 8192
#define N3C  (3 * C_)       // 2304

// ---------------- scratch (device globals; no allocations allowed) ----------
__device__ float g_Q[B_ * H_ * T_ * HD_];     // [B,H,T,HD], pre-scaled by 1/8
__device__ float g_K[B_ * H_ * T_ * HD_];
__device__ float g_V[B_ * H_ * T_ * HD_];
__device__ float g_meanV[B_ * H_ * HD_];
__device__ float g_att[B_ * T_ * C_];         // attention output, [B,T,C]

// =====================================================================
// SGEMM: 128x128 block tile, BK=16, 256 threads, 8x8 per thread
// =====================================================================
#define BM 128
#define BN 128
#define BK 16

// ---- QKV GEMM: x[8192,768] @ W_attn[768,2304] + b_attn, scatter to Q/K/V ---
__global__ void __launch_bounds__(256)
gemm_qkv_kernel(const float* __restrict__ A, const float* __restrict__ Bw,
                const float* __restrict__ bias)
{
    __shared__ float As[BK][BM + 4];
    __shared__ float Bs[BK][BN];

    const int tid = threadIdx.x;
    const int tc = tid & 15;          // 0..15 -> output cols tc*8..+7
    const int tr = tid >> 4;          // 0..15 -> output rows tr*8..+7
    const int m0 = blockIdx.y * BM;
    const int n0 = blockIdx.x * BN;

    float acc[8][8];
#pragma unroll
    for (int i = 0; i < 8; i++)
#pragma unroll
        for (int j = 0; j < 8; j++) acc[i][j] = 0.f;

    for (int k0 = 0; k0 < C_; k0 += BK) {
        // load A tile: 128 x 16 (transposed into As[k][m])
#pragma unroll
        for (int i = 0; i < 2; i++) {
            int f = tid + i * 256;            // 0..511 float4s
            int row = f >> 2;
            int kc = (f & 3) * 4;
            float4 v = *(const float4*)(A + (size_t)(m0 + row) * C_ + k0 + kc);
            As[kc + 0][row] = v.x;
            As[kc + 1][row] = v.y;
            As[kc + 2][row] = v.z;
            As[kc + 3][row] = v.w;
        }
        // load B tile: 16 x 128
#pragma unroll
        for (int i = 0; i < 2; i++) {
            int f = tid + i * 256;
            int row = f >> 5;                 // 0..15
            int nc = (f & 31) * 4;
            *(float4*)(&Bs[row][nc]) =
                *(const float4*)(Bw + (size_t)(k0 + row) * N3C + n0 + nc);
        }
        __syncthreads();

#pragma unroll
        for (int k = 0; k < BK; k++) {
            float a[8], bb[8];
            *(float4*)(a)     = *(const float4*)(&As[k][tr * 8]);
            *(float4*)(a + 4) = *(const float4*)(&As[k][tr * 8 + 4]);
            *(float4*)(bb)     = *(const float4*)(&Bs[k][tc * 8]);
            *(float4*)(bb + 4) = *(const float4*)(&Bs[k][tc * 8 + 4]);
#pragma unroll
            for (int i = 0; i < 8; i++)
#pragma unroll
                for (int j = 0; j < 8; j++) acc[i][j] += a[i] * bb[j];
        }
        __syncthreads();
    }

    // epilogue: bias, scatter into Q/K/V with [B,H,T,HD] layout (Q scaled)
#pragma unroll
    for (int i = 0; i < 8; i++) {
        int m = m0 + tr * 8 + i;
        int b = m >> 10;          // /1024
        int t = m & 1023;
#pragma unroll
        for (int j = 0; j < 8; j++) {
            int n = n0 + tc * 8 + j;
            float v = acc[i][j] + bias[n];
            int which = n / C_;
            int c = n - which * C_;
            int h = c >> 6;
            int d = c & 63;
            size_t idx = ((size_t)(b * H_ + h) * T_ + t) * HD_ + d;
            if (which == 0)       g_Q[idx] = v * 0.125f;   // fold 1/sqrt(64)
            else if (which == 1)  g_K[idx] = v;
            else                  g_V[idx] = v;
        }
    }
}

// ---- Proj GEMM: g_att[8192,768] @ W_proj[768,768] + b_proj -> out ----------
__global__ void __launch_bounds__(256)
gemm_proj_kernel(const float* __restrict__ Bw, const float* __restrict__ bias,
                 float* __restrict__ out)
{
    __shared__ float As[BK][BM + 4];
    __shared__ float Bs[BK][BN];

    const int tid = threadIdx.x;
    const int tc = tid & 15;
    const int tr = tid >> 4;
    const int m0 = blockIdx.y * BM;
    const int n0 = blockIdx.x * BN;

    float acc[8][8];
#pragma unroll
    for (int i = 0; i < 8; i++)
#pragma unroll
        for (int j = 0; j < 8; j++) acc[i][j] = 0.f;

    for (int k0 = 0; k0 < C_; k0 += BK) {
#pragma unroll
        for (int i = 0; i < 2; i++) {
            int f = tid + i * 256;
            int row = f >> 2;
            int kc = (f & 3) * 4;
            float4 v = *(const float4*)(g_att + (size_t)(m0 + row) * C_ + k0 + kc);
            As[kc + 0][row] = v.x;
            As[kc + 1][row] = v.y;
            As[kc + 2][row] = v.z;
            As[kc + 3][row] = v.w;
        }
#pragma unroll
        for (int i = 0; i < 2; i++) {
            int f = tid + i * 256;
            int row = f >> 5;
            int nc = (f & 31) * 4;
            *(float4*)(&Bs[row][nc]) =
                *(const float4*)(Bw + (size_t)(k0 + row) * C_ + n0 + nc);
        }
        __syncthreads();

#pragma unroll
        for (int k = 0; k < BK; k++) {
            float a[8], bb[8];
            *(float4*)(a)     = *(const float4*)(&As[k][tr * 8]);
            *(float4*)(a + 4) = *(const float4*)(&As[k][tr * 8 + 4]);
            *(float4*)(bb)     = *(const float4*)(&Bs[k][tc * 8]);
            *(float4*)(bb + 4) = *(const float4*)(&Bs[k][tc * 8 + 4]);
#pragma unroll
            for (int i = 0; i < 8; i++)
#pragma unroll
                for (int j = 0; j < 8; j++) acc[i][j] += a[i] * bb[j];
        }
        __syncthreads();
    }

#pragma unroll
    for (int i = 0; i < 8; i++) {
        int m = m0 + tr * 8 + i;
#pragma unroll
        for (int j = 0; j < 8; j += 4) {
            int n = n0 + tc * 8 + j;
            float4 v;
            v.x = acc[i][j + 0] + bias[n + 0];
            v.y = acc[i][j + 1] + bias[n + 1];
            v.z = acc[i][j + 2] + bias[n + 2];
            v.w = acc[i][j + 3] + bias[n + 3];
            *(float4*)(out + (size_t)m * C_ + n) = v;
        }
    }
}

// =====================================================================
// meanV: masked rows output uniform softmax => mean over ALL T of V
// =====================================================================
__global__ void meanv_kernel()
{
    __shared__ float red[256];
    const int bh = blockIdx.x;              // 0..95
    const int tid = threadIdx.x;
    const int d = tid & 63;
    const int part = tid >> 6;              // 0..3
    const size_t base = (size_t)bh * T_ * HD_;
    float s = 0.f;
    const int t0 = part * 256;
    for (int t = t0; t < t0 + 256; t++) s += g_V[base + (size_t)t * HD_ + d];
    red[tid] = s;
    __syncthreads();
    if (part == 0)
        g_meanV[bh * HD_ + d] =
            (red[d] + red[d + 64] + red[d + 128] + red[d + 192]) * (1.0f / 1024.0f);
}

// =====================================================================
// Flash-style causal attention: 64-query tile per block, fp32
//   grid = (16 qtiles, 96 bh), 256 threads (16x16 -> 4x4 register tiles)
// =====================================================================
#define QT 64
#define KT 64
#define PAD_LD 68   // 64 + 4 floats padding (keeps 16B alignment)

__global__ void __launch_bounds__(256)
attn_kernel(const int* __restrict__ mask)
{
    extern __shared__ float sh[];
    float* sQt = sh;                          // [HD][PAD_LD]  (d-major)
    float* sKt = sQt + HD_ * PAD_LD;          // [HD][PAD_LD]  (d-major)
    float* sV  = sKt + HD_ * PAD_LD;          // [KT][PAD_LD]  (key-major)
    float* sS  = sV + KT * PAD_LD;            // [QT][PAD_LD]
    float* sM  = sS + QT * PAD_LD;            // [QT]
    float* sL  = sM + QT;                     // [QT]
    float* sCorr = sL + QT;                   // [QT]

    const int tid = threadIdx.x;
    const int tx = tid & 15;
    const int ty = tid >> 4;
    const int r0 = ty * 4;
    const int c0 = tx * 4;

    const int qt = blockIdx.x;
    const int bh = blockIdx.y;
    const int b = bh / H_;
    const int h = bh - b * H_;
    const int q0 = qt * QT;

    // load Q tile transposed: sQt[d][q]
    {
        const size_t base_q = ((size_t)bh * T_ + q0) * HD_;
#pragma unroll
        for (int i = 0; i < 4; i++) {
            int f = tid + i * 256;             // 0..1023 float4s
            int q = f >> 4;
            int dv = (f & 15) * 4;
            float4 v = *(const float4*)(g_Q + base_q + (size_t)q * HD_ + dv);
            sQt[(dv + 0) * PAD_LD + q] = v.x;
            sQt[(dv + 1) * PAD_LD + q] = v.y;
            sQt[(dv + 2) * PAD_LD + q] = v.z;
            sQt[(dv + 3) * PAD_LD + q] = v.w;
        }
    }
    if (tid < QT) { sM[tid] = -1e30f; sL[tid] = 0.f; }

    float o[4][4];
#pragma unroll
    for (int i = 0; i < 4; i++)
#pragma unroll
        for (int j = 0; j < 4; j++) o[i][j] = 0.f;

    for (int kt = 0; kt <= qt; kt++) {
        __syncthreads();   // protects sQt/sM/sL init (1st iter) and tile reuse

        // load K tile transposed (sKt[d][k]) and V tile (sV[k][d])
        {
            const size_t base_k = ((size_t)bh * T_ + kt * KT) * HD_;
#pragma unroll
            for (int i = 0; i < 4; i++) {
                int f = tid + i * 256;
                int r = f >> 4;
                int dv = (f & 15) * 4;
                float4 kv = *(const float4*)(g_K + base_k + (size_t)r * HD_ + dv);
                sKt[(dv + 0) * PAD_LD + r] = kv.x;
                sKt[(dv + 1) * PAD_LD + r] = kv.y;
                sKt[(dv + 2) * PAD_LD + r] = kv.z;
                sKt[(dv + 3) * PAD_LD + r] = kv.w;
                float4 vv = *(const float4*)(g_V + base_k + (size_t)r * HD_ + dv);
                *(float4*)(&sV[r * PAD_LD + dv]) = vv;
            }
        }
        __syncthreads();

        // S tile = Q @ K^T  (4x4 per thread)
        float s[4][4];
#pragma unroll
        for (int i = 0; i < 4; i++)
#pragma unroll
            for (int j = 0; j < 4; j++) s[i][j] = 0.f;

#pragma unroll 4
        for (int d = 0; d < HD_; d++) {
            float4 qv = *(const float4*)(&sQt[d * PAD_LD + r0]);
            float4 kv = *(const float4*)(&sKt[d * PAD_LD + c0]);
            float qa[4] = {qv.x, qv.y, qv.z, qv.w};
            float ka[4] = {kv.x, kv.y, kv.z, kv.w};
#pragma unroll
            for (int i = 0; i < 4; i++)
#pragma unroll
                for (int j = 0; j < 4; j++) s[i][j] += qa[i] * ka[j];
        }

        // causal mask on the diagonal tile
        if (kt == qt) {
#pragma unroll
            for (int i = 0; i < 4; i++)
#pragma unroll
                for (int j = 0; j < 4; j++)
                    if (c0 + j > r0 + i) s[i][j] = -1e30f;
        }

        // stage S to shared
#pragma unroll
        for (int i = 0; i < 4; i++) {
            float4 v = make_float4(s[i][0], s[i][1], s[i][2], s[i][3]);
            *(float4*)(&sS[(r0 + i) * PAD_LD + c0]) = v;
        }
        __syncthreads();

        // per-row online softmax statistics (one thread per query row)
        if (tid < QT) {
            const int r = tid;
            float tm = -1e30f;
            const float* row = &sS[r * PAD_LD];
#pragma unroll 8
            for (int c = 0; c < KT; c++) tm = fmaxf(tm, row[c]);
            float m_old = sM[r];
            float m_new = fmaxf(m_old, tm);
            float corr = __expf(m_old - m_new);
            float lsum = 0.f;
            float* roww = &sS[r * PAD_LD];
#pragma unroll 8
            for (int c = 0; c < KT; c++) {
                float p = __expf(roww[c] - m_new);
                roww[c] = p;
                lsum += p;
            }
            sL[r] = sL[r] * corr + lsum;
            sM[r] = m_new;
            sCorr[r] = corr;
        }
        __syncthreads();

        // rescale O and accumulate P @ V
        float cr[4];
#pragma unroll
        for (int i = 0; i < 4; i++) cr[i] = sCorr[r0 + i];
#pragma unroll
        for (int i = 0; i < 4; i++)
#pragma unroll
            for (int j = 0; j < 4; j++) o[i][j] *= cr[i];

#pragma unroll 4
        for (int jk = 0; jk < KT; jk++) {
            float4 vv = *(const float4*)(&sV[jk * PAD_LD + c0]);
            float va[4] = {vv.x, vv.y, vv.z, vv.w};
            float p0 = sS[(r0 + 0) * PAD_LD + jk];
            float p1 = sS[(r0 + 1) * PAD_LD + jk];
            float p2 = sS[(r0 + 2) * PAD_LD + jk];
            float p3 = sS[(r0 + 3) * PAD_LD + jk];
#pragma unroll
            for (int j = 0; j < 4; j++) {
                o[0][j] += p0 * va[j];
                o[1][j] += p1 * va[j];
                o[2][j] += p2 * va[j];
                o[3][j] += p3 * va[j];
            }
        }
    }

    // epilogue: normalize, masked-row override, write [B,T,C]
#pragma unroll
    for (int i = 0; i < 4; i++) {
        int qrow = q0 + r0 + i;
        float inv_l = 1.f / sL[r0 + i];
        bool row_masked = (mask[b * T_ + qrow] == 0);
        float4 v;
        if (row_masked) {
            const float* mv = &g_meanV[bh * HD_ + c0];
            v = make_float4(mv[0], mv[1], mv[2], mv[3]);
        } else {
            v = make_float4(o[i][0] * inv_l, o[i][1] * inv_l,
                            o[i][2] * inv_l, o[i][3] * inv_l);
        }
        *(float4*)(&g_att[((size_t)b * T_ + qrow) * C_ + h * HD_ + c0]) = v;
    }
}

// =====================================================================
// launcher
// =====================================================================
extern "C" void kernel_launch(void* const* d_in, const int* in_sizes, int n_in,
                              void* d_out, int out_size)
{
    const float* x      = (const float*)d_in[0];
    const int*   mask   = (const int*)d_in[1];
    const float* W_attn = (const float*)d_in[2];
    const float* b_attn = (const float*)d_in[3];
    const float* W_proj = (const float*)d_in[4];
    const float* b_proj = (const float*)d_in[5];
    float* out = (float*)d_out;

    // 1) QKV projection + scatter
    {
        dim3 grid(N3C / BN, M_ / BM);   // (18, 64)
        gemm_qkv_kernel<<<grid, 256>>>(x, W_attn, b_attn);
    }
    // 2) per-(b,h) mean of V (for masked rows)
    meanv_kernel<<<B_ * H_, 256>>>();
    // 3) causal flash attention
    {
        const int smem = (2 * HD_ * PAD_LD + KT * PAD_LD + QT * PAD_LD + 3 * QT)
                         * (int)sizeof(float);   // ~70.4 KB
        cudaFuncSetAttribute(attn_kernel,
                             cudaFuncAttributeMaxDynamicSharedMemorySize, smem);
        dim3 grid(T_ / QT, B_ * H_);    // (16, 96)
        attn_kernel<<<grid, 256, smem>>>(mask);
    }
    // 4) output projection
    {
        dim3 grid(C_ / BN, M_ / BM);    // (6, 64)
        gemm_proj_kernel<<<grid, 256>>>(W_proj, b_proj, out);
    }
}

// round 9
// speedup vs baseline: 1.7176x; 1.7176x over previous
#include <cuda_runtime.h>
#include <cuda_bf16.h>
#include <cstdint>
#include <math.h>

// Problem constants
#define B_   8
#define T_   1024
#define C_   768
#define H_   12
#define HD_  64
#define M_   (B_ * T_)      // 8192
#define N3C  (3 * C_)       // 2304
#define KDIM 768

// ---------------- scratch (device globals; no allocations allowed) ----------
__device__ float g_Q[B_ * H_ * T_ * HD_];     // [B,H,T,HD], pre-scaled by 1/8
__device__ float g_K[B_ * H_ * T_ * HD_];
__device__ float g_V[B_ * H_ * T_ * HD_];
__device__ float g_meanV[B_ * H_ * HD_];

// bf16 split operands
__device__ __nv_bfloat16 g_Xh[M_ * C_];       // x hi  [8192,768]
__device__ __nv_bfloat16 g_Xl[M_ * C_];       // x lo
__device__ __nv_bfloat16 g_WaTh[N3C * C_];    // W_attn^T hi [2304,768] (k-contig)
__device__ __nv_bfloat16 g_WaTl[N3C * C_];
__device__ __nv_bfloat16 g_WpTh[C_ * C_];     // W_proj^T hi [768,768]
__device__ __nv_bfloat16 g_WpTl[C_ * C_];
__device__ __nv_bfloat16 g_ATTh[M_ * C_];     // attention out hi [8192,768]
__device__ __nv_bfloat16 g_ATTl[M_ * C_];

// =====================================================================
// family-common PTX helpers (NO tcgen05 — ptx target is sm_103 base)
// =====================================================================
__device__ __forceinline__ uint32_t smem_to_u32(const void* p) {
    uint32_t a;
    asm("{ .reg .u64 t; cvta.to.shared.u64 t, %1; cvt.u32.u64 %0, t; }"
        : "=r"(a) : "l"(p));
    return a;
}

__device__ __forceinline__ void cp16(uint32_t saddr, const void* g) {
    asm volatile("cp.async.cg.shared.global [%0], [%1], 16;"
                 :: "r"(saddr), "l"(g));
}
#define CP_COMMIT() asm volatile("cp.async.commit_group;")
#define CP_WAIT0()  asm volatile("cp.async.wait_group 0;")

__device__ __forceinline__ void ldmx4(uint32_t* r, uint32_t addr) {
    asm volatile("ldmatrix.sync.aligned.m8n8.x4.shared.b16 {%0,%1,%2,%3}, [%4];"
                 : "=r"(r[0]), "=r"(r[1]), "=r"(r[2]), "=r"(r[3]) : "r"(addr));
}

__device__ __forceinline__ void mma_bf16(float* d, const uint32_t* a,
                                         uint32_t b0, uint32_t b1) {
    asm volatile(
        "mma.sync.aligned.m16n8k16.row.col.f32.bf16.bf16.f32 "
        "{%0,%1,%2,%3}, {%4,%5,%6,%7}, {%8,%9}, {%0,%1,%2,%3};"
        : "+f"(d[0]), "+f"(d[1]), "+f"(d[2]), "+f"(d[3])
        : "r"(a[0]), "r"(a[1]), "r"(a[2]), "r"(a[3]), "r"(b0), "r"(b1));
}

// smem tile layout: [128 rows][32 bf16] = row stride 64B, 4x 16B chunks/row,
// chunk position swizzled: c_sw = c ^ ((row>>1)&3)  (conflict-free ldmatrix)
#define TILE_BYTES 8192
#define STAGE_BYTES (4 * TILE_BYTES)   // Ah, Al, Bh, Bl
#define GEMM_SMEM (2 * STAGE_BYTES)    // 65536, double buffered

__device__ __forceinline__ uint32_t sw_off(int row, int c) {
    return (uint32_t)(row * 64 + ((c ^ ((row >> 1) & 3)) * 16));
}

// issue cp.async for one stage (all 4 tiles), k-slice [k0, k0+32)
__device__ __forceinline__ void load_stage(
    const __nv_bfloat16* Ah, const __nv_bfloat16* Al,
    const __nv_bfloat16* Bh, const __nv_bfloat16* Bl,
    int m0, int n0, int k0, uint32_t sbase, int tid)
{
#pragma unroll
    for (int i = 0; i < 2; i++) {
        int q = tid + i * 256;        // 512 chunks per tile
        int row = q >> 2;
        int c = q & 3;
        uint32_t so = sw_off(row, c);
        size_t goA = (size_t)(m0 + row) * KDIM + k0 + c * 8;
        size_t goB = (size_t)(n0 + row) * KDIM + k0 + c * 8;
        cp16(sbase + 0 * TILE_BYTES + so, Ah + goA);
        cp16(sbase + 1 * TILE_BYTES + so, Al + goA);
        cp16(sbase + 2 * TILE_BYTES + so, Bh + goB);
        cp16(sbase + 3 * TILE_BYTES + so, Bl + goB);
    }
}

// compute one BK=32 stage: acc[mt][nt][4] += split-bf16 products
__device__ __forceinline__ void compute_stage(uint32_t sbase, int lane,
                                              int m_warp, int n_warp,
                                              float acc[4][4][4])
{
    const uint32_t aBase  = sbase;
    const uint32_t alBase = sbase + TILE_BYTES;
    const uint32_t bhBase = sbase + 2 * TILE_BYTES;
    const uint32_t blBase = sbase + 3 * TILE_BYTES;

    const int a_r  = lane & 15;
    const int a_kh = (lane >> 4) & 1;
    const int b_r  = (lane & 7) + ((lane >> 4) & 1) * 8;
    const int b_kh = (lane >> 3) & 1;

#pragma unroll
    for (int s = 0; s < 2; s++) {          // two k16 steps
        uint32_t bh[8], bl[8];
#pragma unroll
        for (int p = 0; p < 2; p++) {      // n-tile pairs (16 n each)
            int rn = n_warp + p * 16 + b_r;
            int c = s * 2 + b_kh;
            uint32_t off = sw_off(rn, c);
            ldmx4(&bh[p * 4], bhBase + off);
            ldmx4(&bl[p * 4], blBase + off);
        }
#pragma unroll
        for (int mt = 0; mt < 4; mt++) {
            int rm = m_warp + mt * 16 + a_r;
            int c = s * 2 + a_kh;
            uint32_t off = sw_off(rm, c);
            uint32_t ah[4], al[4];
            ldmx4(ah, aBase + off);
            ldmx4(al, alBase + off);
#pragma unroll
            for (int nt = 0; nt < 4; nt++) {
                float* d = acc[mt][nt];
                mma_bf16(d, ah, bh[nt * 2], bh[nt * 2 + 1]);   // hi*hi
                mma_bf16(d, ah, bl[nt * 2], bl[nt * 2 + 1]);   // hi*lo
                mma_bf16(d, al, bh[nt * 2], bh[nt * 2 + 1]);   // lo*hi
            }
        }
    }
}

__device__ __forceinline__ void gemm_mainloop_mma(
    const __nv_bfloat16* Ah, const __nv_bfloat16* Al,
    const __nv_bfloat16* Bh, const __nv_bfloat16* Bl,
    int m0, int n0, uint32_t smem_u, int tid,
    int m_warp, int n_warp, float acc[4][4][4])
{
    const int lane = tid & 31;
    const int NIT = KDIM / 32;     // 24

    load_stage(Ah, Al, Bh, Bl, m0, n0, 0, smem_u, tid);
    CP_COMMIT();

    for (int it = 0; it < NIT; it++) {
        CP_WAIT0();
        __syncthreads();
        if (it + 1 < NIT) {
            load_stage(Ah, Al, Bh, Bl, m0, n0, (it + 1) * 32,
                       smem_u + ((it + 1) & 1) * STAGE_BYTES, tid);
            CP_COMMIT();
        }
        compute_stage(smem_u + (it & 1) * STAGE_BYTES, lane, m_warp, n_warp, acc);
        __syncthreads();
    }
}

// ---- QKV: X @ WaT^T -> scatter Q/K/V (+bias, Q*0.125) ---------------------
__global__ void __launch_bounds__(256, 2)
gemm_qkv_mma(const float* __restrict__ bias)
{
    extern __shared__ char smem[];
    uint32_t smem_u = smem_to_u32(smem);
    const int tid = threadIdx.x;
    const int wid = tid >> 5, lane = tid & 31;
    const int m_warp = (wid >> 2) * 64, n_warp = (wid & 3) * 32;
    const int n0 = blockIdx.x * 128, m0 = blockIdx.y * 128;

    float acc[4][4][4];
#pragma unroll
    for (int i = 0; i < 4; i++)
#pragma unroll
        for (int j = 0; j < 4; j++)
#pragma unroll
            for (int k = 0; k < 4; k++) acc[i][j][k] = 0.f;

    gemm_mainloop_mma(g_Xh, g_Xl, g_WaTh, g_WaTl, m0, n0, smem_u, tid,
                      m_warp, n_warp, acc);

    // epilogue: d-frag thread mapping: rows g,g+8; cols 2*tig,2*tig+1
    const int gg = lane >> 2, tig = lane & 3;
#pragma unroll
    for (int mt = 0; mt < 4; mt++) {
#pragma unroll
        for (int nt = 0; nt < 4; nt++) {
            int col = n0 + n_warp + nt * 8 + tig * 2;
            int which = col / C_;
            int c = col - which * C_;
            int h = c >> 6, d = c & 63;
            float bx = bias[col], by = bias[col + 1];
            float* dst = (which == 0) ? g_Q : (which == 1) ? g_K : g_V;
            float scl = (which == 0) ? 0.125f : 1.0f;
#pragma unroll
            for (int rr = 0; rr < 2; rr++) {
                int m = m0 + m_warp + mt * 16 + gg + rr * 8;
                int b = m >> 10, t = m & 1023;
                float2 v;
                v.x = (acc[mt][nt][rr * 2 + 0] + bx) * scl;
                v.y = (acc[mt][nt][rr * 2 + 1] + by) * scl;
                *(float2*)(dst + ((size_t)(b * H_ + h) * T_ + t) * HD_ + d) = v;
            }
        }
    }
}

// ---- Proj: ATT @ WpT^T + b_proj -> out ------------------------------------
__global__ void __launch_bounds__(256, 2)
gemm_proj_mma(const float* __restrict__ bias, float* __restrict__ out)
{
    extern __shared__ char smem[];
    uint32_t smem_u = smem_to_u32(smem);
    const int tid = threadIdx.x;
    const int wid = tid >> 5, lane = tid & 31;
    const int m_warp = (wid >> 2) * 64, n_warp = (wid & 3) * 32;
    const int n0 = blockIdx.x * 128, m0 = blockIdx.y * 128;

    float acc[4][4][4];
#pragma unroll
    for (int i = 0; i < 4; i++)
#pragma unroll
        for (int j = 0; j < 4; j++)
#pragma unroll
            for (int k = 0; k < 4; k++) acc[i][j][k] = 0.f;

    gemm_mainloop_mma(g_ATTh, g_ATTl, g_WpTh, g_WpTl, m0, n0, smem_u, tid,
                      m_warp, n_warp, acc);

    const int gg = lane >> 2, tig = lane & 3;
#pragma unroll
    for (int mt = 0; mt < 4; mt++) {
#pragma unroll
        for (int nt = 0; nt < 4; nt++) {
            int col = n0 + n_warp + nt * 8 + tig * 2;
            float bx = bias[col], by = bias[col + 1];
#pragma unroll
            for (int rr = 0; rr < 2; rr++) {
                int m = m0 + m_warp + mt * 16 + gg + rr * 8;
                float2 v;
                v.x = acc[mt][nt][rr * 2 + 0] + bx;
                v.y = acc[mt][nt][rr * 2 + 1] + by;
                *(float2*)(out + (size_t)m * C_ + col) = v;
            }
        }
    }
}

// =====================================================================
// preprocessing: fp32 -> split bf16 (hi + lo)
// =====================================================================
__device__ __forceinline__ void split_bf16(float v, __nv_bfloat16& h, __nv_bfloat16& l) {
    h = __float2bfloat16(v);
    l = __float2bfloat16(v - __bfloat162float(h));
}

__global__ void split_kernel(const float* __restrict__ X,
                             __nv_bfloat16* __restrict__ Xh,
                             __nv_bfloat16* __restrict__ Xl, int n4)
{
    int idx = blockIdx.x * blockDim.x + threadIdx.x;
    if (idx >= n4) return;
    float4 v = ((const float4*)X)[idx];
    __nv_bfloat16 h0, h1, h2, h3, l0, l1, l2, l3;
    split_bf16(v.x, h0, l0); split_bf16(v.y, h1, l1);
    split_bf16(v.z, h2, l2); split_bf16(v.w, h3, l3);
    __nv_bfloat162* ph = (__nv_bfloat162*)(Xh + 4 * (size_t)idx);
    __nv_bfloat162* pl = (__nv_bfloat162*)(Xl + 4 * (size_t)idx);
    ph[0] = __nv_bfloat162(h0, h1); ph[1] = __nv_bfloat162(h2, h3);
    pl[0] = __nv_bfloat162(l0, l1); pl[1] = __nv_bfloat162(l2, l3);
}

// W [K, N] fp32 -> Th/Tl [N, K] bf16 (transpose + split)
__global__ void transpose_split_kernel(const float* __restrict__ W,
                                       __nv_bfloat16* __restrict__ Th,
                                       __nv_bfloat16* __restrict__ Tl,
                                       int K, int N)
{
    __shared__ float tile[32][33];
    const int nb = blockIdx.x * 32, kb = blockIdx.y * 32;
    const int tx = threadIdx.x, ty = threadIdx.y;  // 32 x 8
#pragma unroll
    for (int i = 0; i < 32; i += 8)
        tile[ty + i][tx] = W[(size_t)(kb + ty + i) * N + nb + tx];
    __syncthreads();
#pragma unroll
    for (int i = 0; i < 32; i += 8) {
        float v = tile[tx][ty + i];
        int n = nb + ty + i, k = kb + tx;
        __nv_bfloat16 h, l;
        split_bf16(v, h, l);
        Th[(size_t)n * K + k] = h;
        Tl[(size_t)n * K + k] = l;
    }
}

// =====================================================================
// meanV: masked rows output uniform softmax => mean over ALL T of V
// =====================================================================
__global__ void meanv_kernel()
{
    __shared__ float red[256];
    const int bh = blockIdx.x;
    const int tid = threadIdx.x;
    const int d = tid & 63;
    const int part = tid >> 6;
    const size_t base = (size_t)bh * T_ * HD_;
    float s = 0.f;
    const int t0 = part * 256;
    for (int t = t0; t < t0 + 256; t++) s += g_V[base + (size_t)t * HD_ + d];
    red[tid] = s;
    __syncthreads();
    if (part == 0)
        g_meanV[bh * HD_ + d] =
            (red[d] + red[d + 64] + red[d + 128] + red[d + 192]) * (1.0f / 1024.0f);
}

// =====================================================================
// Flash-style causal attention (fp32), epilogue emits split-bf16
// =====================================================================
#define QT 64
#define KT 64
#define PAD_LD 68

__global__ void __launch_bounds__(256)
attn_kernel(const int* __restrict__ mask)
{
    extern __shared__ float sh[];
    float* sQt = sh;
    float* sKt = sQt + HD_ * PAD_LD;
    float* sV  = sKt + HD_ * PAD_LD;
    float* sS  = sV + KT * PAD_LD;
    float* sM  = sS + QT * PAD_LD;
    float* sL  = sM + QT;
    float* sCorr = sL + QT;

    const int tid = threadIdx.x;
    const int tx = tid & 15;
    const int ty = tid >> 4;
    const int r0 = ty * 4;
    const int c0 = tx * 4;

    const int qt = blockIdx.x;
    const int bh = blockIdx.y;
    const int b = bh / H_;
    const int h = bh - b * H_;
    const int q0 = qt * QT;

    {
        const size_t base_q = ((size_t)bh * T_ + q0) * HD_;
#pragma unroll
        for (int i = 0; i < 4; i++) {
            int f = tid + i * 256;
            int q = f >> 4;
            int dv = (f & 15) * 4;
            float4 v = *(const float4*)(g_Q + base_q + (size_t)q * HD_ + dv);
            sQt[(dv + 0) * PAD_LD + q] = v.x;
            sQt[(dv + 1) * PAD_LD + q] = v.y;
            sQt[(dv + 2) * PAD_LD + q] = v.z;
            sQt[(dv + 3) * PAD_LD + q] = v.w;
        }
    }
    if (tid < QT) { sM[tid] = -1e30f; sL[tid] = 0.f; }

    float o[4][4];
#pragma unroll
    for (int i = 0; i < 4; i++)
#pragma unroll
        for (int j = 0; j < 4; j++) o[i][j] = 0.f;

    for (int kt = 0; kt <= qt; kt++) {
        __syncthreads();

        {
            const size_t base_k = ((size_t)bh * T_ + kt * KT) * HD_;
#pragma unroll
            for (int i = 0; i < 4; i++) {
                int f = tid + i * 256;
                int r = f >> 4;
                int dv = (f & 15) * 4;
                float4 kv = *(const float4*)(g_K + base_k + (size_t)r * HD_ + dv);
                sKt[(dv + 0) * PAD_LD + r] = kv.x;
                sKt[(dv + 1) * PAD_LD + r] = kv.y;
                sKt[(dv + 2) * PAD_LD + r] = kv.z;
                sKt[(dv + 3) * PAD_LD + r] = kv.w;
                float4 vv = *(const float4*)(g_V + base_k + (size_t)r * HD_ + dv);
                *(float4*)(&sV[r * PAD_LD + dv]) = vv;
            }
        }
        __syncthreads();

        float s[4][4];
#pragma unroll
        for (int i = 0; i < 4; i++)
#pragma unroll
            for (int j = 0; j < 4; j++) s[i][j] = 0.f;

#pragma unroll 4
        for (int d = 0; d < HD_; d++) {
            float4 qv = *(const float4*)(&sQt[d * PAD_LD + r0]);
            float4 kv = *(const float4*)(&sKt[d * PAD_LD + c0]);
            float qa[4] = {qv.x, qv.y, qv.z, qv.w};
            float ka[4] = {kv.x, kv.y, kv.z, kv.w};
#pragma unroll
            for (int i = 0; i < 4; i++)
#pragma unroll
                for (int j = 0; j < 4; j++) s[i][j] += qa[i] * ka[j];
        }

        if (kt == qt) {
#pragma unroll
            for (int i = 0; i < 4; i++)
#pragma unroll
                for (int j = 0; j < 4; j++)
                    if (c0 + j > r0 + i) s[i][j] = -1e30f;
        }

#pragma unroll
        for (int i = 0; i < 4; i++) {
            float4 v = make_float4(s[i][0], s[i][1], s[i][2], s[i][3]);
            *(float4*)(&sS[(r0 + i) * PAD_LD + c0]) = v;
        }
        __syncthreads();

        if (tid < QT) {
            const int r = tid;
            float tm = -1e30f;
            const float* row = &sS[r * PAD_LD];
#pragma unroll 8
            for (int c = 0; c < KT; c++) tm = fmaxf(tm, row[c]);
            float m_old = sM[r];
            float m_new = fmaxf(m_old, tm);
            float corr = __expf(m_old - m_new);
            float lsum = 0.f;
            float* roww = &sS[r * PAD_LD];
#pragma unroll 8
            for (int c = 0; c < KT; c++) {
                float p = __expf(roww[c] - m_new);
                roww[c] = p;
                lsum += p;
            }
            sL[r] = sL[r] * corr + lsum;
            sM[r] = m_new;
            sCorr[r] = corr;
        }
        __syncthreads();

        float cr[4];
#pragma unroll
        for (int i = 0; i < 4; i++) cr[i] = sCorr[r0 + i];
#pragma unroll
        for (int i = 0; i < 4; i++)
#pragma unroll
            for (int j = 0; j < 4; j++) o[i][j] *= cr[i];

#pragma unroll 4
        for (int jk = 0; jk < KT; jk++) {
            float4 vv = *(const float4*)(&sV[jk * PAD_LD + c0]);
            float va[4] = {vv.x, vv.y, vv.z, vv.w};
            float p0 = sS[(r0 + 0) * PAD_LD + jk];
            float p1 = sS[(r0 + 1) * PAD_LD + jk];
            float p2 = sS[(r0 + 2) * PAD_LD + jk];
            float p3 = sS[(r0 + 3) * PAD_LD + jk];
#pragma unroll
            for (int j = 0; j < 4; j++) {
                o[0][j] += p0 * va[j];
                o[1][j] += p1 * va[j];
                o[2][j] += p2 * va[j];
                o[3][j] += p3 * va[j];
            }
        }
    }

    // epilogue: normalize, masked-row override, split-bf16 store [B,T,C]
#pragma unroll
    for (int i = 0; i < 4; i++) {
        int qrow = q0 + r0 + i;
        float inv_l = 1.f / sL[r0 + i];
        bool row_masked = (mask[b * T_ + qrow] == 0);
        float vals[4];
        if (row_masked) {
            const float* mv = &g_meanV[bh * HD_ + c0];
            vals[0] = mv[0]; vals[1] = mv[1]; vals[2] = mv[2]; vals[3] = mv[3];
        } else {
            vals[0] = o[i][0] * inv_l; vals[1] = o[i][1] * inv_l;
            vals[2] = o[i][2] * inv_l; vals[3] = o[i][3] * inv_l;
        }
        size_t base = ((size_t)b * T_ + qrow) * C_ + h * HD_ + c0;
        __nv_bfloat16 hh[4], ll[4];
#pragma unroll
        for (int j = 0; j < 4; j++) split_bf16(vals[j], hh[j], ll[j]);
        *(__nv_bfloat162*)(g_ATTh + base)     = __nv_bfloat162(hh[0], hh[1]);
        *(__nv_bfloat162*)(g_ATTh + base + 2) = __nv_bfloat162(hh[2], hh[3]);
        *(__nv_bfloat162*)(g_ATTl + base)     = __nv_bfloat162(ll[0], ll[1]);
        *(__nv_bfloat162*)(g_ATTl + base + 2) = __nv_bfloat162(ll[2], ll[3]);
    }
}

// =====================================================================
// launcher
// =====================================================================
extern "C" void kernel_launch(void* const* d_in, const int* in_sizes, int n_in,
                              void* d_out, int out_size)
{
    const float* x      = (const float*)d_in[0];
    const int*   mask   = (const int*)d_in[1];
    const float* W_attn = (const float*)d_in[2];
    const float* b_attn = (const float*)d_in[3];
    const float* W_proj = (const float*)d_in[4];
    const float* b_proj = (const float*)d_in[5];
    float* out = (float*)d_out;

    __nv_bfloat16 *p_Xh, *p_Xl, *p_WaTh, *p_WaTl, *p_WpTh, *p_WpTl;
    cudaGetSymbolAddress((void**)&p_Xh, g_Xh);
    cudaGetSymbolAddress((void**)&p_Xl, g_Xl);
    cudaGetSymbolAddress((void**)&p_WaTh, g_WaTh);
    cudaGetSymbolAddress((void**)&p_WaTl, g_WaTl);
    cudaGetSymbolAddress((void**)&p_WpTh, g_WpTh);
    cudaGetSymbolAddress((void**)&p_WpTl, g_WpTl);

    // 0) split / transpose-split preprocessing
    split_kernel<<<(M_ * C_ / 4 + 255) / 256, 256>>>(x, p_Xh, p_Xl, M_ * C_ / 4);
    transpose_split_kernel<<<dim3(N3C / 32, C_ / 32), dim3(32, 8)>>>(
        W_attn, p_WaTh, p_WaTl, C_, N3C);
    transpose_split_kernel<<<dim3(C_ / 32, C_ / 32), dim3(32, 8)>>>(
        W_proj, p_WpTh, p_WpTl, C_, C_);

    // 1) QKV projection via mma.sync bf16 (split-3)
    {
        cudaFuncSetAttribute(gemm_qkv_mma,
                             cudaFuncAttributeMaxDynamicSharedMemorySize, GEMM_SMEM);
        dim3 grid(N3C / 128, M_ / 128);   // (18, 64)
        gemm_qkv_mma<<<grid, 256, GEMM_SMEM>>>(b_attn);
    }
    // 2) per-(b,h) mean of V
    meanv_kernel<<<B_ * H_, 256>>>();
    // 3) causal flash attention (fp32)
    {
        const int smem = (2 * HD_ * PAD_LD + KT * PAD_LD + QT * PAD_LD + 3 * QT)
                         * (int)sizeof(float);
        cudaFuncSetAttribute(attn_kernel,
                             cudaFuncAttributeMaxDynamicSharedMemorySize, smem);
        dim3 grid(T_ / QT, B_ * H_);
        attn_kernel<<<grid, 256, smem>>>(mask);
    }
    // 4) output projection via mma.sync bf16 (split-3)
    {
        cudaFuncSetAttribute(gemm_proj_mma,
                             cudaFuncAttributeMaxDynamicSharedMemorySize, GEMM_SMEM);
        dim3 grid(C_ / 128, M_ / 128);    // (6, 64)
        gemm_proj_mma<<<grid, 256, GEMM_SMEM>>>(b_proj, out);
    }
}

// round 10
// speedup vs baseline: 3.0230x; 1.7600x over previous
#include <cuda_runtime.h>
#include <cuda_bf16.h>
#include <cstdint>
#include <math.h>

// Problem constants
#define B_   8
#define T_   1024
#define C_   768
#define H_   12
#define HD_  64
#define M_   (B_ * T_)      // 8192
#define N3C  (3 * C_)       // 2304
#define KDIM 768
#define QT   64

// ---------------- scratch (device globals; no allocations allowed) ----------
__device__ float g_Q[B_ * H_ * T_ * HD_];     // [B,H,T,HD], scaled by 0.125*log2e
__device__ float g_K[B_ * H_ * T_ * HD_];
__device__ float g_V[B_ * H_ * T_ * HD_];
__device__ float g_meanV[B_ * H_ * HD_];

// bf16 split operands
__device__ __nv_bfloat16 g_Xh[M_ * C_];       // x hi  [8192,768]
__device__ __nv_bfloat16 g_Xl[M_ * C_];       // x lo
__device__ __nv_bfloat16 g_WaTh[N3C * C_];    // W_attn^T hi [2304,768] (k-contig)
__device__ __nv_bfloat16 g_WaTl[N3C * C_];
__device__ __nv_bfloat16 g_WpTh[C_ * C_];     // W_proj^T hi [768,768]
__device__ __nv_bfloat16 g_WpTl[C_ * C_];
__device__ __nv_bfloat16 g_ATTh[M_ * C_];     // attention out hi [8192,768]
__device__ __nv_bfloat16 g_ATTl[M_ * C_];

// =====================================================================
// family-common PTX helpers (NO tcgen05 — ptx target is sm_103 base)
// =====================================================================
__device__ __forceinline__ uint32_t smem_to_u32(const void* p) {
    uint32_t a;
    asm("{ .reg .u64 t; cvta.to.shared.u64 t, %1; cvt.u32.u64 %0, t; }"
        : "=r"(a) : "l"(p));
    return a;
}

__device__ __forceinline__ void cp16(uint32_t saddr, const void* g) {
    asm volatile("cp.async.cg.shared.global [%0], [%1], 16;"
                 :: "r"(saddr), "l"(g));
}
#define CP_COMMIT() asm volatile("cp.async.commit_group;")
#define CP_WAIT0()  asm volatile("cp.async.wait_group 0;")

__device__ __forceinline__ void ldmx4(uint32_t* r, uint32_t addr) {
    asm volatile("ldmatrix.sync.aligned.m8n8.x4.shared.b16 {%0,%1,%2,%3}, [%4];"
                 : "=r"(r[0]), "=r"(r[1]), "=r"(r[2]), "=r"(r[3]) : "r"(addr));
}

__device__ __forceinline__ void mma_bf16(float* d, const uint32_t* a,
                                         uint32_t b0, uint32_t b1) {
    asm volatile(
        "mma.sync.aligned.m16n8k16.row.col.f32.bf16.bf16.f32 "
        "{%0,%1,%2,%3}, {%4,%5,%6,%7}, {%8,%9}, {%0,%1,%2,%3};"
        : "+f"(d[0]), "+f"(d[1]), "+f"(d[2]), "+f"(d[3])
        : "r"(a[0]), "r"(a[1]), "r"(a[2]), "r"(a[3]), "r"(b0), "r"(b1));
}

// pack two fp32 -> bf16x2 (lo = first arg, hi = second)
__device__ __forceinline__ uint32_t pk2(float lo, float hi) {
    uint32_t r;
    asm("cvt.rn.bf16x2.f32 %0, %1, %2;" : "=r"(r) : "f"(hi), "f"(lo));
    return r;
}
__device__ __forceinline__ float lo_f(uint32_t p) { return __uint_as_float(p << 16); }
__device__ __forceinline__ float hi_f(uint32_t p) { return __uint_as_float(p & 0xFFFF0000u); }
__device__ __forceinline__ float ex2f(float x) {
    float r; asm("ex2.approx.f32 %0, %1;" : "=f"(r) : "f"(x)); return r;
}

// =====================================================================
// GEMM (unchanged from R9): 128x128, BK=32, split-3 bf16 mma.sync
// =====================================================================
#define TILE_BYTES 8192
#define STAGE_BYTES (4 * TILE_BYTES)
#define GEMM_SMEM (2 * STAGE_BYTES)

__device__ __forceinline__ uint32_t sw_off(int row, int c) {
    return (uint32_t)(row * 64 + ((c ^ ((row >> 1) & 3)) * 16));
}

__device__ __forceinline__ void load_stage(
    const __nv_bfloat16* Ah, const __nv_bfloat16* Al,
    const __nv_bfloat16* Bh, const __nv_bfloat16* Bl,
    int m0, int n0, int k0, uint32_t sbase, int tid)
{
#pragma unroll
    for (int i = 0; i < 2; i++) {
        int q = tid + i * 256;
        int row = q >> 2;
        int c = q & 3;
        uint32_t so = sw_off(row, c);
        size_t goA = (size_t)(m0 + row) * KDIM + k0 + c * 8;
        size_t goB = (size_t)(n0 + row) * KDIM + k0 + c * 8;
        cp16(sbase + 0 * TILE_BYTES + so, Ah + goA);
        cp16(sbase + 1 * TILE_BYTES + so, Al + goA);
        cp16(sbase + 2 * TILE_BYTES + so, Bh + goB);
        cp16(sbase + 3 * TILE_BYTES + so, Bl + goB);
    }
}

__device__ __forceinline__ void compute_stage(uint32_t sbase, int lane,
                                              int m_warp, int n_warp,
                                              float acc[4][4][4])
{
    const uint32_t aBase  = sbase;
    const uint32_t alBase = sbase + TILE_BYTES;
    const uint32_t bhBase = sbase + 2 * TILE_BYTES;
    const uint32_t blBase = sbase + 3 * TILE_BYTES;

    const int a_r  = lane & 15;
    const int a_kh = (lane >> 4) & 1;
    const int b_r  = (lane & 7) + ((lane >> 4) & 1) * 8;
    const int b_kh = (lane >> 3) & 1;

#pragma unroll
    for (int s = 0; s < 2; s++) {
        uint32_t bh[8], bl[8];
#pragma unroll
        for (int p = 0; p < 2; p++) {
            int rn = n_warp + p * 16 + b_r;
            int c = s * 2 + b_kh;
            uint32_t off = sw_off(rn, c);
            ldmx4(&bh[p * 4], bhBase + off);
            ldmx4(&bl[p * 4], blBase + off);
        }
#pragma unroll
        for (int mt = 0; mt < 4; mt++) {
            int rm = m_warp + mt * 16 + a_r;
            int c = s * 2 + a_kh;
            uint32_t off = sw_off(rm, c);
            uint32_t ah[4], al[4];
            ldmx4(ah, aBase + off);
            ldmx4(al, alBase + off);
#pragma unroll
            for (int nt = 0; nt < 4; nt++) {
                float* d = acc[mt][nt];
                mma_bf16(d, ah, bh[nt * 2], bh[nt * 2 + 1]);
                mma_bf16(d, ah, bl[nt * 2], bl[nt * 2 + 1]);
                mma_bf16(d, al, bh[nt * 2], bh[nt * 2 + 1]);
            }
        }
    }
}

__device__ __forceinline__ void gemm_mainloop_mma(
    const __nv_bfloat16* Ah, const __nv_bfloat16* Al,
    const __nv_bfloat16* Bh, const __nv_bfloat16* Bl,
    int m0, int n0, uint32_t smem_u, int tid,
    int m_warp, int n_warp, float acc[4][4][4])
{
    const int lane = tid & 31;
    const int NIT = KDIM / 32;

    load_stage(Ah, Al, Bh, Bl, m0, n0, 0, smem_u, tid);
    CP_COMMIT();

    for (int it = 0; it < NIT; it++) {
        CP_WAIT0();
        __syncthreads();
        if (it + 1 < NIT) {
            load_stage(Ah, Al, Bh, Bl, m0, n0, (it + 1) * 32,
                       smem_u + ((it + 1) & 1) * STAGE_BYTES, tid);
            CP_COMMIT();
        }
        compute_stage(smem_u + (it & 1) * STAGE_BYTES, lane, m_warp, n_warp, acc);
        __syncthreads();
    }
}

// ---- QKV: X @ WaT^T -> scatter Q/K/V (+bias, Q*0.125*log2e) ---------------
__global__ void __launch_bounds__(256, 2)
gemm_qkv_mma(const float* __restrict__ bias)
{
    extern __shared__ char smem[];
    uint32_t smem_u = smem_to_u32(smem);
    const int tid = threadIdx.x;
    const int wid = tid >> 5, lane = tid & 31;
    const int m_warp = (wid >> 2) * 64, n_warp = (wid & 3) * 32;
    const int n0 = blockIdx.x * 128, m0 = blockIdx.y * 128;

    float acc[4][4][4];
#pragma unroll
    for (int i = 0; i < 4; i++)
#pragma unroll
        for (int j = 0; j < 4; j++)
#pragma unroll
            for (int k = 0; k < 4; k++) acc[i][j][k] = 0.f;

    gemm_mainloop_mma(g_Xh, g_Xl, g_WaTh, g_WaTl, m0, n0, smem_u, tid,
                      m_warp, n_warp, acc);

    const int gg = lane >> 2, tig = lane & 3;
#pragma unroll
    for (int mt = 0; mt < 4; mt++) {
#pragma unroll
        for (int nt = 0; nt < 4; nt++) {
            int col = n0 + n_warp + nt * 8 + tig * 2;
            int which = col / C_;
            int c = col - which * C_;
            int h = c >> 6, d = c & 63;
            float bx = bias[col], by = bias[col + 1];
            float* dst = (which == 0) ? g_Q : (which == 1) ? g_K : g_V;
            // fold 1/sqrt(64) * log2(e) into Q for base-2 softmax
            float scl = (which == 0) ? 0.18033688011112042f : 1.0f;
#pragma unroll
            for (int rr = 0; rr < 2; rr++) {
                int m = m0 + m_warp + mt * 16 + gg + rr * 8;
                int b = m >> 10, t = m & 1023;
                float2 v;
                v.x = (acc[mt][nt][rr * 2 + 0] + bx) * scl;
                v.y = (acc[mt][nt][rr * 2 + 1] + by) * scl;
                *(float2*)(dst + ((size_t)(b * H_ + h) * T_ + t) * HD_ + d) = v;
            }
        }
    }
}

// ---- Proj: ATT @ WpT^T + b_proj -> out ------------------------------------
__global__ void __launch_bounds__(256, 2)
gemm_proj_mma(const float* __restrict__ bias, float* __restrict__ out)
{
    extern __shared__ char smem[];
    uint32_t smem_u = smem_to_u32(smem);
    const int tid = threadIdx.x;
    const int wid = tid >> 5, lane = tid & 31;
    const int m_warp = (wid >> 2) * 64, n_warp = (wid & 3) * 32;
    const int n0 = blockIdx.x * 128, m0 = blockIdx.y * 128;

    float acc[4][4][4];
#pragma unroll
    for (int i = 0; i < 4; i++)
#pragma unroll
        for (int j = 0; j < 4; j++)
#pragma unroll
            for (int k = 0; k < 4; k++) acc[i][j][k] = 0.f;

    gemm_mainloop_mma(g_ATTh, g_ATTl, g_WpTh, g_WpTl, m0, n0, smem_u, tid,
                      m_warp, n_warp, acc);

    const int gg = lane >> 2, tig = lane & 3;
#pragma unroll
    for (int mt = 0; mt < 4; mt++) {
#pragma unroll
        for (int nt = 0; nt < 4; nt++) {
            int col = n0 + n_warp + nt * 8 + tig * 2;
            float bx = bias[col], by = bias[col + 1];
#pragma unroll
            for (int rr = 0; rr < 2; rr++) {
                int m = m0 + m_warp + mt * 16 + gg + rr * 8;
                float2 v;
                v.x = acc[mt][nt][rr * 2 + 0] + bx;
                v.y = acc[mt][nt][rr * 2 + 1] + by;
                *(float2*)(out + (size_t)m * C_ + col) = v;
            }
        }
    }
}

// =====================================================================
// preprocessing: fp32 -> split bf16 (hi + lo)
// =====================================================================
__device__ __forceinline__ void split_bf16(float v, __nv_bfloat16& h, __nv_bfloat16& l) {
    h = __float2bfloat16(v);
    l = __float2bfloat16(v - __bfloat162float(h));
}

__global__ void split_kernel(const float* __restrict__ X,
                             __nv_bfloat16* __restrict__ Xh,
                             __nv_bfloat16* __restrict__ Xl, int n4)
{
    int idx = blockIdx.x * blockDim.x + threadIdx.x;
    if (idx >= n4) return;
    float4 v = ((const float4*)X)[idx];
    __nv_bfloat16 h0, h1, h2, h3, l0, l1, l2, l3;
    split_bf16(v.x, h0, l0); split_bf16(v.y, h1, l1);
    split_bf16(v.z, h2, l2); split_bf16(v.w, h3, l3);
    __nv_bfloat162* ph = (__nv_bfloat162*)(Xh + 4 * (size_t)idx);
    __nv_bfloat162* pl = (__nv_bfloat162*)(Xl + 4 * (size_t)idx);
    ph[0] = __nv_bfloat162(h0, h1); ph[1] = __nv_bfloat162(h2, h3);
    pl[0] = __nv_bfloat162(l0, l1); pl[1] = __nv_bfloat162(l2, l3);
}

__global__ void transpose_split_kernel(const float* __restrict__ W,
                                       __nv_bfloat16* __restrict__ Th,
                                       __nv_bfloat16* __restrict__ Tl,
                                       int K, int N)
{
    __shared__ float tile[32][33];
    const int nb = blockIdx.x * 32, kb = blockIdx.y * 32;
    const int tx = threadIdx.x, ty = threadIdx.y;
#pragma unroll
    for (int i = 0; i < 32; i += 8)
        tile[ty + i][tx] = W[(size_t)(kb + ty + i) * N + nb + tx];
    __syncthreads();
#pragma unroll
    for (int i = 0; i < 32; i += 8) {
        float v = tile[tx][ty + i];
        int n = nb + ty + i, k = kb + tx;
        __nv_bfloat16 h, l;
        split_bf16(v, h, l);
        Th[(size_t)n * K + k] = h;
        Tl[(size_t)n * K + k] = l;
    }
}

// =====================================================================
// meanV
// =====================================================================
__global__ void meanv_kernel()
{
    __shared__ float red[256];
    const int bh = blockIdx.x;
    const int tid = threadIdx.x;
    const int d = tid & 63;
    const int part = tid >> 6;
    const size_t base = (size_t)bh * T_ * HD_;
    float s = 0.f;
    const int t0 = part * 256;
    for (int t = t0; t < t0 + 256; t++) s += g_V[base + (size_t)t * HD_ + d];
    red[tid] = s;
    __syncthreads();
    if (part == 0)
        g_meanV[bh * HD_ + d] =
            (red[d] + red[d + 64] + red[d + 128] + red[d + 192]) * (1.0f / 1024.0f);
}

// =====================================================================
// Tensor-core flash attention: 4 warps, m16 slab per warp, split-3 mma
// smem: Qh|Ql|Kh|Kl|Vh|Vl  (6 x 8KB = 48 KB)
// =====================================================================
// Q/K tiles: [64 rows][64 bf16] (128B rows), swizzle: chunk ^ (row&7)
#define QK_OFF(row, chunk) \
    ((uint32_t)((row) * 128 + ((((chunk) ^ ((row) & 7))) * 16)))
// V^T tile: [d rows][t cols], extra XOR so transpose stores are conflict-free
#define V_OFF(row, chunk) \
    ((uint32_t)((row) * 128 + ((((chunk) ^ ((row) & 7) ^ (((row) >> 3) & 3))) * 16)))
#define ATTN_SMEM 49152

__global__ void __launch_bounds__(128, 3)
attn_mma_kernel(const int* __restrict__ mask)
{
    extern __shared__ char smem[];
    char* sQh = smem;
    char* sQl = smem + 8192;
    char* sKh = smem + 16384;
    char* sKl = smem + 24576;
    char* sVh = smem + 32768;
    char* sVl = smem + 40960;
    const uint32_t su = smem_to_u32(smem);
    const uint32_t uQh = su, uQl = su + 8192, uKh = su + 16384,
                   uKl = su + 24576, uVh = su + 32768, uVl = su + 40960;

    const int tid = threadIdx.x;
    const int w = tid >> 5, lane = tid & 31;
    const int g = lane >> 2, tig = lane & 3;
    const int qt = blockIdx.x, bh = blockIdx.y;
    const int b = bh / H_, h = bh - b * H_;
    const int q0 = qt * QT;

    // ---- load Q tile once: fp32 -> split bf16, swizzled ----
    {
        const size_t base_q = ((size_t)bh * T_ + q0) * HD_;
#pragma unroll
        for (int i = 0; i < 8; i++) {
            int f = tid + i * 128;
            int row = f >> 4, fc = f & 15;
            float4 v = *(const float4*)(g_Q + base_q + (size_t)row * 64 + fc * 4);
            uint32_t hx = pk2(v.x, v.y), hz = pk2(v.z, v.w);
            uint32_t lx = pk2(v.x - lo_f(hx), v.y - hi_f(hx));
            uint32_t lz = pk2(v.z - lo_f(hz), v.w - hi_f(hz));
            uint32_t off = (uint32_t)(row * 128) +
                           ((uint32_t)(((fc >> 1) ^ (row & 7)) * 16)) + (fc & 1) * 8;
            *(uint2*)(sQh + off) = make_uint2(hx, lz * 0 + hz);
            *(uint2*)(sQl + off) = make_uint2(lx, lz);
        }
    }

    float o[8][4];
#pragma unroll
    for (int i = 0; i < 8; i++)
#pragma unroll
        for (int j = 0; j < 4; j++) o[i][j] = 0.f;
    float m0 = -1e30f, m1 = -1e30f, l0 = 0.f, l1 = 0.f;

    const int a_row = w * 16 + (lane & 15);
    const int a_kh = (lane >> 4) & 1;
    const int b_r = (lane & 7) + ((lane >> 4) & 1) * 8;
    const int b_kh = (lane >> 3) & 1;
    const int vd = (w & 1) * 32 + lane;    // V transpose: this thread's d-row
    const int vt0 = (w >> 1) * 32;         // V transpose: t-range start

    for (int kt = 0; kt <= qt; kt++) {
        __syncthreads();
        const size_t base_k = ((size_t)bh * T_ + kt * 64) * HD_;

        // K tile: fp32 -> split bf16 swizzled (row = t, col = d)
#pragma unroll
        for (int i = 0; i < 8; i++) {
            int f = tid + i * 128;
            int row = f >> 4, fc = f & 15;
            float4 v = *(const float4*)(g_K + base_k + (size_t)row * 64 + fc * 4);
            uint32_t hx = pk2(v.x, v.y), hz = pk2(v.z, v.w);
            uint32_t lx = pk2(v.x - lo_f(hx), v.y - hi_f(hx));
            uint32_t lz = pk2(v.z - lo_f(hz), v.w - hi_f(hz));
            uint32_t off = (uint32_t)(row * 128) +
                           ((uint32_t)(((fc >> 1) ^ (row & 7)) * 16)) + (fc & 1) * 8;
            *(uint2*)(sKh + off) = make_uint2(hx, hz);
            *(uint2*)(sKl + off) = make_uint2(lx, lz);
        }
        // V tile transposed: sVt[d][t], split bf16
#pragma unroll
        for (int tq = 0; tq < 8; tq++) {
            int tb = vt0 + tq * 4;
            float p0 = g_V[base_k + (size_t)(tb + 0) * 64 + vd];
            float p1 = g_V[base_k + (size_t)(tb + 1) * 64 + vd];
            float p2 = g_V[base_k + (size_t)(tb + 2) * 64 + vd];
            float p3 = g_V[base_k + (size_t)(tb + 3) * 64 + vd];
            uint32_t h0 = pk2(p0, p1), h1 = pk2(p2, p3);
            uint32_t q0v = pk2(p0 - lo_f(h0), p1 - hi_f(h0));
            uint32_t q1v = pk2(p2 - lo_f(h1), p3 - hi_f(h1));
            uint32_t off = V_OFF(vd, tb >> 3) + ((tb >> 2) & 1) * 8;
            *(uint2*)(sVh + off) = make_uint2(h0, h1);
            *(uint2*)(sVl + off) = make_uint2(q0v, q1v);
        }
        __syncthreads();

        // ---- S = Q K^T (m16 x n64, k=64), split-3 ----
        float s[8][4];
#pragma unroll
        for (int i = 0; i < 8; i++)
#pragma unroll
            for (int j = 0; j < 4; j++) s[i][j] = 0.f;

#pragma unroll
        for (int ks = 0; ks < 4; ks++) {
            uint32_t ah[4], al[4];
            uint32_t aoff = QK_OFF(a_row, ks * 2 + a_kh);
            ldmx4(ah, uQh + aoff);
            ldmx4(al, uQl + aoff);
#pragma unroll
            for (int np = 0; np < 4; np++) {
                uint32_t kb[4], kl[4];
                uint32_t boff = QK_OFF(np * 16 + b_r, ks * 2 + b_kh);
                ldmx4(kb, uKh + boff);
                ldmx4(kl, uKl + boff);
                mma_bf16(s[np * 2], ah, kb[0], kb[1]);
                mma_bf16(s[np * 2], ah, kl[0], kl[1]);
                mma_bf16(s[np * 2], al, kb[0], kb[1]);
                mma_bf16(s[np * 2 + 1], ah, kb[2], kb[3]);
                mma_bf16(s[np * 2 + 1], ah, kl[2], kl[3]);
                mma_bf16(s[np * 2 + 1], al, kb[2], kb[3]);
            }
        }

        // causal mask on diagonal tile
        if (kt == qt) {
            const int r0 = w * 16 + g, r1 = r0 + 8;
#pragma unroll
            for (int nt = 0; nt < 8; nt++) {
                int c = nt * 8 + tig * 2;
                if (c > r0)     s[nt][0] = -1e30f;
                if (c + 1 > r0) s[nt][1] = -1e30f;
                if (c > r1)     s[nt][2] = -1e30f;
                if (c + 1 > r1) s[nt][3] = -1e30f;
            }
        }

        // ---- online softmax (base-2; log2e folded into Q) ----
        float mx0 = -1e30f, mx1 = -1e30f;
#pragma unroll
        for (int nt = 0; nt < 8; nt++) {
            mx0 = fmaxf(mx0, fmaxf(s[nt][0], s[nt][1]));
            mx1 = fmaxf(mx1, fmaxf(s[nt][2], s[nt][3]));
        }
        mx0 = fmaxf(mx0, __shfl_xor_sync(0xffffffffu, mx0, 1));
        mx0 = fmaxf(mx0, __shfl_xor_sync(0xffffffffu, mx0, 2));
        mx1 = fmaxf(mx1, __shfl_xor_sync(0xffffffffu, mx1, 1));
        mx1 = fmaxf(mx1, __shfl_xor_sync(0xffffffffu, mx1, 2));
        float mn0 = fmaxf(m0, mx0), mn1 = fmaxf(m1, mx1);
        float cr0 = ex2f(m0 - mn0), cr1 = ex2f(m1 - mn1);
        m0 = mn0; m1 = mn1;

        float sum0 = 0.f, sum1 = 0.f;
#pragma unroll
        for (int nt = 0; nt < 8; nt++) {
            s[nt][0] = ex2f(s[nt][0] - mn0);
            s[nt][1] = ex2f(s[nt][1] - mn0);
            s[nt][2] = ex2f(s[nt][2] - mn1);
            s[nt][3] = ex2f(s[nt][3] - mn1);
            sum0 += s[nt][0] + s[nt][1];
            sum1 += s[nt][2] + s[nt][3];
        }
        sum0 += __shfl_xor_sync(0xffffffffu, sum0, 1);
        sum0 += __shfl_xor_sync(0xffffffffu, sum0, 2);
        sum1 += __shfl_xor_sync(0xffffffffu, sum1, 1);
        sum1 += __shfl_xor_sync(0xffffffffu, sum1, 2);
        l0 = l0 * cr0 + sum0;
        l1 = l1 * cr1 + sum1;

#pragma unroll
        for (int nt = 0; nt < 8; nt++) {
            o[nt][0] *= cr0; o[nt][1] *= cr0;
            o[nt][2] *= cr1; o[nt][3] *= cr1;
        }

        // ---- O += P V  (P frags built in registers from S frags) ----
#pragma unroll
        for (int kc = 0; kc < 4; kc++) {
            const float* sa = s[2 * kc];
            const float* sb = s[2 * kc + 1];
            uint32_t pah[4], pal[4];
            pah[0] = pk2(sa[0], sa[1]);
            pal[0] = pk2(sa[0] - lo_f(pah[0]), sa[1] - hi_f(pah[0]));
            pah[1] = pk2(sa[2], sa[3]);
            pal[1] = pk2(sa[2] - lo_f(pah[1]), sa[3] - hi_f(pah[1]));
            pah[2] = pk2(sb[0], sb[1]);
            pal[2] = pk2(sb[0] - lo_f(pah[2]), sb[1] - hi_f(pah[2]));
            pah[3] = pk2(sb[2], sb[3]);
            pal[3] = pk2(sb[2] - lo_f(pah[3]), sb[3] - hi_f(pah[3]));
#pragma unroll
            for (int np = 0; np < 4; np++) {
                uint32_t vb[4], vl[4];
                uint32_t off = V_OFF(np * 16 + b_r, kc * 2 + b_kh);
                ldmx4(vb, uVh + off);
                ldmx4(vl, uVl + off);
                mma_bf16(o[np * 2], pah, vb[0], vb[1]);
                mma_bf16(o[np * 2], pah, vl[0], vl[1]);
                mma_bf16(o[np * 2], pal, vb[0], vb[1]);
                mma_bf16(o[np * 2 + 1], pah, vb[2], vb[3]);
                mma_bf16(o[np * 2 + 1], pah, vl[2], vl[3]);
                mma_bf16(o[np * 2 + 1], pal, vb[2], vb[3]);
            }
        }
    }

    // ---- epilogue: normalize, masked-row override, split-bf16 store ----
    const float il0 = 1.f / l0, il1 = 1.f / l1;
    const int r0g = q0 + w * 16 + g, r1g = r0g + 8;
    const bool mk0 = (mask[b * T_ + r0g] == 0);
    const bool mk1 = (mask[b * T_ + r1g] == 0);
    const size_t ob0 = ((size_t)b * T_ + r0g) * C_ + h * 64;
    const size_t ob1 = ((size_t)b * T_ + r1g) * C_ + h * 64;
#pragma unroll
    for (int nt = 0; nt < 8; nt++) {
        int d = nt * 8 + tig * 2;
        float y0 = o[nt][0] * il0, y1 = o[nt][1] * il0;
        if (mk0) { y0 = g_meanV[bh * 64 + d]; y1 = g_meanV[bh * 64 + d + 1]; }
        uint32_t hh = pk2(y0, y1);
        uint32_t ll = pk2(y0 - lo_f(hh), y1 - hi_f(hh));
        *(uint32_t*)(g_ATTh + ob0 + d) = hh;
        *(uint32_t*)(g_ATTl + ob0 + d) = ll;
        float z0 = o[nt][2] * il1, z1 = o[nt][3] * il1;
        if (mk1) { z0 = g_meanV[bh * 64 + d]; z1 = g_meanV[bh * 64 + d + 1]; }
        uint32_t hh1 = pk2(z0, z1);
        uint32_t ll1 = pk2(z0 - lo_f(hh1), z1 - hi_f(hh1));
        *(uint32_t*)(g_ATTh + ob1 + d) = hh1;
        *(uint32_t*)(g_ATTl + ob1 + d) = ll1;
    }
}

// =====================================================================
// launcher
// =====================================================================
extern "C" void kernel_launch(void* const* d_in, const int* in_sizes, int n_in,
                              void* d_out, int out_size)
{
    const float* x      = (const float*)d_in[0];
    const int*   mask   = (const int*)d_in[1];
    const float* W_attn = (const float*)d_in[2];
    const float* b_attn = (const float*)d_in[3];
    const float* W_proj = (const float*)d_in[4];
    const float* b_proj = (const float*)d_in[5];
    float* out = (float*)d_out;

    __nv_bfloat16 *p_Xh, *p_Xl, *p_WaTh, *p_WaTl, *p_WpTh, *p_WpTl;
    cudaGetSymbolAddress((void**)&p_Xh, g_Xh);
    cudaGetSymbolAddress((void**)&p_Xl, g_Xl);
    cudaGetSymbolAddress((void**)&p_WaTh, g_WaTh);
    cudaGetSymbolAddress((void**)&p_WaTl, g_WaTl);
    cudaGetSymbolAddress((void**)&p_WpTh, g_WpTh);
    cudaGetSymbolAddress((void**)&p_WpTl, g_WpTl);

    // 0) split / transpose-split preprocessing
    split_kernel<<<(M_ * C_ / 4 + 255) / 256, 256>>>(x, p_Xh, p_Xl, M_ * C_ / 4);
    transpose_split_kernel<<<dim3(N3C / 32, C_ / 32), dim3(32, 8)>>>(
        W_attn, p_WaTh, p_WaTl, C_, N3C);
    transpose_split_kernel<<<dim3(C_ / 32, C_ / 32), dim3(32, 8)>>>(
        W_proj, p_WpTh, p_WpTl, C_, C_);

    // 1) QKV projection via mma.sync bf16 (split-3)
    {
        cudaFuncSetAttribute(gemm_qkv_mma,
                             cudaFuncAttributeMaxDynamicSharedMemorySize, GEMM_SMEM);
        dim3 grid(N3C / 128, M_ / 128);
        gemm_qkv_mma<<<grid, 256, GEMM_SMEM>>>(b_attn);
    }
    // 2) per-(b,h) mean of V
    meanv_kernel<<<B_ * H_, 256>>>();
    // 3) causal flash attention on tensor cores (split-3)
    {
        cudaFuncSetAttribute(attn_mma_kernel,
                             cudaFuncAttributeMaxDynamicSharedMemorySize, ATTN_SMEM);
        dim3 grid(T_ / QT, B_ * H_);
        attn_mma_kernel<<<grid, 128, ATTN_SMEM>>>(mask);
    }
    // 4) output projection via mma.sync bf16 (split-3)
    {
        cudaFuncSetAttribute(gemm_proj_mma,
                             cudaFuncAttributeMaxDynamicSharedMemorySize, GEMM_SMEM);
        dim3 grid(C_ / 128, M_ / 128);
        gemm_proj_mma<<<grid, 256, GEMM_SMEM>>>(b_proj, out);
    }
}

// round 11
// speedup vs baseline: 4.0111x; 1.3269x over previous
#include <cuda_runtime.h>
#include <cuda_bf16.h>
#include <cuda_fp16.h>
#include <cstdint>
#include <math.h>

// Problem constants
#define B_   8
#define T_   1024
#define C_   768
#define H_   12
#define HD_  64
#define M_   (B_ * T_)      // 8192
#define N3C  (3 * C_)       // 2304
#define KDIM 768
#define QT   64

// ---------------- scratch (device globals; no allocations allowed) ----------
__device__ float g_Q[B_ * H_ * T_ * HD_];     // [B,H,T,HD], scaled by 0.125*log2e
__device__ float g_K[B_ * H_ * T_ * HD_];
__device__ float g_V[B_ * H_ * T_ * HD_];
__device__ float g_meanV[B_ * H_ * HD_];

// fp16 operands (single precision-level, no split)
__device__ __half g_X16[M_ * C_];             // x        [8192,768]
__device__ __half g_WaT[N3C * C_];            // W_attn^T [2304,768] (k-contig)
__device__ __half g_WpT[C_ * C_];             // W_proj^T [768,768]
__device__ __half g_ATT[M_ * C_];             // attention out [8192,768]

// =====================================================================
// family-common PTX helpers (NO tcgen05 — ptx target is sm_103 base)
// =====================================================================
__device__ __forceinline__ uint32_t smem_to_u32(const void* p) {
    uint32_t a;
    asm("{ .reg .u64 t; cvta.to.shared.u64 t, %1; cvt.u32.u64 %0, t; }"
        : "=r"(a) : "l"(p));
    return a;
}

__device__ __forceinline__ void cp16(uint32_t saddr, const void* g) {
    asm volatile("cp.async.cg.shared.global [%0], [%1], 16;"
                 :: "r"(saddr), "l"(g));
}
#define CP_COMMIT() asm volatile("cp.async.commit_group;")
#define CP_WAIT0()  asm volatile("cp.async.wait_group 0;")

__device__ __forceinline__ void ldmx4(uint32_t* r, uint32_t addr) {
    asm volatile("ldmatrix.sync.aligned.m8n8.x4.shared.b16 {%0,%1,%2,%3}, [%4];"
                 : "=r"(r[0]), "=r"(r[1]), "=r"(r[2]), "=r"(r[3]) : "r"(addr));
}

// fp16 MMA, fp32 accumulate
__device__ __forceinline__ void mma_f16(float* d, const uint32_t* a,
                                        uint32_t b0, uint32_t b1) {
    asm volatile(
        "mma.sync.aligned.m16n8k16.row.col.f32.f16.f16.f32 "
        "{%0,%1,%2,%3}, {%4,%5,%6,%7}, {%8,%9}, {%0,%1,%2,%3};"
        : "+f"(d[0]), "+f"(d[1]), "+f"(d[2]), "+f"(d[3])
        : "r"(a[0]), "r"(a[1]), "r"(a[2]), "r"(a[3]), "r"(b0), "r"(b1));
}

// pack two fp32 -> half2 (lo lane = first arg)
__device__ __forceinline__ uint32_t pkh2(float lo, float hi) {
    __half2 t = __floats2half2_rn(lo, hi);
    return *(uint32_t*)&t;
}
__device__ __forceinline__ float ex2f(float x) {
    float r; asm("ex2.approx.f32 %0, %1;" : "=f"(r) : "f"(x)); return r;
}

// =====================================================================
// GEMM: 128x128, BK=32, single-product fp16 mma.sync, double buffered
// =====================================================================
#define TILE_BYTES 8192
#define STAGE_BYTES (2 * TILE_BYTES)   // A, B
#define GEMM_SMEM (2 * STAGE_BYTES)    // 32768

__device__ __forceinline__ uint32_t sw_off(int row, int c) {
    return (uint32_t)(row * 64 + ((c ^ ((row >> 1) & 3)) * 16));
}

__device__ __forceinline__ void load_stage(
    const __half* A, const __half* Bm,
    int m0, int n0, int k0, uint32_t sbase, int tid)
{
#pragma unroll
    for (int i = 0; i < 2; i++) {
        int q = tid + i * 256;        // 512 chunks per tile
        int row = q >> 2;
        int c = q & 3;
        uint32_t so = sw_off(row, c);
        cp16(sbase + so, A + (size_t)(m0 + row) * KDIM + k0 + c * 8);
        cp16(sbase + TILE_BYTES + so, Bm + (size_t)(n0 + row) * KDIM + k0 + c * 8);
    }
}

__device__ __forceinline__ void compute_stage(uint32_t sbase, int lane,
                                              int m_warp, int n_warp,
                                              float acc[4][4][4])
{
    const uint32_t aBase = sbase;
    const uint32_t bBase = sbase + TILE_BYTES;

    const int a_r  = lane & 15;
    const int a_kh = (lane >> 4) & 1;
    const int b_r  = (lane & 7) + ((lane >> 4) & 1) * 8;
    const int b_kh = (lane >> 3) & 1;

#pragma unroll
    for (int s = 0; s < 2; s++) {          // two k16 steps
        uint32_t bh[8];
#pragma unroll
        for (int p = 0; p < 2; p++) {
            int rn = n_warp + p * 16 + b_r;
            int c = s * 2 + b_kh;
            ldmx4(&bh[p * 4], bBase + sw_off(rn, c));
        }
#pragma unroll
        for (int mt = 0; mt < 4; mt++) {
            int rm = m_warp + mt * 16 + a_r;
            int c = s * 2 + a_kh;
            uint32_t ah[4];
            ldmx4(ah, aBase + sw_off(rm, c));
#pragma unroll
            for (int nt = 0; nt < 4; nt++)
                mma_f16(acc[mt][nt], ah, bh[nt * 2], bh[nt * 2 + 1]);
        }
    }
}

__device__ __forceinline__ void gemm_mainloop_mma(
    const __half* A, const __half* Bm,
    int m0, int n0, uint32_t smem_u, int tid,
    int m_warp, int n_warp, float acc[4][4][4])
{
    const int lane = tid & 31;
    const int NIT = KDIM / 32;     // 24

    load_stage(A, Bm, m0, n0, 0, smem_u, tid);
    CP_COMMIT();

    for (int it = 0; it < NIT; it++) {
        CP_WAIT0();
        __syncthreads();
        if (it + 1 < NIT) {
            load_stage(A, Bm, m0, n0, (it + 1) * 32,
                       smem_u + ((it + 1) & 1) * STAGE_BYTES, tid);
            CP_COMMIT();
        }
        compute_stage(smem_u + (it & 1) * STAGE_BYTES, lane, m_warp, n_warp, acc);
        __syncthreads();
    }
}

// ---- QKV: X @ WaT^T -> scatter Q/K/V (+bias, Q*0.125*log2e) ---------------
__global__ void __launch_bounds__(256, 2)
gemm_qkv_mma(const float* __restrict__ bias)
{
    extern __shared__ char smem[];
    uint32_t smem_u = smem_to_u32(smem);
    const int tid = threadIdx.x;
    const int wid = tid >> 5, lane = tid & 31;
    const int m_warp = (wid >> 2) * 64, n_warp = (wid & 3) * 32;
    const int n0 = blockIdx.x * 128, m0 = blockIdx.y * 128;

    float acc[4][4][4];
#pragma unroll
    for (int i = 0; i < 4; i++)
#pragma unroll
        for (int j = 0; j < 4; j++)
#pragma unroll
            for (int k = 0; k < 4; k++) acc[i][j][k] = 0.f;

    gemm_mainloop_mma(g_X16, g_WaT, m0, n0, smem_u, tid, m_warp, n_warp, acc);

    const int gg = lane >> 2, tig = lane & 3;
#pragma unroll
    for (int mt = 0; mt < 4; mt++) {
#pragma unroll
        for (int nt = 0; nt < 4; nt++) {
            int col = n0 + n_warp + nt * 8 + tig * 2;
            int which = col / C_;
            int c = col - which * C_;
            int h = c >> 6, d = c & 63;
            float bx = bias[col], by = bias[col + 1];
            float* dst = (which == 0) ? g_Q : (which == 1) ? g_K : g_V;
            // fold 1/sqrt(64) * log2(e) into Q for base-2 softmax
            float scl = (which == 0) ? 0.18033688011112042f : 1.0f;
#pragma unroll
            for (int rr = 0; rr < 2; rr++) {
                int m = m0 + m_warp + mt * 16 + gg + rr * 8;
                int b = m >> 10, t = m & 1023;
                float2 v;
                v.x = (acc[mt][nt][rr * 2 + 0] + bx) * scl;
                v.y = (acc[mt][nt][rr * 2 + 1] + by) * scl;
                *(float2*)(dst + ((size_t)(b * H_ + h) * T_ + t) * HD_ + d) = v;
            }
        }
    }
}

// ---- Proj: ATT @ WpT^T + b_proj -> out ------------------------------------
__global__ void __launch_bounds__(256, 2)
gemm_proj_mma(const float* __restrict__ bias, float* __restrict__ out)
{
    extern __shared__ char smem[];
    uint32_t smem_u = smem_to_u32(smem);
    const int tid = threadIdx.x;
    const int wid = tid >> 5, lane = tid & 31;
    const int m_warp = (wid >> 2) * 64, n_warp = (wid & 3) * 32;
    const int n0 = blockIdx.x * 128, m0 = blockIdx.y * 128;

    float acc[4][4][4];
#pragma unroll
    for (int i = 0; i < 4; i++)
#pragma unroll
        for (int j = 0; j < 4; j++)
#pragma unroll
            for (int k = 0; k < 4; k++) acc[i][j][k] = 0.f;

    gemm_mainloop_mma(g_ATT, g_WpT, m0, n0, smem_u, tid, m_warp, n_warp, acc);

    const int gg = lane >> 2, tig = lane & 3;
#pragma unroll
    for (int mt = 0; mt < 4; mt++) {
#pragma unroll
        for (int nt = 0; nt < 4; nt++) {
            int col = n0 + n_warp + nt * 8 + tig * 2;
            float bx = bias[col], by = bias[col + 1];
#pragma unroll
            for (int rr = 0; rr < 2; rr++) {
                int m = m0 + m_warp + mt * 16 + gg + rr * 8;
                float2 v;
                v.x = acc[mt][nt][rr * 2 + 0] + bx;
                v.y = acc[mt][nt][rr * 2 + 1] + by;
                *(float2*)(out + (size_t)m * C_ + col) = v;
            }
        }
    }
}

// =====================================================================
// preprocessing: fp32 -> fp16
// =====================================================================
__global__ void to_half_kernel(const float* __restrict__ X,
                               __half* __restrict__ Y, int n4)
{
    int idx = blockIdx.x * blockDim.x + threadIdx.x;
    if (idx >= n4) return;
    float4 v = ((const float4*)X)[idx];
    __half2* py = (__half2*)(Y + 4 * (size_t)idx);
    py[0] = __floats2half2_rn(v.x, v.y);
    py[1] = __floats2half2_rn(v.z, v.w);
}

// W [K, N] fp32 -> T [N, K] fp16 (transpose)
__global__ void transpose_half_kernel(const float* __restrict__ W,
                                      __half* __restrict__ Th, int K, int N)
{
    __shared__ float tile[32][33];
    const int nb = blockIdx.x * 32, kb = blockIdx.y * 32;
    const int tx = threadIdx.x, ty = threadIdx.y;  // 32 x 8
#pragma unroll
    for (int i = 0; i < 32; i += 8)
        tile[ty + i][tx] = W[(size_t)(kb + ty + i) * N + nb + tx];
    __syncthreads();
#pragma unroll
    for (int i = 0; i < 32; i += 8) {
        int n = nb + ty + i, k = kb + tx;
        Th[(size_t)n * K + k] = __float2half_rn(tile[tx][ty + i]);
    }
}

// =====================================================================
// meanV
// =====================================================================
__global__ void meanv_kernel()
{
    __shared__ float red[256];
    const int bh = blockIdx.x;
    const int tid = threadIdx.x;
    const int d = tid & 63;
    const int part = tid >> 6;
    const size_t base = (size_t)bh * T_ * HD_;
    float s = 0.f;
    const int t0 = part * 256;
    for (int t = t0; t < t0 + 256; t++) s += g_V[base + (size_t)t * HD_ + d];
    red[tid] = s;
    __syncthreads();
    if (part == 0)
        g_meanV[bh * HD_ + d] =
            (red[d] + red[d + 64] + red[d + 128] + red[d + 192]) * (1.0f / 1024.0f);
}

// =====================================================================
// Tensor-core flash attention: 4 warps, m16 slab per warp, fp16 single
// smem: Q|K|V  (3 x 8KB = 24 KB)
// =====================================================================
#define QK_OFF(row, chunk) \
    ((uint32_t)((row) * 128 + ((((chunk) ^ ((row) & 7))) * 16)))
#define V_OFF(row, chunk) \
    ((uint32_t)((row) * 128 + ((((chunk) ^ ((row) & 7) ^ (((row) >> 3) & 3))) * 16)))
#define ATTN_SMEM 24576

__global__ void __launch_bounds__(128, 4)
attn_mma_kernel(const int* __restrict__ mask)
{
    extern __shared__ char smem[];
    char* sQ = smem;
    char* sK = smem + 8192;
    char* sV = smem + 16384;
    const uint32_t su = smem_to_u32(smem);
    const uint32_t uQ = su, uK = su + 8192, uV = su + 16384;

    const int tid = threadIdx.x;
    const int w = tid >> 5, lane = tid & 31;
    const int g = lane >> 2, tig = lane & 3;
    const int qt = blockIdx.x, bh = blockIdx.y;
    const int b = bh / H_, h = bh - b * H_;
    const int q0 = qt * QT;

    // ---- load Q tile once: fp32 -> fp16, swizzled ----
    {
        const size_t base_q = ((size_t)bh * T_ + q0) * HD_;
#pragma unroll
        for (int i = 0; i < 8; i++) {
            int f = tid + i * 128;
            int row = f >> 4, fc = f & 15;
            float4 v = *(const float4*)(g_Q + base_q + (size_t)row * 64 + fc * 4);
            uint32_t hx = pkh2(v.x, v.y), hz = pkh2(v.z, v.w);
            uint32_t off = (uint32_t)(row * 128) +
                           ((uint32_t)(((fc >> 1) ^ (row & 7)) * 16)) + (fc & 1) * 8;
            *(uint2*)(sQ + off) = make_uint2(hx, hz);
        }
    }

    float o[8][4];
#pragma unroll
    for (int i = 0; i < 8; i++)
#pragma unroll
        for (int j = 0; j < 4; j++) o[i][j] = 0.f;
    float m0 = -1e30f, m1 = -1e30f, l0 = 0.f, l1 = 0.f;

    const int a_row = w * 16 + (lane & 15);
    const int a_kh = (lane >> 4) & 1;
    const int b_r = (lane & 7) + ((lane >> 4) & 1) * 8;
    const int b_kh = (lane >> 3) & 1;
    const int vd = (w & 1) * 32 + lane;    // V transpose: this thread's d-row
    const int vt0 = (w >> 1) * 32;         // V transpose: t-range start

    for (int kt = 0; kt <= qt; kt++) {
        __syncthreads();
        const size_t base_k = ((size_t)bh * T_ + kt * 64) * HD_;

        // K tile: fp32 -> fp16 swizzled (row = t, col = d)
#pragma unroll
        for (int i = 0; i < 8; i++) {
            int f = tid + i * 128;
            int row = f >> 4, fc = f & 15;
            float4 v = *(const float4*)(g_K + base_k + (size_t)row * 64 + fc * 4);
            uint32_t hx = pkh2(v.x, v.y), hz = pkh2(v.z, v.w);
            uint32_t off = (uint32_t)(row * 128) +
                           ((uint32_t)(((fc >> 1) ^ (row & 7)) * 16)) + (fc & 1) * 8;
            *(uint2*)(sK + off) = make_uint2(hx, hz);
        }
        // V tile transposed: sV[d][t], fp16
#pragma unroll
        for (int tq = 0; tq < 8; tq++) {
            int tb = vt0 + tq * 4;
            float p0 = g_V[base_k + (size_t)(tb + 0) * 64 + vd];
            float p1 = g_V[base_k + (size_t)(tb + 1) * 64 + vd];
            float p2 = g_V[base_k + (size_t)(tb + 2) * 64 + vd];
            float p3 = g_V[base_k + (size_t)(tb + 3) * 64 + vd];
            uint32_t h0 = pkh2(p0, p1), h1 = pkh2(p2, p3);
            uint32_t off = V_OFF(vd, tb >> 3) + ((tb >> 2) & 1) * 8;
            *(uint2*)(sV + off) = make_uint2(h0, h1);
        }
        __syncthreads();

        // ---- S = Q K^T (m16 x n64, k=64), fp16 single ----
        float s[8][4];
#pragma unroll
        for (int i = 0; i < 8; i++)
#pragma unroll
            for (int j = 0; j < 4; j++) s[i][j] = 0.f;

#pragma unroll
        for (int ks = 0; ks < 4; ks++) {
            uint32_t ah[4];
            ldmx4(ah, uQ + QK_OFF(a_row, ks * 2 + a_kh));
#pragma unroll
            for (int np = 0; np < 4; np++) {
                uint32_t kb[4];
                ldmx4(kb, uK + QK_OFF(np * 16 + b_r, ks * 2 + b_kh));
                mma_f16(s[np * 2], ah, kb[0], kb[1]);
                mma_f16(s[np * 2 + 1], ah, kb[2], kb[3]);
            }
        }

        // causal mask on diagonal tile
        if (kt == qt) {
            const int r0 = w * 16 + g, r1 = r0 + 8;
#pragma unroll
            for (int nt = 0; nt < 8; nt++) {
                int c = nt * 8 + tig * 2;
                if (c > r0)     s[nt][0] = -1e30f;
                if (c + 1 > r0) s[nt][1] = -1e30f;
                if (c > r1)     s[nt][2] = -1e30f;
                if (c + 1 > r1) s[nt][3] = -1e30f;
            }
        }

        // ---- online softmax (base-2; log2e folded into Q) ----
        float mx0 = -1e30f, mx1 = -1e30f;
#pragma unroll
        for (int nt = 0; nt < 8; nt++) {
            mx0 = fmaxf(mx0, fmaxf(s[nt][0], s[nt][1]));
            mx1 = fmaxf(mx1, fmaxf(s[nt][2], s[nt][3]));
        }
        mx0 = fmaxf(mx0, __shfl_xor_sync(0xffffffffu, mx0, 1));
        mx0 = fmaxf(mx0, __shfl_xor_sync(0xffffffffu, mx0, 2));
        mx1 = fmaxf(mx1, __shfl_xor_sync(0xffffffffu, mx1, 1));
        mx1 = fmaxf(mx1, __shfl_xor_sync(0xffffffffu, mx1, 2));
        float mn0 = fmaxf(m0, mx0), mn1 = fmaxf(m1, mx1);
        float cr0 = ex2f(m0 - mn0), cr1 = ex2f(m1 - mn1);
        m0 = mn0; m1 = mn1;

        float sum0 = 0.f, sum1 = 0.f;
#pragma unroll
        for (int nt = 0; nt < 8; nt++) {
            s[nt][0] = ex2f(s[nt][0] - mn0);
            s[nt][1] = ex2f(s[nt][1] - mn0);
            s[nt][2] = ex2f(s[nt][2] - mn1);
            s[nt][3] = ex2f(s[nt][3] - mn1);
            sum0 += s[nt][0] + s[nt][1];
            sum1 += s[nt][2] + s[nt][3];
        }
        sum0 += __shfl_xor_sync(0xffffffffu, sum0, 1);
        sum0 += __shfl_xor_sync(0xffffffffu, sum0, 2);
        sum1 += __shfl_xor_sync(0xffffffffu, sum1, 1);
        sum1 += __shfl_xor_sync(0xffffffffu, sum1, 2);
        l0 = l0 * cr0 + sum0;
        l1 = l1 * cr1 + sum1;

#pragma unroll
        for (int nt = 0; nt < 8; nt++) {
            o[nt][0] *= cr0; o[nt][1] *= cr0;
            o[nt][2] *= cr1; o[nt][3] *= cr1;
        }

        // ---- O += P V  (P frags built in registers from S frags) ----
#pragma unroll
        for (int kc = 0; kc < 4; kc++) {
            const float* sa = s[2 * kc];
            const float* sb = s[2 * kc + 1];
            uint32_t pah[4];
            pah[0] = pkh2(sa[0], sa[1]);
            pah[1] = pkh2(sa[2], sa[3]);
            pah[2] = pkh2(sb[0], sb[1]);
            pah[3] = pkh2(sb[2], sb[3]);
#pragma unroll
            for (int np = 0; np < 4; np++) {
                uint32_t vb[4];
                ldmx4(vb, uV + V_OFF(np * 16 + b_r, kc * 2 + b_kh));
                mma_f16(o[np * 2], pah, vb[0], vb[1]);
                mma_f16(o[np * 2 + 1], pah, vb[2], vb[3]);
            }
        }
    }

    // ---- epilogue: normalize, masked-row override, fp16 store ----
    const float il0 = 1.f / l0, il1 = 1.f / l1;
    const int r0g = q0 + w * 16 + g, r1g = r0g + 8;
    const bool mk0 = (mask[b * T_ + r0g] == 0);
    const bool mk1 = (mask[b * T_ + r1g] == 0);
    const size_t ob0 = ((size_t)b * T_ + r0g) * C_ + h * 64;
    const size_t ob1 = ((size_t)b * T_ + r1g) * C_ + h * 64;
#pragma unroll
    for (int nt = 0; nt < 8; nt++) {
        int d = nt * 8 + tig * 2;
        float y0 = o[nt][0] * il0, y1 = o[nt][1] * il0;
        if (mk0) { y0 = g_meanV[bh * 64 + d]; y1 = g_meanV[bh * 64 + d + 1]; }
        *(uint32_t*)(g_ATT + ob0 + d) = pkh2(y0, y1);
        float z0 = o[nt][2] * il1, z1 = o[nt][3] * il1;
        if (mk1) { z0 = g_meanV[bh * 64 + d]; z1 = g_meanV[bh * 64 + d + 1]; }
        *(uint32_t*)(g_ATT + ob1 + d) = pkh2(z0, z1);
    }
}

// =====================================================================
// launcher
// =====================================================================
extern "C" void kernel_launch(void* const* d_in, const int* in_sizes, int n_in,
                              void* d_out, int out_size)
{
    const float* x      = (const float*)d_in[0];
    const int*   mask   = (const int*)d_in[1];
    const float* W_attn = (const float*)d_in[2];
    const float* b_attn = (const float*)d_in[3];
    const float* W_proj = (const float*)d_in[4];
    const float* b_proj = (const float*)d_in[5];
    float* out = (float*)d_out;

    __half *p_X16, *p_WaT, *p_WpT;
    cudaGetSymbolAddress((void**)&p_X16, g_X16);
    cudaGetSymbolAddress((void**)&p_WaT, g_WaT);
    cudaGetSymbolAddress((void**)&p_WpT, g_WpT);

    // 0) fp32 -> fp16 preprocessing
    to_half_kernel<<<(M_ * C_ / 4 + 255) / 256, 256>>>(x, p_X16, M_ * C_ / 4);
    transpose_half_kernel<<<dim3(N3C / 32, C_ / 32), dim3(32, 8)>>>(
        W_attn, p_WaT, C_, N3C);
    transpose_half_kernel<<<dim3(C_ / 32, C_ / 32), dim3(32, 8)>>>(
        W_proj, p_WpT, C_, C_);

    // 1) QKV projection via mma.sync fp16
    {
        cudaFuncSetAttribute(gemm_qkv_mma,
                             cudaFuncAttributeMaxDynamicSharedMemorySize, GEMM_SMEM);
        dim3 grid(N3C / 128, M_ / 128);
        gemm_qkv_mma<<<grid, 256, GEMM_SMEM>>>(b_attn);
    }
    // 2) per-(b,h) mean of V
    meanv_kernel<<<B_ * H_, 256>>>();
    // 3) causal flash attention on tensor cores (fp16)
    {
        cudaFuncSetAttribute(attn_mma_kernel,
                             cudaFuncAttributeMaxDynamicSharedMemorySize, ATTN_SMEM);
        dim3 grid(T_ / QT, B_ * H_);
        attn_mma_kernel<<<grid, 128, ATTN_SMEM>>>(mask);
    }
    // 4) output projection via mma.sync fp16
    {
        cudaFuncSetAttribute(gemm_proj_mma,
                             cudaFuncAttributeMaxDynamicSharedMemorySize, GEMM_SMEM);
        dim3 grid(C_ / 128, M_ / 128);
        gemm_proj_mma<<<grid, 256, GEMM_SMEM>>>(b_proj, out);
    }
}

// round 12
// speedup vs baseline: 6.5624x; 1.6360x over previous
#include <cuda_runtime.h>
#include <cuda_fp16.h>
#include <cstdint>
#include <math.h>

// Problem constants
#define B_   8
#define T_   1024
#define C_   768
#define H_   12
#define HD_  64
#define M_   (B_ * T_)      // 8192
#define N3C  (3 * C_)       // 2304
#define KDIM 768
#define QT   64

// ---------------- scratch (device globals; no allocations allowed) ----------
__device__ __half g_Qh[B_ * H_ * T_ * HD_];   // [B,H,T,HD], scaled 0.125*log2e
__device__ __half g_Kh[B_ * H_ * T_ * HD_];
__device__ __half g_Vh[B_ * H_ * T_ * HD_];
__device__ float  g_meanV[B_ * H_ * HD_];

__device__ __half g_X16[M_ * C_];             // x        [8192,768]
__device__ __half g_WaT[N3C * C_];            // W_attn^T [2304,768] (k-contig)
__device__ __half g_WpT[C_ * C_];             // W_proj^T [768,768]
__device__ __half g_ATT[M_ * C_];             // attention out [8192,768]

// =====================================================================
// family-common PTX helpers (NO tcgen05 — ptx target is sm_103 base)
// =====================================================================
__device__ __forceinline__ uint32_t smem_to_u32(const void* p) {
    uint32_t a;
    asm("{ .reg .u64 t; cvta.to.shared.u64 t, %1; cvt.u32.u64 %0, t; }"
        : "=r"(a) : "l"(p));
    return a;
}

__device__ __forceinline__ void cp16(uint32_t saddr, const void* g) {
    asm volatile("cp.async.cg.shared.global [%0], [%1], 16;"
                 :: "r"(saddr), "l"(g));
}
#define CP_COMMIT() asm volatile("cp.async.commit_group;")
#define CP_WAIT0()  asm volatile("cp.async.wait_group 0;")
#define CP_WAIT2()  asm volatile("cp.async.wait_group 2;")

__device__ __forceinline__ void ldmx4(uint32_t* r, uint32_t addr) {
    asm volatile("ldmatrix.sync.aligned.m8n8.x4.shared.b16 {%0,%1,%2,%3}, [%4];"
                 : "=r"(r[0]), "=r"(r[1]), "=r"(r[2]), "=r"(r[3]) : "r"(addr));
}
__device__ __forceinline__ void ldmx4t(uint32_t* r, uint32_t addr) {
    asm volatile("ldmatrix.sync.aligned.m8n8.x4.trans.shared.b16 {%0,%1,%2,%3}, [%4];"
                 : "=r"(r[0]), "=r"(r[1]), "=r"(r[2]), "=r"(r[3]) : "r"(addr));
}

// fp16 MMA, fp32 accumulate
__device__ __forceinline__ void mma_f16(float* d, const uint32_t* a,
                                        uint32_t b0, uint32_t b1) {
    asm volatile(
        "mma.sync.aligned.m16n8k16.row.col.f32.f16.f16.f32 "
        "{%0,%1,%2,%3}, {%4,%5,%6,%7}, {%8,%9}, {%0,%1,%2,%3};"
        : "+f"(d[0]), "+f"(d[1]), "+f"(d[2]), "+f"(d[3])
        : "r"(a[0]), "r"(a[1]), "r"(a[2]), "r"(a[3]), "r"(b0), "r"(b1));
}

__device__ __forceinline__ uint32_t pkh2(float lo, float hi) {
    __half2 t = __floats2half2_rn(lo, hi);
    return *(uint32_t*)&t;
}
__device__ __forceinline__ float ex2f(float x) {
    float r; asm("ex2.approx.f32 %0, %1;" : "=f"(r) : "f"(x)); return r;
}

// =====================================================================
// GEMM: 128x128, BK=32, fp16 mma.sync, 4-stage cp.async pipeline
// =====================================================================
#define TILE_BYTES 8192
#define STAGE_BYTES (2 * TILE_BYTES)       // A, B per stage = 16 KB
#define GEMM_STAGES 4
#define GEMM_SMEM (GEMM_STAGES * STAGE_BYTES)   // 65536

__device__ __forceinline__ uint32_t sw_off(int row, int c) {
    return (uint32_t)(row * 64 + ((c ^ ((row >> 1) & 3)) * 16));
}

__device__ __forceinline__ void load_stage(
    const __half* A, const __half* Bm,
    int m0, int n0, int k0, uint32_t sbase, int tid)
{
#pragma unroll
    for (int i = 0; i < 2; i++) {
        int q = tid + i * 256;        // 512 chunks per tile
        int row = q >> 2;
        int c = q & 3;
        uint32_t so = sw_off(row, c);
        cp16(sbase + so, A + (size_t)(m0 + row) * KDIM + k0 + c * 8);
        cp16(sbase + TILE_BYTES + so, Bm + (size_t)(n0 + row) * KDIM + k0 + c * 8);
    }
}

__device__ __forceinline__ void compute_stage(uint32_t sbase, int lane,
                                              int m_warp, int n_warp,
                                              float acc[4][4][4])
{
    const uint32_t aBase = sbase;
    const uint32_t bBase = sbase + TILE_BYTES;

    const int a_r  = lane & 15;
    const int a_kh = (lane >> 4) & 1;
    const int b_r  = (lane & 7) + ((lane >> 4) & 1) * 8;
    const int b_kh = (lane >> 3) & 1;

#pragma unroll
    for (int s = 0; s < 2; s++) {          // two k16 steps
        uint32_t bh[8];
#pragma unroll
        for (int p = 0; p < 2; p++) {
            int rn = n_warp + p * 16 + b_r;
            int c = s * 2 + b_kh;
            ldmx4(&bh[p * 4], bBase + sw_off(rn, c));
        }
#pragma unroll
        for (int mt = 0; mt < 4; mt++) {
            int rm = m_warp + mt * 16 + a_r;
            int c = s * 2 + a_kh;
            uint32_t ah[4];
            ldmx4(ah, aBase + sw_off(rm, c));
#pragma unroll
            for (int nt = 0; nt < 4; nt++)
                mma_f16(acc[mt][nt], ah, bh[nt * 2], bh[nt * 2 + 1]);
        }
    }
}

__device__ __forceinline__ void gemm_mainloop_mma(
    const __half* A, const __half* Bm,
    int m0, int n0, uint32_t smem_u, int tid,
    int m_warp, int n_warp, float acc[4][4][4])
{
    const int lane = tid & 31;
    const int NIT = KDIM / 32;     // 24

    load_stage(A, Bm, m0, n0, 0, smem_u, tid);
    CP_COMMIT();
    load_stage(A, Bm, m0, n0, 32, smem_u + STAGE_BYTES, tid);
    CP_COMMIT();
    load_stage(A, Bm, m0, n0, 64, smem_u + 2 * STAGE_BYTES, tid);
    CP_COMMIT();

#pragma unroll 1
    for (int it = 0; it < NIT; it++) {
        CP_WAIT2();                    // stage `it` resident
        __syncthreads();               // everyone done with stage it-1 (same buf as it+3)
        if (it + 3 < NIT)
            load_stage(A, Bm, m0, n0, (it + 3) * 32,
                       smem_u + ((it + 3) & 3) * STAGE_BYTES, tid);
        CP_COMMIT();                   // always commit (empty group at tail)
        compute_stage(smem_u + (it & 3) * STAGE_BYTES, lane, m_warp, n_warp, acc);
    }
}

// ---- QKV: X @ WaT^T -> scatter fp16 Q/K/V (+bias, Q*0.125*log2e) ----------
__global__ void __launch_bounds__(256, 2)
gemm_qkv_mma(const float* __restrict__ bias)
{
    extern __shared__ char smem[];
    uint32_t smem_u = smem_to_u32(smem);
    const int tid = threadIdx.x;
    const int wid = tid >> 5, lane = tid & 31;
    const int m_warp = (wid >> 2) * 64, n_warp = (wid & 3) * 32;
    const int n0 = blockIdx.x * 128, m0 = blockIdx.y * 128;

    float acc[4][4][4];
#pragma unroll
    for (int i = 0; i < 4; i++)
#pragma unroll
        for (int j = 0; j < 4; j++)
#pragma unroll
            for (int k = 0; k < 4; k++) acc[i][j][k] = 0.f;

    gemm_mainloop_mma(g_X16, g_WaT, m0, n0, smem_u, tid, m_warp, n_warp, acc);

    const int gg = lane >> 2, tig = lane & 3;
#pragma unroll
    for (int mt = 0; mt < 4; mt++) {
#pragma unroll
        for (int nt = 0; nt < 4; nt++) {
            int col = n0 + n_warp + nt * 8 + tig * 2;
            int which = col / C_;
            int c = col - which * C_;
            int h = c >> 6, d = c & 63;
            float bx = bias[col], by = bias[col + 1];
            __half* dst = (which == 0) ? g_Qh : (which == 1) ? g_Kh : g_Vh;
            // fold 1/sqrt(64) * log2(e) into Q for base-2 softmax
            float scl = (which == 0) ? 0.18033688011112042f : 1.0f;
#pragma unroll
            for (int rr = 0; rr < 2; rr++) {
                int m = m0 + m_warp + mt * 16 + gg + rr * 8;
                int b = m >> 10, t = m & 1023;
                float vx = (acc[mt][nt][rr * 2 + 0] + bx) * scl;
                float vy = (acc[mt][nt][rr * 2 + 1] + by) * scl;
                *(uint32_t*)(dst + ((size_t)(b * H_ + h) * T_ + t) * HD_ + d) =
                    pkh2(vx, vy);
            }
        }
    }
}

// ---- Proj: ATT @ WpT^T + b_proj -> out ------------------------------------
__global__ void __launch_bounds__(256, 2)
gemm_proj_mma(const float* __restrict__ bias, float* __restrict__ out)
{
    extern __shared__ char smem[];
    uint32_t smem_u = smem_to_u32(smem);
    const int tid = threadIdx.x;
    const int wid = tid >> 5, lane = tid & 31;
    const int m_warp = (wid >> 2) * 64, n_warp = (wid & 3) * 32;
    const int n0 = blockIdx.x * 128, m0 = blockIdx.y * 128;

    float acc[4][4][4];
#pragma unroll
    for (int i = 0; i < 4; i++)
#pragma unroll
        for (int j = 0; j < 4; j++)
#pragma unroll
            for (int k = 0; k < 4; k++) acc[i][j][k] = 0.f;

    gemm_mainloop_mma(g_ATT, g_WpT, m0, n0, smem_u, tid, m_warp, n_warp, acc);

    const int gg = lane >> 2, tig = lane & 3;
#pragma unroll
    for (int mt = 0; mt < 4; mt++) {
#pragma unroll
        for (int nt = 0; nt < 4; nt++) {
            int col = n0 + n_warp + nt * 8 + tig * 2;
            float bx = bias[col], by = bias[col + 1];
#pragma unroll
            for (int rr = 0; rr < 2; rr++) {
                int m = m0 + m_warp + mt * 16 + gg + rr * 8;
                float2 v;
                v.x = acc[mt][nt][rr * 2 + 0] + bx;
                v.y = acc[mt][nt][rr * 2 + 1] + by;
                *(float2*)(out + (size_t)m * C_ + col) = v;
            }
        }
    }
}

// =====================================================================
// preprocessing: fp32 -> fp16 (+ transposes for weights)
// =====================================================================
__global__ void to_half_kernel(const float* __restrict__ X,
                               __half* __restrict__ Y, int n4)
{
    int idx = blockIdx.x * blockDim.x + threadIdx.x;
    if (idx >= n4) return;
    float4 v = ((const float4*)X)[idx];
    __half2* py = (__half2*)(Y + 4 * (size_t)idx);
    py[0] = __floats2half2_rn(v.x, v.y);
    py[1] = __floats2half2_rn(v.z, v.w);
}

__global__ void transpose_half_kernel(const float* __restrict__ W,
                                      __half* __restrict__ Th, int K, int N)
{
    __shared__ float tile[32][33];
    const int nb = blockIdx.x * 32, kb = blockIdx.y * 32;
    const int tx = threadIdx.x, ty = threadIdx.y;  // 32 x 8
#pragma unroll
    for (int i = 0; i < 32; i += 8)
        tile[ty + i][tx] = W[(size_t)(kb + ty + i) * N + nb + tx];
    __syncthreads();
#pragma unroll
    for (int i = 0; i < 32; i += 8) {
        int n = nb + ty + i, k = kb + tx;
        Th[(size_t)n * K + k] = __float2half_rn(tile[tx][ty + i]);
    }
}

// =====================================================================
// meanV (reads fp16 V, fp32 accumulate)
// =====================================================================
__global__ void meanv_kernel()
{
    __shared__ float red[256];
    const int bh = blockIdx.x;
    const int tid = threadIdx.x;
    const int d = tid & 63;
    const int part = tid >> 6;
    const size_t base = (size_t)bh * T_ * HD_;
    float s = 0.f;
    const int t0 = part * 256;
    for (int t = t0; t < t0 + 256; t++)
        s += __half2float(g_Vh[base + (size_t)t * HD_ + d]);
    red[tid] = s;
    __syncthreads();
    if (part == 0)
        g_meanV[bh * HD_ + d] =
            (red[d] + red[d + 64] + red[d + 128] + red[d + 192]) * (1.0f / 1024.0f);
}

// =====================================================================
// Tensor-core flash attention: fp16, cp.async K/V, ldmatrix.trans for V
// smem: Q 8KB | stage0 {K,V} 16KB | stage1 {K,V} 16KB = 40KB
// =====================================================================
#define QK_OFF(row, chunk) \
    ((uint32_t)((row) * 128 + ((((chunk) ^ ((row) & 7))) * 16)))
#define ATTN_SMEM 40960

__device__ __forceinline__ void attn_load_kv(const __half* gk, const __half* gv,
                                             uint32_t uK, uint32_t uV, int tid)
{
#pragma unroll
    for (int i = 0; i < 4; i++) {
        int q = tid + i * 128;        // 512 chunks per 8KB tile
        int row = q >> 3, c = q & 7;
        uint32_t off = QK_OFF(row, c);
        cp16(uK + off, gk + (size_t)row * 64 + c * 8);
        cp16(uV + off, gv + (size_t)row * 64 + c * 8);
    }
}

__global__ void __launch_bounds__(128, 4)
attn_mma_kernel(const int* __restrict__ mask)
{
    extern __shared__ char smem[];
    const uint32_t su = smem_to_u32(smem);
    const uint32_t uQ = su;
    // stage s: K at 8192 + s*16384, V at 16384 + s*16384

    const int tid = threadIdx.x;
    const int w = tid >> 5, lane = tid & 31;
    const int g = lane >> 2, tig = lane & 3;
    const int qt = (int)gridDim.x - 1 - blockIdx.x;   // heavy tiles first
    const int bh = blockIdx.y;
    const int b = bh / H_, h = bh - b * H_;
    const int q0 = qt * QT;

    const __half* gq_base = g_Qh + ((size_t)bh * T_ + q0) * HD_;
    const __half* gk_bh = g_Kh + (size_t)bh * T_ * HD_;
    const __half* gv_bh = g_Vh + (size_t)bh * T_ * HD_;

    // ---- Q tile + first K/V stage via cp.async ----
#pragma unroll
    for (int i = 0; i < 4; i++) {
        int q = tid + i * 128;
        int row = q >> 3, c = q & 7;
        cp16(uQ + QK_OFF(row, c), gq_base + (size_t)row * 64 + c * 8);
    }
    attn_load_kv(gk_bh, gv_bh, su + 8192, su + 16384, tid);
    CP_COMMIT();

    float o[8][4];
#pragma unroll
    for (int i = 0; i < 8; i++)
#pragma unroll
        for (int j = 0; j < 4; j++) o[i][j] = 0.f;
    float m0 = -1e30f, m1 = -1e30f, l0 = 0.f, l1 = 0.f;

    const int a_row = w * 16 + (lane & 15);
    const int a_kh = (lane >> 4) & 1;
    const int b_r = (lane & 7) + ((lane >> 4) & 1) * 8;
    const int b_kh = (lane >> 3) & 1;
    // V trans-fragment lane addressing (t-row / d-chunk)
    const int vt_r = (lane & 7) + ((lane >> 3) & 1) * 8;
    const int vd_c = (lane >> 4) & 1;

#pragma unroll 1
    for (int kt = 0; kt <= qt; kt++) {
        CP_WAIT0();
        __syncthreads();   // stage kt ready; all threads done with stage kt-1
        if (kt < qt) {
            attn_load_kv(gk_bh + (size_t)(kt + 1) * 64 * HD_,
                         gv_bh + (size_t)(kt + 1) * 64 * HD_,
                         su + 8192 + ((kt + 1) & 1) * 16384,
                         su + 16384 + ((kt + 1) & 1) * 16384, tid);
            CP_COMMIT();
        }
        const uint32_t uK = su + 8192 + (kt & 1) * 16384;
        const uint32_t uV = su + 16384 + (kt & 1) * 16384;

        // ---- S = Q K^T (m16 x n64, k=64) ----
        float s[8][4];
#pragma unroll
        for (int i = 0; i < 8; i++)
#pragma unroll
            for (int j = 0; j < 4; j++) s[i][j] = 0.f;

#pragma unroll
        for (int ks = 0; ks < 4; ks++) {
            uint32_t ah[4];
            ldmx4(ah, uQ + QK_OFF(a_row, ks * 2 + a_kh));
#pragma unroll
            for (int np = 0; np < 4; np++) {
                uint32_t kb[4];
                ldmx4(kb, uK + QK_OFF(np * 16 + b_r, ks * 2 + b_kh));
                mma_f16(s[np * 2], ah, kb[0], kb[1]);
                mma_f16(s[np * 2 + 1], ah, kb[2], kb[3]);
            }
        }

        // causal mask on diagonal tile
        if (kt == qt) {
            const int r0 = w * 16 + g, r1 = r0 + 8;
#pragma unroll
            for (int nt = 0; nt < 8; nt++) {
                int c = nt * 8 + tig * 2;
                if (c > r0)     s[nt][0] = -1e30f;
                if (c + 1 > r0) s[nt][1] = -1e30f;
                if (c > r1)     s[nt][2] = -1e30f;
                if (c + 1 > r1) s[nt][3] = -1e30f;
            }
        }

        // ---- online softmax (base-2; log2e folded into Q) ----
        float mx0 = -1e30f, mx1 = -1e30f;
#pragma unroll
        for (int nt = 0; nt < 8; nt++) {
            mx0 = fmaxf(mx0, fmaxf(s[nt][0], s[nt][1]));
            mx1 = fmaxf(mx1, fmaxf(s[nt][2], s[nt][3]));
        }
        mx0 = fmaxf(mx0, __shfl_xor_sync(0xffffffffu, mx0, 1));
        mx0 = fmaxf(mx0, __shfl_xor_sync(0xffffffffu, mx0, 2));
        mx1 = fmaxf(mx1, __shfl_xor_sync(0xffffffffu, mx1, 1));
        mx1 = fmaxf(mx1, __shfl_xor_sync(0xffffffffu, mx1, 2));
        float mn0 = fmaxf(m0, mx0), mn1 = fmaxf(m1, mx1);
        float cr0 = ex2f(m0 - mn0), cr1 = ex2f(m1 - mn1);
        m0 = mn0; m1 = mn1;

        float sum0 = 0.f, sum1 = 0.f;
#pragma unroll
        for (int nt = 0; nt < 8; nt++) {
            s[nt][0] = ex2f(s[nt][0] - mn0);
            s[nt][1] = ex2f(s[nt][1] - mn0);
            s[nt][2] = ex2f(s[nt][2] - mn1);
            s[nt][3] = ex2f(s[nt][3] - mn1);
            sum0 += s[nt][0] + s[nt][1];
            sum1 += s[nt][2] + s[nt][3];
        }
        sum0 += __shfl_xor_sync(0xffffffffu, sum0, 1);
        sum0 += __shfl_xor_sync(0xffffffffu, sum0, 2);
        sum1 += __shfl_xor_sync(0xffffffffu, sum1, 1);
        sum1 += __shfl_xor_sync(0xffffffffu, sum1, 2);
        l0 = l0 * cr0 + sum0;
        l1 = l1 * cr1 + sum1;

#pragma unroll
        for (int nt = 0; nt < 8; nt++) {
            o[nt][0] *= cr0; o[nt][1] *= cr0;
            o[nt][2] *= cr1; o[nt][3] *= cr1;
        }

        // ---- O += P V  (V B-frags via ldmatrix.trans on [t][d] tile) ----
#pragma unroll
        for (int kc = 0; kc < 4; kc++) {
            const float* sa = s[2 * kc];
            const float* sb = s[2 * kc + 1];
            uint32_t pah[4];
            pah[0] = pkh2(sa[0], sa[1]);
            pah[1] = pkh2(sa[2], sa[3]);
            pah[2] = pkh2(sb[0], sb[1]);
            pah[3] = pkh2(sb[2], sb[3]);
#pragma unroll
            for (int np = 0; np < 4; np++) {
                uint32_t vb[4];
                ldmx4t(vb, uV + QK_OFF(kc * 16 + vt_r, np * 2 + vd_c));
                mma_f16(o[np * 2], pah, vb[0], vb[1]);
                mma_f16(o[np * 2 + 1], pah, vb[2], vb[3]);
            }
        }
    }

    // ---- epilogue: normalize, masked-row override, fp16 store ----
    const float il0 = 1.f / l0, il1 = 1.f / l1;
    const int r0g = q0 + w * 16 + g, r1g = r0g + 8;
    const bool mk0 = (mask[b * T_ + r0g] == 0);
    const bool mk1 = (mask[b * T_ + r1g] == 0);
    const size_t ob0 = ((size_t)b * T_ + r0g) * C_ + h * 64;
    const size_t ob1 = ((size_t)b * T_ + r1g) * C_ + h * 64;
#pragma unroll
    for (int nt = 0; nt < 8; nt++) {
        int d = nt * 8 + tig * 2;
        float y0 = o[nt][0] * il0, y1 = o[nt][1] * il0;
        if (mk0) { y0 = g_meanV[bh * 64 + d]; y1 = g_meanV[bh * 64 + d + 1]; }
        *(uint32_t*)(g_ATT + ob0 + d) = pkh2(y0, y1);
        float z0 = o[nt][2] * il1, z1 = o[nt][3] * il1;
        if (mk1) { z0 = g_meanV[bh * 64 + d]; z1 = g_meanV[bh * 64 + d + 1]; }
        *(uint32_t*)(g_ATT + ob1 + d) = pkh2(z0, z1);
    }
}

// =====================================================================
// launcher
// =====================================================================
extern "C" void kernel_launch(void* const* d_in, const int* in_sizes, int n_in,
                              void* d_out, int out_size)
{
    const float* x      = (const float*)d_in[0];
    const int*   mask   = (const int*)d_in[1];
    const float* W_attn = (const float*)d_in[2];
    const float* b_attn = (const float*)d_in[3];
    const float* W_proj = (const float*)d_in[4];
    const float* b_proj = (const float*)d_in[5];
    float* out = (float*)d_out;

    __half *p_X16, *p_WaT, *p_WpT;
    cudaGetSymbolAddress((void**)&p_X16, g_X16);
    cudaGetSymbolAddress((void**)&p_WaT, g_WaT);
    cudaGetSymbolAddress((void**)&p_WpT, g_WpT);

    // 0) fp32 -> fp16 preprocessing
    to_half_kernel<<<(M_ * C_ / 4 + 255) / 256, 256>>>(x, p_X16, M_ * C_ / 4);
    transpose_half_kernel<<<dim3(N3C / 32, C_ / 32), dim3(32, 8)>>>(
        W_attn, p_WaT, C_, N3C);
    transpose_half_kernel<<<dim3(C_ / 32, C_ / 32), dim3(32, 8)>>>(
        W_proj, p_WpT, C_, C_);

    // 1) QKV projection via mma.sync fp16 (4-stage pipeline)
    {
        cudaFuncSetAttribute(gemm_qkv_mma,
                             cudaFuncAttributeMaxDynamicSharedMemorySize, GEMM_SMEM);
        dim3 grid(N3C / 128, M_ / 128);
        gemm_qkv_mma<<<grid, 256, GEMM_SMEM>>>(b_attn);
    }
    // 2) per-(b,h) mean of V
    meanv_kernel<<<B_ * H_, 256>>>();
    // 3) causal flash attention on tensor cores (fp16, async K/V)
    {
        cudaFuncSetAttribute(attn_mma_kernel,
                             cudaFuncAttributeMaxDynamicSharedMemorySize, ATTN_SMEM);
        dim3 grid(T_ / QT, B_ * H_);
        attn_mma_kernel<<<grid, 128, ATTN_SMEM>>>(mask);
    }
    // 4) output projection via mma.sync fp16 (4-stage pipeline)
    {
        cudaFuncSetAttribute(gemm_proj_mma,
                             cudaFuncAttributeMaxDynamicSharedMemorySize, GEMM_SMEM);
        dim3 grid(C_ / 128, M_ / 128);
        gemm_proj_mma<<<grid, 256, GEMM_SMEM>>>(b_proj, out);
    }
}

// round 14
// speedup vs baseline: 6.6934x; 1.0200x over previous
#include <cuda_runtime.h>
#include <cuda_fp16.h>
#include <cstdint>
#include <math.h>

// Problem constants
#define B_   8
#define T_   1024
#define C_   768
#define H_   12
#define HD_  64
#define M_   (B_ * T_)      // 8192
#define N3C  (3 * C_)       // 2304
#define KDIM 768

// ---------------- scratch (device globals; no allocations allowed) ----------
__device__ __half g_Qh[B_ * H_ * T_ * HD_];   // [B,H,T,HD], scaled 0.125*log2e
__device__ __half g_Kh[B_ * H_ * T_ * HD_];
__device__ __half g_Vh[B_ * H_ * T_ * HD_];
__device__ float  g_meanV[B_ * H_ * HD_];

__device__ __half g_X16[M_ * C_];             // x        [8192,768]
__device__ __half g_WaT[N3C * C_];            // W_attn^T [2304,768] (k-contig)
__device__ __half g_WpT[C_ * C_];             // W_proj^T [768,768]
__device__ __half g_ATT[M_ * C_];             // attention out [8192,768]

// =====================================================================
// family-common PTX helpers (NO tcgen05 — ptx target is sm_103 base)
// =====================================================================
__device__ __forceinline__ uint32_t smem_to_u32(const void* p) {
    uint32_t a;
    asm("{ .reg .u64 t; cvta.to.shared.u64 t, %1; cvt.u32.u64 %0, t; }"
        : "=r"(a) : "l"(p));
    return a;
}

__device__ __forceinline__ void cp16(uint32_t saddr, const void* g) {
    asm volatile("cp.async.cg.shared.global [%0], [%1], 16;"
                 :: "r"(saddr), "l"(g));
}
#define CP_COMMIT() asm volatile("cp.async.commit_group;")
#define CP_WAIT0()  asm volatile("cp.async.wait_group 0;")
#define CP_WAIT1()  asm volatile("cp.async.wait_group 1;")

__device__ __forceinline__ void ldmx4(uint32_t* r, uint32_t addr) {
    asm volatile("ldmatrix.sync.aligned.m8n8.x4.shared.b16 {%0,%1,%2,%3}, [%4];"
                 : "=r"(r[0]), "=r"(r[1]), "=r"(r[2]), "=r"(r[3]) : "r"(addr));
}
__device__ __forceinline__ void ldmx4t(uint32_t* r, uint32_t addr) {
    asm volatile("ldmatrix.sync.aligned.m8n8.x4.trans.shared.b16 {%0,%1,%2,%3}, [%4];"
                 : "=r"(r[0]), "=r"(r[1]), "=r"(r[2]), "=r"(r[3]) : "r"(addr));
}

// fp16 MMA, fp32 accumulate
__device__ __forceinline__ void mma_f16(float* d, const uint32_t* a,
                                        uint32_t b0, uint32_t b1) {
    asm volatile(
        "mma.sync.aligned.m16n8k16.row.col.f32.f16.f16.f32 "
        "{%0,%1,%2,%3}, {%4,%5,%6,%7}, {%8,%9}, {%0,%1,%2,%3};"
        : "+f"(d[0]), "+f"(d[1]), "+f"(d[2]), "+f"(d[3])
        : "r"(a[0]), "r"(a[1]), "r"(a[2]), "r"(a[3]), "r"(b0), "r"(b1));
}

__device__ __forceinline__ uint32_t pkh2(float lo, float hi) {
    __half2 t = __floats2half2_rn(lo, hi);
    return *(uint32_t*)&t;
}
__device__ __forceinline__ float ex2f(float x) {
    float r; asm("ex2.approx.f32 %0, %1;" : "=f"(r) : "f"(x)); return r;
}

// 128B-row swizzled tile offset: [rows][64 half] rows of 8 16B chunks
__device__ __forceinline__ uint32_t qkoff(int row, int c) {
    return (uint32_t)(row * 128 + ((c ^ (row & 7)) * 16));
}

// =====================================================================
// GEMM: 128x128 tile, BK=64, fp16 mma.sync, 3-stage cp.async pipeline
// =====================================================================
#define TILE_B64 16384                     // 128 rows x 64 half (128B rows)
#define STAGE_B64 (2 * TILE_B64)           // A + B = 32 KB
#define GEMM_SMEM (3 * STAGE_B64)          // 98304

__device__ __forceinline__ void load_stage64(
    const __half* A, const __half* Bm,
    int m0, int n0, int k0, uint32_t sbase, int tid)
{
#pragma unroll
    for (int i = 0; i < 4; i++) {
        int q = tid + i * 256;             // 1024 chunks per tile
        int row = q >> 3;
        int c = q & 7;
        uint32_t so = qkoff(row, c);
        cp16(sbase + so, A + (size_t)(m0 + row) * KDIM + k0 + c * 8);
        cp16(sbase + TILE_B64 + so, Bm + (size_t)(n0 + row) * KDIM + k0 + c * 8);
    }
}

__device__ __forceinline__ void compute_stage64(uint32_t sbase, int lane,
                                                int m_warp, int n_warp,
                                                float acc[4][4][4])
{
    const uint32_t aBase = sbase;
    const uint32_t bBase = sbase + TILE_B64;

    const int a_r  = lane & 15;
    const int a_kh = (lane >> 4) & 1;
    const int b_r  = (lane & 7) + ((lane >> 4) & 1) * 8;
    const int b_kh = (lane >> 3) & 1;

#pragma unroll
    for (int s = 0; s < 4; s++) {          // four k16 steps
        uint32_t bh[8];
#pragma unroll
        for (int p = 0; p < 2; p++) {
            int rn = n_warp + p * 16 + b_r;
            ldmx4(&bh[p * 4], bBase + qkoff(rn, s * 2 + b_kh));
        }
#pragma unroll
        for (int mt = 0; mt < 4; mt++) {
            int rm = m_warp + mt * 16 + a_r;
            uint32_t ah[4];
            ldmx4(ah, aBase + qkoff(rm, s * 2 + a_kh));
#pragma unroll
            for (int nt = 0; nt < 4; nt++)
                mma_f16(acc[mt][nt], ah, bh[nt * 2], bh[nt * 2 + 1]);
        }
    }
}

__device__ __forceinline__ void gemm_mainloop_mma(
    const __half* A, const __half* Bm,
    int m0, int n0, uint32_t smem_u, int tid,
    int m_warp, int n_warp, float acc[4][4][4])
{
    const int lane = tid & 31;
    const int NIT = KDIM / 64;             // 12

    load_stage64(A, Bm, m0, n0, 0, smem_u, tid);
    CP_COMMIT();
    load_stage64(A, Bm, m0, n0, 64, smem_u + STAGE_B64, tid);
    CP_COMMIT();

#pragma unroll 1
    for (int it = 0; it < NIT; it++) {
        CP_WAIT1();                        // stage `it` resident
        __syncthreads();                   // all threads done with stage it-1
        if (it + 2 < NIT)
            load_stage64(A, Bm, m0, n0, (it + 2) * 64,
                         smem_u + ((it + 2) % 3) * STAGE_B64, tid);
        CP_COMMIT();                       // always commit (empty at tail)
        compute_stage64(smem_u + (it % 3) * STAGE_B64, lane, m_warp, n_warp, acc);
    }
}

// ---- QKV: X @ WaT^T -> scatter fp16 Q/K/V (+bias, Q*0.125*log2e) ----------
__global__ void __launch_bounds__(256, 2)
gemm_qkv_mma(const float* __restrict__ bias)
{
    extern __shared__ char smem[];
    uint32_t smem_u = smem_to_u32(smem);
    const int tid = threadIdx.x;
    const int wid = tid >> 5, lane = tid & 31;
    const int m_warp = (wid >> 2) * 64, n_warp = (wid & 3) * 32;
    const int n0 = blockIdx.x * 128, m0 = blockIdx.y * 128;

    float acc[4][4][4];
#pragma unroll
    for (int i = 0; i < 4; i++)
#pragma unroll
        for (int j = 0; j < 4; j++)
#pragma unroll
            for (int k = 0; k < 4; k++) acc[i][j][k] = 0.f;

    gemm_mainloop_mma(g_X16, g_WaT, m0, n0, smem_u, tid, m_warp, n_warp, acc);

    const int gg = lane >> 2, tig = lane & 3;
#pragma unroll
    for (int mt = 0; mt < 4; mt++) {
#pragma unroll
        for (int nt = 0; nt < 4; nt++) {
            int col = n0 + n_warp + nt * 8 + tig * 2;
            int which = col / C_;
            int c = col - which * C_;
            int h = c >> 6, d = c & 63;
            float bx = bias[col], by = bias[col + 1];
            __half* dst = (which == 0) ? g_Qh : (which == 1) ? g_Kh : g_Vh;
            // fold 1/sqrt(64) * log2(e) into Q for base-2 softmax
            float scl = (which == 0) ? 0.18033688011112042f : 1.0f;
#pragma unroll
            for (int rr = 0; rr < 2; rr++) {
                int m = m0 + m_warp + mt * 16 + gg + rr * 8;
                int b = m >> 10, t = m & 1023;
                float vx = (acc[mt][nt][rr * 2 + 0] + bx) * scl;
                float vy = (acc[mt][nt][rr * 2 + 1] + by) * scl;
                *(uint32_t*)(dst + ((size_t)(b * H_ + h) * T_ + t) * HD_ + d) =
                    pkh2(vx, vy);
            }
        }
    }
}

// ---- Proj: ATT @ WpT^T + b_proj -> out ------------------------------------
__global__ void __launch_bounds__(256, 2)
gemm_proj_mma(const float* __restrict__ bias, float* __restrict__ out)
{
    extern __shared__ char smem[];
    uint32_t smem_u = smem_to_u32(smem);
    const int tid = threadIdx.x;
    const int wid = tid >> 5, lane = tid & 31;
    const int m_warp = (wid >> 2) * 64, n_warp = (wid & 3) * 32;
    const int n0 = blockIdx.x * 128, m0 = blockIdx.y * 128;

    float acc[4][4][4];
#pragma unroll
    for (int i = 0; i < 4; i++)
#pragma unroll
        for (int j = 0; j < 4; j++)
#pragma unroll
            for (int k = 0; k < 4; k++) acc[i][j][k] = 0.f;

    gemm_mainloop_mma(g_ATT, g_WpT, m0, n0, smem_u, tid, m_warp, n_warp, acc);

    const int gg = lane >> 2, tig = lane & 3;
#pragma unroll
    for (int mt = 0; mt < 4; mt++) {
#pragma unroll
        for (int nt = 0; nt < 4; nt++) {
            int col = n0 + n_warp + nt * 8 + tig * 2;
            float bx = bias[col], by = bias[col + 1];
#pragma unroll
            for (int rr = 0; rr < 2; rr++) {
                int m = m0 + m_warp + mt * 16 + gg + rr * 8;
                float2 v;
                v.x = acc[mt][nt][rr * 2 + 0] + bx;
                v.y = acc[mt][nt][rr * 2 + 1] + by;
                *(float2*)(out + (size_t)m * C_ + col) = v;
            }
        }
    }
}

// =====================================================================
// preprocessing: fp32 -> fp16 (+ transposes for weights)
// =====================================================================
__global__ void to_half_kernel(const float* __restrict__ X,
                               __half* __restrict__ Y, int n4)
{
    int idx = blockIdx.x * blockDim.x + threadIdx.x;
    if (idx >= n4) return;
    float4 v = ((const float4*)X)[idx];
    __half2* py = (__half2*)(Y + 4 * (size_t)idx);
    py[0] = __floats2half2_rn(v.x, v.y);
    py[1] = __floats2half2_rn(v.z, v.w);
}

__global__ void transpose_half_kernel(const float* __restrict__ W,
                                      __half* __restrict__ Th, int K, int N)
{
    __shared__ float tile[32][33];
    const int nb = blockIdx.x * 32, kb = blockIdx.y * 32;
    const int tx = threadIdx.x, ty = threadIdx.y;  // 32 x 8
#pragma unroll
    for (int i = 0; i < 32; i += 8)
        tile[ty + i][tx] = W[(size_t)(kb + ty + i) * N + nb + tx];
    __syncthreads();
#pragma unroll
    for (int i = 0; i < 32; i += 8) {
        int n = nb + ty + i, k = kb + tx;
        Th[(size_t)n * K + k] = __float2half_rn(tile[tx][ty + i]);
    }
}

// =====================================================================
// meanV (reads fp16 V, fp32 accumulate)
// =====================================================================
__global__ void meanv_kernel()
{
    __shared__ float red[256];
    const int bh = blockIdx.x;
    const int tid = threadIdx.x;
    const int d = tid & 63;
    const int part = tid >> 6;
    const size_t base = (size_t)bh * T_ * HD_;
    float s = 0.f;
    const int t0 = part * 256;
    for (int t = t0; t < t0 + 256; t++)
        s += __half2float(g_Vh[base + (size_t)t * HD_ + d]);
    red[tid] = s;
    __syncthreads();
    if (part == 0)
        g_meanV[bh * HD_ + d] =
            (red[d] + red[d + 64] + red[d + 128] + red[d + 192]) * (1.0f / 1024.0f);
}

// =====================================================================
// Tensor-core flash attention: QT=128, 8 warps, fp16, async K/V
// smem: Q 16KB | stage0 {K,V} 16KB | stage1 {K,V} 16KB = 48KB
// =====================================================================
#define ATTN_SMEM 49152

__device__ __forceinline__ void attn_load_kv(const __half* gk, const __half* gv,
                                             uint32_t uK, uint32_t uV, int tid)
{
#pragma unroll
    for (int i = 0; i < 2; i++) {
        int q = tid + i * 256;        // 512 chunks per 8KB tile
        int row = q >> 3, c = q & 7;
        uint32_t off = qkoff(row, c);
        cp16(uK + off, gk + (size_t)row * 64 + c * 8);
        cp16(uV + off, gv + (size_t)row * 64 + c * 8);
    }
}

__global__ void __launch_bounds__(256, 2)
attn_mma_kernel(const int* __restrict__ mask)
{
    extern __shared__ char smem[];
    const uint32_t su = smem_to_u32(smem);
    const uint32_t uQ = su;
    // stage s: K at 16384 + s*16384, V at 24576 + s*16384

    const int tid = threadIdx.x;
    const int w = tid >> 5, lane = tid & 31;
    const int g = lane >> 2, tig = lane & 3;
    const int qq = (int)gridDim.x - 1 - blockIdx.x;   // heavy tiles first
    const int bh = blockIdx.y;
    const int b = bh / H_, h = bh - b * H_;
    const int q0 = qq * 128;
    const int NK = 2 * qq + 2;

    const __half* gq = g_Qh + ((size_t)bh * T_ + q0) * HD_;
    const __half* gk_bh = g_Kh + (size_t)bh * T_ * HD_;
    const __half* gv_bh = g_Vh + (size_t)bh * T_ * HD_;

    // ---- Q tile (128 rows) + first K/V stage via cp.async ----
#pragma unroll
    for (int i = 0; i < 4; i++) {
        int q = tid + i * 256;
        int row = q >> 3, c = q & 7;
        cp16(uQ + qkoff(row, c), gq + (size_t)row * 64 + c * 8);
    }
    attn_load_kv(gk_bh, gv_bh, su + 16384, su + 24576, tid);
    CP_COMMIT();

    float o[8][4];
#pragma unroll
    for (int i = 0; i < 8; i++)
#pragma unroll
        for (int j = 0; j < 4; j++) o[i][j] = 0.f;
    float m0 = -1e30f, m1 = -1e30f, l0 = 0.f, l1 = 0.f;

    const int a_row = w * 16 + (lane & 15);     // Q row 0..127
    const int a_kh = (lane >> 4) & 1;
    const int b_r = (lane & 7) + ((lane >> 4) & 1) * 8;
    const int b_kh = (lane >> 3) & 1;
    // V trans-fragment lane addressing (t-row / d-chunk)
    const int vt_r = (lane & 7) + ((lane >> 3) & 1) * 8;
    const int vd_c = (lane >> 4) & 1;

#pragma unroll 1
    for (int kt = 0; kt < NK; kt++) {
        CP_WAIT0();
        __syncthreads();   // stage kt ready; all threads done with stage kt-1
        if (kt + 1 < NK) {
            attn_load_kv(gk_bh + (size_t)(kt + 1) * 64 * HD_,
                         gv_bh + (size_t)(kt + 1) * 64 * HD_,
                         su + 16384 + ((kt + 1) & 1) * 16384,
                         su + 24576 + ((kt + 1) & 1) * 16384, tid);
            CP_COMMIT();
        }
        const uint32_t uK = su + 16384 + (kt & 1) * 16384;
        const uint32_t uV = su + 24576 + (kt & 1) * 16384;

        // ---- S = Q K^T (m16 x n64, k=64) ----
        float s[8][4];
#pragma unroll
        for (int i = 0; i < 8; i++)
#pragma unroll
            for (int j = 0; j < 4; j++) s[i][j] = 0.f;

#pragma unroll
        for (int ks = 0; ks < 4; ks++) {
            uint32_t ah[4];
            ldmx4(ah, uQ + qkoff(a_row, ks * 2 + a_kh));
#pragma unroll
            for (int np = 0; np < 4; np++) {
                uint32_t kb[4];
                ldmx4(kb, uK + qkoff(np * 16 + b_r, ks * 2 + b_kh));
                mma_f16(s[np * 2], ah, kb[0], kb[1]);
                mma_f16(s[np * 2 + 1], ah, kb[2], kb[3]);
            }
        }

        // causal mask when this k-tile crosses the warp's diagonal
        if (kt * 64 + 63 > q0 + w * 16) {
            const int r0 = q0 + w * 16 + g, r1 = r0 + 8;
            const int cb = kt * 64 + tig * 2;
#pragma unroll
            for (int nt = 0; nt < 8; nt++) {
                int c = cb + nt * 8;
                if (c > r0)     s[nt][0] = -1e30f;
                if (c + 1 > r0) s[nt][1] = -1e30f;
                if (c > r1)     s[nt][2] = -1e30f;
                if (c + 1 > r1) s[nt][3] = -1e30f;
            }
        }

        // ---- online softmax (base-2; log2e folded into Q) ----
        float mx0 = -1e30f, mx1 = -1e30f;
#pragma unroll
        for (int nt = 0; nt < 8; nt++) {
            mx0 = fmaxf(mx0, fmaxf(s[nt][0], s[nt][1]));
            mx1 = fmaxf(mx1, fmaxf(s[nt][2], s[nt][3]));
        }
        mx0 = fmaxf(mx0, __shfl_xor_sync(0xffffffffu, mx0, 1));
        mx0 = fmaxf(mx0, __shfl_xor_sync(0xffffffffu, mx0, 2));
        mx1 = fmaxf(mx1, __shfl_xor_sync(0xffffffffu, mx1, 1));
        mx1 = fmaxf(mx1, __shfl_xor_sync(0xffffffffu, mx1, 2));
        float mn0 = fmaxf(m0, mx0), mn1 = fmaxf(m1, mx1);
        float cr0 = ex2f(m0 - mn0), cr1 = ex2f(m1 - mn1);
        m0 = mn0; m1 = mn1;

        float sum0 = 0.f, sum1 = 0.f;
#pragma unroll
        for (int nt = 0; nt < 8; nt++) {
            s[nt][0] = ex2f(s[nt][0] - mn0);
            s[nt][1] = ex2f(s[nt][1] - mn0);
            s[nt][2] = ex2f(s[nt][2] - mn1);
            s[nt][3] = ex2f(s[nt][3] - mn1);
            sum0 += s[nt][0] + s[nt][1];
            sum1 += s[nt][2] + s[nt][3];
        }
        sum0 += __shfl_xor_sync(0xffffffffu, sum0, 1);
        sum0 += __shfl_xor_sync(0xffffffffu, sum0, 2);
        sum1 += __shfl_xor_sync(0xffffffffu, sum1, 1);
        sum1 += __shfl_xor_sync(0xffffffffu, sum1, 2);
        l0 = l0 * cr0 + sum0;
        l1 = l1 * cr1 + sum1;

#pragma unroll
        for (int nt = 0; nt < 8; nt++) {
            o[nt][0] *= cr0; o[nt][1] *= cr0;
            o[nt][2] *= cr1; o[nt][3] *= cr1;
        }

        // ---- O += P V  (V B-frags via ldmatrix.trans on [t][d] tile) ----
#pragma unroll
        for (int kc = 0; kc < 4; kc++) {
            const float* sa = s[2 * kc];
            const float* sb = s[2 * kc + 1];
            uint32_t pah[4];
            pah[0] = pkh2(sa[0], sa[1]);
            pah[1] = pkh2(sa[2], sa[3]);
            pah[2] = pkh2(sb[0], sb[1]);
            pah[3] = pkh2(sb[2], sb[3]);
#pragma unroll
            for (int np = 0; np < 4; np++) {
                uint32_t vb[4];
                ldmx4t(vb, uV + qkoff(kc * 16 + vt_r, np * 2 + vd_c));
                mma_f16(o[np * 2], pah, vb[0], vb[1]);
                mma_f16(o[np * 2 + 1], pah, vb[2], vb[3]);
            }
        }
    }

    // ---- epilogue: normalize, masked-row override, fp16 store ----
    const float il0 = 1.f / l0, il1 = 1.f / l1;
    const int r0g = q0 + w * 16 + g, r1g = r0g + 8;
    const bool mk0 = (mask[b * T_ + r0g] == 0);
    const bool mk1 = (mask[b * T_ + r1g] == 0);
    const size_t ob0 = ((size_t)b * T_ + r0g) * C_ + h * 64;
    const size_t ob1 = ((size_t)b * T_ + r1g) * C_ + h * 64;
#pragma unroll
    for (int nt = 0; nt < 8; nt++) {
        int d = nt * 8 + tig * 2;
        float y0 = o[nt][0] * il0, y1 = o[nt][1] * il0;
        if (mk0) { y0 = g_meanV[bh * 64 + d]; y1 = g_meanV[bh * 64 + d + 1]; }
        *(uint32_t*)(g_ATT + ob0 + d) = pkh2(y0, y1);
        float z0 = o[nt][2] * il1, z1 = o[nt][3] * il1;
        if (mk1) { z0 = g_meanV[bh * 64 + d]; z1 = g_meanV[bh * 64 + d + 1]; }
        *(uint32_t*)(g_ATT + ob1 + d) = pkh2(z0, z1);
    }
}

// =====================================================================
// launcher
// =====================================================================
extern "C" void kernel_launch(void* const* d_in, const int* in_sizes, int n_in,
                              void* d_out, int out_size)
{
    const float* x      = (const float*)d_in[0];
    const int*   mask   = (const int*)d_in[1];
    const float* W_attn = (const float*)d_in[2];
    const float* b_attn = (const float*)d_in[3];
    const float* W_proj = (const float*)d_in[4];
    const float* b_proj = (const float*)d_in[5];
    float* out = (float*)d_out;

    __half *p_X16, *p_WaT, *p_WpT;
    cudaGetSymbolAddress((void**)&p_X16, g_X16);
    cudaGetSymbolAddress((void**)&p_WaT, g_WaT);
    cudaGetSymbolAddress((void**)&p_WpT, g_WpT);

    // 0) fp32 -> fp16 preprocessing
    to_half_kernel<<<(M_ * C_ / 4 + 255) / 256, 256>>>(x, p_X16, M_ * C_ / 4);
    transpose_half_kernel<<<dim3(N3C / 32, C_ / 32), dim3(32, 8)>>>(
        W_attn, p_WaT, C_, N3C);
    transpose_half_kernel<<<dim3(C_ / 32, C_ / 32), dim3(32, 8)>>>(
        W_proj, p_WpT, C_, C_);

    // 1) QKV projection via mma.sync fp16 (BK=64, 3-stage pipeline)
    {
        cudaFuncSetAttribute(gemm_qkv_mma,
                             cudaFuncAttributeMaxDynamicSharedMemorySize, GEMM_SMEM);
        dim3 grid(N3C / 128, M_ / 128);
        gemm_qkv_mma<<<grid, 256, GEMM_SMEM>>>(b_attn);
    }
    // 2) per-(b,h) mean of V
    meanv_kernel<<<B_ * H_, 256>>>();
    // 3) causal flash attention on tensor cores (QT=128, fp16, async K/V)
    {
        cudaFuncSetAttribute(attn_mma_kernel,
                             cudaFuncAttributeMaxDynamicSharedMemorySize, ATTN_SMEM);
        dim3 grid(T_ / 128, B_ * H_);
        attn_mma_kernel<<<grid, 256, ATTN_SMEM>>>(mask);
    }
    // 4) output projection via mma.sync fp16 (BK=64, 3-stage pipeline)
    {
        cudaFuncSetAttribute(gemm_proj_mma,
                             cudaFuncAttributeMaxDynamicSharedMemorySize, GEMM_SMEM);
        dim3 grid(C_ / 128, M_ / 128);
        gemm_proj_mma<<<grid, 256, GEMM_SMEM>>>(b_proj, out);
    }
}

// round 15
// speedup vs baseline: 6.7422x; 1.0073x over previous
#include <cuda_runtime.h>
#include <cuda_fp16.h>
#include <cstdint>
#include <math.h>

// Problem constants
#define B_   8
#define T_   1024
#define C_   768
#define H_   12
#define HD_  64
#define M_   (B_ * T_)      // 8192
#define N3C  (3 * C_)       // 2304
#define KDIM 768

// ---------------- scratch (device globals; no allocations allowed) ----------
__device__ __half g_Qh[B_ * H_ * T_ * HD_];   // [B,H,T,HD], scaled 0.125*log2e
__device__ __half g_Kh[B_ * H_ * T_ * HD_];
__device__ __half g_Vh[B_ * H_ * T_ * HD_];
__device__ float  g_meanV[B_ * H_ * HD_];

__device__ __half g_X16[M_ * C_];             // x        [8192,768]
__device__ __half g_WaT[N3C * C_];            // W_attn^T [2304,768] (k-contig)
__device__ __half g_WpT[C_ * C_];             // W_proj^T [768,768]
__device__ __half g_ATT[M_ * C_];             // attention out [8192,768]

// =====================================================================
// family-common PTX helpers (NO tcgen05 — ptx target is sm_103 base)
// =====================================================================
__device__ __forceinline__ uint32_t smem_to_u32(const void* p) {
    uint32_t a;
    asm("{ .reg .u64 t; cvta.to.shared.u64 t, %1; cvt.u32.u64 %0, t; }"
        : "=r"(a) : "l"(p));
    return a;
}

__device__ __forceinline__ void cp16(uint32_t saddr, const void* g) {
    asm volatile("cp.async.cg.shared.global [%0], [%1], 16;"
                 :: "r"(saddr), "l"(g));
}
#define CP_COMMIT() asm volatile("cp.async.commit_group;")
#define CP_WAIT0()  asm volatile("cp.async.wait_group 0;")
#define CP_WAIT1()  asm volatile("cp.async.wait_group 1;")

__device__ __forceinline__ void ldmx4(uint32_t* r, uint32_t addr) {
    asm volatile("ldmatrix.sync.aligned.m8n8.x4.shared.b16 {%0,%1,%2,%3}, [%4];"
                 : "=r"(r[0]), "=r"(r[1]), "=r"(r[2]), "=r"(r[3]) : "r"(addr));
}
__device__ __forceinline__ void ldmx4t(uint32_t* r, uint32_t addr) {
    asm volatile("ldmatrix.sync.aligned.m8n8.x4.trans.shared.b16 {%0,%1,%2,%3}, [%4];"
                 : "=r"(r[0]), "=r"(r[1]), "=r"(r[2]), "=r"(r[3]) : "r"(addr));
}

// fp16 MMA, fp32 accumulate
__device__ __forceinline__ void mma_f16(float* d, const uint32_t* a,
                                        uint32_t b0, uint32_t b1) {
    asm volatile(
        "mma.sync.aligned.m16n8k16.row.col.f32.f16.f16.f32 "
        "{%0,%1,%2,%3}, {%4,%5,%6,%7}, {%8,%9}, {%0,%1,%2,%3};"
        : "+f"(d[0]), "+f"(d[1]), "+f"(d[2]), "+f"(d[3])
        : "r"(a[0]), "r"(a[1]), "r"(a[2]), "r"(a[3]), "r"(b0), "r"(b1));
}

__device__ __forceinline__ uint32_t pkh2(float lo, float hi) {
    __half2 t = __floats2half2_rn(lo, hi);
    return *(uint32_t*)&t;
}
__device__ __forceinline__ float ex2f(float x) {
    float r; asm("ex2.approx.f32 %0, %1;" : "=f"(r) : "f"(x)); return r;
}

// 128B-row swizzled tile offset: [rows][64 half] rows of 8 16B chunks
__device__ __forceinline__ uint32_t qkoff(int row, int c) {
    return (uint32_t)(row * 128 + ((c ^ (row & 7)) * 16));
}

// =====================================================================
// GEMM: 128x128 CTA tile, 64x64 warp tile (4 warps), BK=64, 3-stage
// =====================================================================
#define TILE_B64 16384                     // 128 rows x 64 half (128B rows)
#define STAGE_B64 (2 * TILE_B64)           // A + B = 32 KB
#define GEMM_SMEM (3 * STAGE_B64)          // 98304

__device__ __forceinline__ void load_stage64(
    const __half* A, const __half* Bm,
    int m0, int n0, int k0, uint32_t sbase, int tid)
{
#pragma unroll
    for (int i = 0; i < 8; i++) {
        int q = tid + i * 128;             // 1024 chunks per tile
        int row = q >> 3;
        int c = q & 7;
        uint32_t so = qkoff(row, c);
        cp16(sbase + so, A + (size_t)(m0 + row) * KDIM + k0 + c * 8);
        cp16(sbase + TILE_B64 + so, Bm + (size_t)(n0 + row) * KDIM + k0 + c * 8);
    }
}

__device__ __forceinline__ void compute_stage64(uint32_t sbase, int lane,
                                                int m_warp, int n_warp,
                                                float acc[4][8][4])
{
    const uint32_t aBase = sbase;
    const uint32_t bBase = sbase + TILE_B64;

    const int a_r  = lane & 15;
    const int a_kh = (lane >> 4) & 1;
    const int b_r  = (lane & 7) + ((lane >> 4) & 1) * 8;
    const int b_kh = (lane >> 3) & 1;

#pragma unroll
    for (int s = 0; s < 4; s++) {          // four k16 steps
        uint32_t bh[16];
#pragma unroll
        for (int p = 0; p < 4; p++) {
            int rn = n_warp + p * 16 + b_r;
            ldmx4(&bh[p * 4], bBase + qkoff(rn, s * 2 + b_kh));
        }
#pragma unroll
        for (int mt = 0; mt < 4; mt++) {
            int rm = m_warp + mt * 16 + a_r;
            uint32_t ah[4];
            ldmx4(ah, aBase + qkoff(rm, s * 2 + a_kh));
#pragma unroll
            for (int nt = 0; nt < 8; nt++)
                mma_f16(acc[mt][nt], ah, bh[nt * 2], bh[nt * 2 + 1]);
        }
    }
}

__device__ __forceinline__ void gemm_mainloop_mma(
    const __half* A, const __half* Bm,
    int m0, int n0, uint32_t smem_u, int tid,
    int m_warp, int n_warp, float acc[4][8][4])
{
    const int lane = tid & 31;
    const int NIT = KDIM / 64;             // 12

    load_stage64(A, Bm, m0, n0, 0, smem_u, tid);
    CP_COMMIT();
    load_stage64(A, Bm, m0, n0, 64, smem_u + STAGE_B64, tid);
    CP_COMMIT();

#pragma unroll 1
    for (int it = 0; it < NIT; it++) {
        CP_WAIT1();                        // stage `it` resident
        __syncthreads();                   // all threads done with stage it-1
        if (it + 2 < NIT)
            load_stage64(A, Bm, m0, n0, (it + 2) * 64,
                         smem_u + ((it + 2) % 3) * STAGE_B64, tid);
        CP_COMMIT();                       // always commit (empty at tail)
        compute_stage64(smem_u + (it % 3) * STAGE_B64, lane, m_warp, n_warp, acc);
    }
}

// ---- QKV: X @ WaT^T -> scatter fp16 Q/K/V (+bias, Q*0.125*log2e) ----------
__global__ void __launch_bounds__(128, 2)
gemm_qkv_mma(const float* __restrict__ bias)
{
    extern __shared__ char smem[];
    uint32_t smem_u = smem_to_u32(smem);
    const int tid = threadIdx.x;
    const int wid = tid >> 5, lane = tid & 31;
    const int m_warp = (wid >> 1) * 64, n_warp = (wid & 1) * 64;
    const int n0 = blockIdx.x * 128, m0 = blockIdx.y * 128;

    float acc[4][8][4];
#pragma unroll
    for (int i = 0; i < 4; i++)
#pragma unroll
        for (int j = 0; j < 8; j++)
#pragma unroll
            for (int k = 0; k < 4; k++) acc[i][j][k] = 0.f;

    gemm_mainloop_mma(g_X16, g_WaT, m0, n0, smem_u, tid, m_warp, n_warp, acc);

    const int gg = lane >> 2, tig = lane & 3;
#pragma unroll
    for (int mt = 0; mt < 4; mt++) {
#pragma unroll
        for (int nt = 0; nt < 8; nt++) {
            int col = n0 + n_warp + nt * 8 + tig * 2;
            int which = col / C_;
            int c = col - which * C_;
            int h = c >> 6, d = c & 63;
            float bx = bias[col], by = bias[col + 1];
            __half* dst = (which == 0) ? g_Qh : (which == 1) ? g_Kh : g_Vh;
            // fold 1/sqrt(64) * log2(e) into Q for base-2 softmax
            float scl = (which == 0) ? 0.18033688011112042f : 1.0f;
#pragma unroll
            for (int rr = 0; rr < 2; rr++) {
                int m = m0 + m_warp + mt * 16 + gg + rr * 8;
                int b = m >> 10, t = m & 1023;
                float vx = (acc[mt][nt][rr * 2 + 0] + bx) * scl;
                float vy = (acc[mt][nt][rr * 2 + 1] + by) * scl;
                *(uint32_t*)(dst + ((size_t)(b * H_ + h) * T_ + t) * HD_ + d) =
                    pkh2(vx, vy);
            }
        }
    }
}

// ---- Proj: ATT @ WpT^T + b_proj -> out ------------------------------------
__global__ void __launch_bounds__(128, 2)
gemm_proj_mma(const float* __restrict__ bias, float* __restrict__ out)
{
    extern __shared__ char smem[];
    uint32_t smem_u = smem_to_u32(smem);
    const int tid = threadIdx.x;
    const int wid = tid >> 5, lane = tid & 31;
    const int m_warp = (wid >> 1) * 64, n_warp = (wid & 1) * 64;
    const int n0 = blockIdx.x * 128, m0 = blockIdx.y * 128;

    float acc[4][8][4];
#pragma unroll
    for (int i = 0; i < 4; i++)
#pragma unroll
        for (int j = 0; j < 8; j++)
#pragma unroll
            for (int k = 0; k < 4; k++) acc[i][j][k] = 0.f;

    gemm_mainloop_mma(g_ATT, g_WpT, m0, n0, smem_u, tid, m_warp, n_warp, acc);

    const int gg = lane >> 2, tig = lane & 3;
#pragma unroll
    for (int mt = 0; mt < 4; mt++) {
#pragma unroll
        for (int nt = 0; nt < 8; nt++) {
            int col = n0 + n_warp + nt * 8 + tig * 2;
            float bx = bias[col], by = bias[col + 1];
#pragma unroll
            for (int rr = 0; rr < 2; rr++) {
                int m = m0 + m_warp + mt * 16 + gg + rr * 8;
                float2 v;
                v.x = acc[mt][nt][rr * 2 + 0] + bx;
                v.y = acc[mt][nt][rr * 2 + 1] + by;
                *(float2*)(out + (size_t)m * C_ + col) = v;
            }
        }
    }
}

// =====================================================================
// preprocessing: fp32 -> fp16 (+ transposes for weights)
// =====================================================================
__global__ void to_half_kernel(const float* __restrict__ X,
                               __half* __restrict__ Y, int n4)
{
    int idx = blockIdx.x * blockDim.x + threadIdx.x;
    if (idx >= n4) return;
    float4 v = ((const float4*)X)[idx];
    __half2* py = (__half2*)(Y + 4 * (size_t)idx);
    py[0] = __floats2half2_rn(v.x, v.y);
    py[1] = __floats2half2_rn(v.z, v.w);
}

__global__ void transpose_half_kernel(const float* __restrict__ W,
                                      __half* __restrict__ Th, int K, int N)
{
    __shared__ float tile[32][33];
    const int nb = blockIdx.x * 32, kb = blockIdx.y * 32;
    const int tx = threadIdx.x, ty = threadIdx.y;  // 32 x 8
#pragma unroll
    for (int i = 0; i < 32; i += 8)
        tile[ty + i][tx] = W[(size_t)(kb + ty + i) * N + nb + tx];
    __syncthreads();
#pragma unroll
    for (int i = 0; i < 32; i += 8) {
        int n = nb + ty + i, k = kb + tx;
        Th[(size_t)n * K + k] = __float2half_rn(tile[tx][ty + i]);
    }
}

// =====================================================================
// meanV (reads fp16 V, fp32 accumulate)
// =====================================================================
__global__ void meanv_kernel()
{
    __shared__ float red[256];
    const int bh = blockIdx.x;
    const int tid = threadIdx.x;
    const int d = tid & 63;
    const int part = tid >> 6;
    const size_t base = (size_t)bh * T_ * HD_;
    float s = 0.f;
    const int t0 = part * 256;
    for (int t = t0; t < t0 + 256; t++)
        s += __half2float(g_Vh[base + (size_t)t * HD_ + d]);
    red[tid] = s;
    __syncthreads();
    if (part == 0)
        g_meanV[bh * HD_ + d] =
            (red[d] + red[d + 64] + red[d + 128] + red[d + 192]) * (1.0f / 1024.0f);
}

// =====================================================================
// Tensor-core flash attention: QT=128, 8 warps, fp16, async K/V
// smem: Q 16KB | stage0 {K,V} 16KB | stage1 {K,V} 16KB = 48KB
// =====================================================================
#define ATTN_SMEM 49152

__device__ __forceinline__ void attn_load_kv(const __half* gk, const __half* gv,
                                             uint32_t uK, uint32_t uV, int tid)
{
#pragma unroll
    for (int i = 0; i < 2; i++) {
        int q = tid + i * 256;        // 512 chunks per 8KB tile
        int row = q >> 3, c = q & 7;
        uint32_t off = qkoff(row, c);
        cp16(uK + off, gk + (size_t)row * 64 + c * 8);
        cp16(uV + off, gv + (size_t)row * 64 + c * 8);
    }
}

__global__ void __launch_bounds__(256, 2)
attn_mma_kernel(const int* __restrict__ mask)
{
    extern __shared__ char smem[];
    const uint32_t su = smem_to_u32(smem);
    const uint32_t uQ = su;
    // stage s: K at 16384 + s*16384, V at 24576 + s*16384

    const int tid = threadIdx.x;
    const int w = tid >> 5, lane = tid & 31;
    const int g = lane >> 2, tig = lane & 3;
    const int qq = (int)gridDim.x - 1 - blockIdx.x;   // heavy tiles first
    const int bh = blockIdx.y;
    const int b = bh / H_, h = bh - b * H_;
    const int q0 = qq * 128;
    const int NK = 2 * qq + 2;

    const __half* gq = g_Qh + ((size_t)bh * T_ + q0) * HD_;
    const __half* gk_bh = g_Kh + (size_t)bh * T_ * HD_;
    const __half* gv_bh = g_Vh + (size_t)bh * T_ * HD_;

    // ---- Q tile (128 rows) + first K/V stage via cp.async ----
#pragma unroll
    for (int i = 0; i < 4; i++) {
        int q = tid + i * 256;
        int row = q >> 3, c = q & 7;
        cp16(uQ + qkoff(row, c), gq + (size_t)row * 64 + c * 8);
    }
    attn_load_kv(gk_bh, gv_bh, su + 16384, su + 24576, tid);
    CP_COMMIT();

    float o[8][4];
#pragma unroll
    for (int i = 0; i < 8; i++)
#pragma unroll
        for (int j = 0; j < 4; j++) o[i][j] = 0.f;
    float m0 = -1e30f, m1 = -1e30f, l0 = 0.f, l1 = 0.f;

    const int a_row = w * 16 + (lane & 15);     // Q row 0..127
    const int a_kh = (lane >> 4) & 1;
    const int b_r = (lane & 7) + ((lane >> 4) & 1) * 8;
    const int b_kh = (lane >> 3) & 1;
    // V trans-fragment lane addressing (t-row / d-chunk)
    const int vt_r = (lane & 7) + ((lane >> 3) & 1) * 8;
    const int vd_c = (lane >> 4) & 1;

#pragma unroll 1
    for (int kt = 0; kt < NK; kt++) {
        CP_WAIT0();
        __syncthreads();   // stage kt ready; all threads done with stage kt-1
        if (kt + 1 < NK) {
            attn_load_kv(gk_bh + (size_t)(kt + 1) * 64 * HD_,
                         gv_bh + (size_t)(kt + 1) * 64 * HD_,
                         su + 16384 + ((kt + 1) & 1) * 16384,
                         su + 24576 + ((kt + 1) & 1) * 16384, tid);
            CP_COMMIT();
        }
        const uint32_t uK = su + 16384 + (kt & 1) * 16384;
        const uint32_t uV = su + 24576 + (kt & 1) * 16384;

        // ---- S = Q K^T (m16 x n64, k=64) ----
        float s[8][4];
#pragma unroll
        for (int i = 0; i < 8; i++)
#pragma unroll
            for (int j = 0; j < 4; j++) s[i][j] = 0.f;

#pragma unroll
        for (int ks = 0; ks < 4; ks++) {
            uint32_t ah[4];
            ldmx4(ah, uQ + qkoff(a_row, ks * 2 + a_kh));
#pragma unroll
            for (int np = 0; np < 4; np++) {
                uint32_t kb[4];
                ldmx4(kb, uK + qkoff(np * 16 + b_r, ks * 2 + b_kh));
                mma_f16(s[np * 2], ah, kb[0], kb[1]);
                mma_f16(s[np * 2 + 1], ah, kb[2], kb[3]);
            }
        }

        // causal mask when this k-tile crosses the warp's diagonal
        if (kt * 64 + 63 > q0 + w * 16) {
            const int r0 = q0 + w * 16 + g, r1 = r0 + 8;
            const int cb = kt * 64 + tig * 2;
#pragma unroll
            for (int nt = 0; nt < 8; nt++) {
                int c = cb + nt * 8;
                if (c > r0)     s[nt][0] = -1e30f;
                if (c + 1 > r0) s[nt][1] = -1e30f;
                if (c > r1)     s[nt][2] = -1e30f;
                if (c + 1 > r1) s[nt][3] = -1e30f;
            }
        }

        // ---- online softmax (base-2; log2e folded into Q) ----
        float mx0 = -1e30f, mx1 = -1e30f;
#pragma unroll
        for (int nt = 0; nt < 8; nt++) {
            mx0 = fmaxf(mx0, fmaxf(s[nt][0], s[nt][1]));
            mx1 = fmaxf(mx1, fmaxf(s[nt][2], s[nt][3]));
        }
        mx0 = fmaxf(mx0, __shfl_xor_sync(0xffffffffu, mx0, 1));
        mx0 = fmaxf(mx0, __shfl_xor_sync(0xffffffffu, mx0, 2));
        mx1 = fmaxf(mx1, __shfl_xor_sync(0xffffffffu, mx1, 1));
        mx1 = fmaxf(mx1, __shfl_xor_sync(0xffffffffu, mx1, 2));
        float mn0 = fmaxf(m0, mx0), mn1 = fmaxf(m1, mx1);
        float cr0 = ex2f(m0 - mn0), cr1 = ex2f(m1 - mn1);
        m0 = mn0; m1 = mn1;

        float sum0 = 0.f, sum1 = 0.f;
#pragma unroll
        for (int nt = 0; nt < 8; nt++) {
            s[nt][0] = ex2f(s[nt][0] - mn0);
            s[nt][1] = ex2f(s[nt][1] - mn0);
            s[nt][2] = ex2f(s[nt][2] - mn1);
            s[nt][3] = ex2f(s[nt][3] - mn1);
            sum0 += s[nt][0] + s[nt][1];
            sum1 += s[nt][2] + s[nt][3];
        }
        sum0 += __shfl_xor_sync(0xffffffffu, sum0, 1);
        sum0 += __shfl_xor_sync(0xffffffffu, sum0, 2);
        sum1 += __shfl_xor_sync(0xffffffffu, sum1, 1);
        sum1 += __shfl_xor_sync(0xffffffffu, sum1, 2);
        l0 = l0 * cr0 + sum0;
        l1 = l1 * cr1 + sum1;

#pragma unroll
        for (int nt = 0; nt < 8; nt++) {
            o[nt][0] *= cr0; o[nt][1] *= cr0;
            o[nt][2] *= cr1; o[nt][3] *= cr1;
        }

        // ---- O += P V  (V B-frags via ldmatrix.trans on [t][d] tile) ----
#pragma unroll
        for (int kc = 0; kc < 4; kc++) {
            const float* sa = s[2 * kc];
            const float* sb = s[2 * kc + 1];
            uint32_t pah[4];
            pah[0] = pkh2(sa[0], sa[1]);
            pah[1] = pkh2(sa[2], sa[3]);
            pah[2] = pkh2(sb[0], sb[1]);
            pah[3] = pkh2(sb[2], sb[3]);
#pragma unroll
            for (int np = 0; np < 4; np++) {
                uint32_t vb[4];
                ldmx4t(vb, uV + qkoff(kc * 16 + vt_r, np * 2 + vd_c));
                mma_f16(o[np * 2], pah, vb[0], vb[1]);
                mma_f16(o[np * 2 + 1], pah, vb[2], vb[3]);
            }
        }
    }

    // ---- epilogue: normalize, masked-row override, fp16 store ----
    const float il0 = 1.f / l0, il1 = 1.f / l1;
    const int r0g = q0 + w * 16 + g, r1g = r0g + 8;
    const bool mk0 = (mask[b * T_ + r0g] == 0);
    const bool mk1 = (mask[b * T_ + r1g] == 0);
    const size_t ob0 = ((size_t)b * T_ + r0g) * C_ + h * 64;
    const size_t ob1 = ((size_t)b * T_ + r1g) * C_ + h * 64;
#pragma unroll
    for (int nt = 0; nt < 8; nt++) {
        int d = nt * 8 + tig * 2;
        float y0 = o[nt][0] * il0, y1 = o[nt][1] * il0;
        if (mk0) { y0 = g_meanV[bh * 64 + d]; y1 = g_meanV[bh * 64 + d + 1]; }
        *(uint32_t*)(g_ATT + ob0 + d) = pkh2(y0, y1);
        float z0 = o[nt][2] * il1, z1 = o[nt][3] * il1;
        if (mk1) { z0 = g_meanV[bh * 64 + d]; z1 = g_meanV[bh * 64 + d + 1]; }
        *(uint32_t*)(g_ATT + ob1 + d) = pkh2(z0, z1);
    }
}

// =====================================================================
// launcher
// =====================================================================
extern "C" void kernel_launch(void* const* d_in, const int* in_sizes, int n_in,
                              void* d_out, int out_size)
{
    const float* x      = (const float*)d_in[0];
    const int*   mask   = (const int*)d_in[1];
    const float* W_attn = (const float*)d_in[2];
    const float* b_attn = (const float*)d_in[3];
    const float* W_proj = (const float*)d_in[4];
    const float* b_proj = (const float*)d_in[5];
    float* out = (float*)d_out;

    __half *p_X16, *p_WaT, *p_WpT;
    cudaGetSymbolAddress((void**)&p_X16, g_X16);
    cudaGetSymbolAddress((void**)&p_WaT, g_WaT);
    cudaGetSymbolAddress((void**)&p_WpT, g_WpT);

    // 0) fp32 -> fp16 preprocessing
    to_half_kernel<<<(M_ * C_ / 4 + 255) / 256, 256>>>(x, p_X16, M_ * C_ / 4);
    transpose_half_kernel<<<dim3(N3C / 32, C_ / 32), dim3(32, 8)>>>(
        W_attn, p_WaT, C_, N3C);
    transpose_half_kernel<<<dim3(C_ / 32, C_ / 32), dim3(32, 8)>>>(
        W_proj, p_WpT, C_, C_);

    // 1) QKV projection via mma.sync fp16 (64x64 warp tiles, 3-stage)
    {
        cudaFuncSetAttribute(gemm_qkv_mma,
                             cudaFuncAttributeMaxDynamicSharedMemorySize, GEMM_SMEM);
        dim3 grid(N3C / 128, M_ / 128);
        gemm_qkv_mma<<<grid, 128, GEMM_SMEM>>>(b_attn);
    }
    // 2) per-(b,h) mean of V
    meanv_kernel<<<B_ * H_, 256>>>();
    // 3) causal flash attention on tensor cores (QT=128, fp16, async K/V)
    {
        cudaFuncSetAttribute(attn_mma_kernel,
                             cudaFuncAttributeMaxDynamicSharedMemorySize, ATTN_SMEM);
        dim3 grid(T_ / 128, B_ * H_);
        attn_mma_kernel<<<grid, 256, ATTN_SMEM>>>(mask);
    }
    // 4) output projection via mma.sync fp16 (64x64 warp tiles, 3-stage)
    {
        cudaFuncSetAttribute(gemm_proj_mma,
                             cudaFuncAttributeMaxDynamicSharedMemorySize, GEMM_SMEM);
        dim3 grid(C_ / 128, M_ / 128);
        gemm_proj_mma<<<grid, 128, GEMM_SMEM>>>(b_proj, out);
    }
}

// round 16
// speedup vs baseline: 6.8101x; 1.0101x over previous
#include <cuda_runtime.h>
#include <cuda_fp16.h>
#include <cstdint>
#include <math.h>

// Problem constants
#define B_   8
#define T_   1024
#define C_   768
#define H_   12
#define HD_  64
#define M_   (B_ * T_)      // 8192
#define N3C  (3 * C_)       // 2304
#define KDIM 768

// ---------------- scratch (device globals; no allocations allowed) ----------
__device__ __half g_Qh[B_ * H_ * T_ * HD_];   // [B,H,T,HD], scaled 0.125*log2e
__device__ __half g_Kh[B_ * H_ * T_ * HD_];
__device__ __half g_Vh[B_ * H_ * T_ * HD_];
__device__ float  g_meanV[B_ * H_ * HD_];

__device__ __half g_X16[M_ * C_];             // x        [8192,768]
__device__ __half g_WaT[N3C * C_];            // W_attn^T [2304,768] (k-contig)
__device__ __half g_WpT[C_ * C_];             // W_proj^T [768,768]
__device__ __half g_ATT[M_ * C_];             // attention out [8192,768]

// =====================================================================
// family-common PTX helpers (NO tcgen05 — ptx target is sm_103 base)
// =====================================================================
__device__ __forceinline__ uint32_t smem_to_u32(const void* p) {
    uint32_t a;
    asm("{ .reg .u64 t; cvta.to.shared.u64 t, %1; cvt.u32.u64 %0, t; }"
        : "=r"(a) : "l"(p));
    return a;
}

__device__ __forceinline__ void cp16(uint32_t saddr, const void* g) {
    asm volatile("cp.async.cg.shared.global [%0], [%1], 16;"
                 :: "r"(saddr), "l"(g));
}
#define CP_COMMIT() asm volatile("cp.async.commit_group;")
#define CP_WAIT0()  asm volatile("cp.async.wait_group 0;")
#define CP_WAIT1()  asm volatile("cp.async.wait_group 1;")

__device__ __forceinline__ void ldmx4(uint32_t* r, uint32_t addr) {
    asm volatile("ldmatrix.sync.aligned.m8n8.x4.shared.b16 {%0,%1,%2,%3}, [%4];"
                 : "=r"(r[0]), "=r"(r[1]), "=r"(r[2]), "=r"(r[3]) : "r"(addr));
}
__device__ __forceinline__ void ldmx4t(uint32_t* r, uint32_t addr) {
    asm volatile("ldmatrix.sync.aligned.m8n8.x4.trans.shared.b16 {%0,%1,%2,%3}, [%4];"
                 : "=r"(r[0]), "=r"(r[1]), "=r"(r[2]), "=r"(r[3]) : "r"(addr));
}

// fp16 MMA, fp32 accumulate
__device__ __forceinline__ void mma_f16(float* d, const uint32_t* a,
                                        uint32_t b0, uint32_t b1) {
    asm volatile(
        "mma.sync.aligned.m16n8k16.row.col.f32.f16.f16.f32 "
        "{%0,%1,%2,%3}, {%4,%5,%6,%7}, {%8,%9}, {%0,%1,%2,%3};"
        : "+f"(d[0]), "+f"(d[1]), "+f"(d[2]), "+f"(d[3])
        : "r"(a[0]), "r"(a[1]), "r"(a[2]), "r"(a[3]), "r"(b0), "r"(b1));
}

__device__ __forceinline__ uint32_t pkh2(float lo, float hi) {
    __half2 t = __floats2half2_rn(lo, hi);
    return *(uint32_t*)&t;
}
__device__ __forceinline__ float ex2f(float x) {
    float r; asm("ex2.approx.f32 %0, %1;" : "=f"(r) : "f"(x)); return r;
}

// 128B-row swizzled tile offset: [rows][64 half] rows of 8 16B chunks
__device__ __forceinline__ uint32_t qkoff(int row, int c) {
    return (uint32_t)(row * 128 + ((c ^ (row & 7)) * 16));
}

// =====================================================================
// GEMM: 128x128 CTA tile, 64x64 warp tile (4 warps), BK=64, 3-stage
// (unchanged from R15 — at the mma.sync ceiling)
// =====================================================================
#define TILE_B64 16384                     // 128 rows x 64 half (128B rows)
#define STAGE_B64 (2 * TILE_B64)           // A + B = 32 KB
#define GEMM_SMEM (3 * STAGE_B64)          // 98304

__device__ __forceinline__ void load_stage64(
    const __half* A, const __half* Bm,
    int m0, int n0, int k0, uint32_t sbase, int tid)
{
#pragma unroll
    for (int i = 0; i < 8; i++) {
        int q = tid + i * 128;             // 1024 chunks per tile
        int row = q >> 3;
        int c = q & 7;
        uint32_t so = qkoff(row, c);
        cp16(sbase + so, A + (size_t)(m0 + row) * KDIM + k0 + c * 8);
        cp16(sbase + TILE_B64 + so, Bm + (size_t)(n0 + row) * KDIM + k0 + c * 8);
    }
}

__device__ __forceinline__ void compute_stage64(uint32_t sbase, int lane,
                                                int m_warp, int n_warp,
                                                float acc[4][8][4])
{
    const uint32_t aBase = sbase;
    const uint32_t bBase = sbase + TILE_B64;

    const int a_r  = lane & 15;
    const int a_kh = (lane >> 4) & 1;
    const int b_r  = (lane & 7) + ((lane >> 4) & 1) * 8;
    const int b_kh = (lane >> 3) & 1;

#pragma unroll
    for (int s = 0; s < 4; s++) {          // four k16 steps
        uint32_t bh[16];
#pragma unroll
        for (int p = 0; p < 4; p++) {
            int rn = n_warp + p * 16 + b_r;
            ldmx4(&bh[p * 4], bBase + qkoff(rn, s * 2 + b_kh));
        }
#pragma unroll
        for (int mt = 0; mt < 4; mt++) {
            int rm = m_warp + mt * 16 + a_r;
            uint32_t ah[4];
            ldmx4(ah, aBase + qkoff(rm, s * 2 + a_kh));
#pragma unroll
            for (int nt = 0; nt < 8; nt++)
                mma_f16(acc[mt][nt], ah, bh[nt * 2], bh[nt * 2 + 1]);
        }
    }
}

__device__ __forceinline__ void gemm_mainloop_mma(
    const __half* A, const __half* Bm,
    int m0, int n0, uint32_t smem_u, int tid,
    int m_warp, int n_warp, float acc[4][8][4])
{
    const int lane = tid & 31;
    const int NIT = KDIM / 64;             // 12

    load_stage64(A, Bm, m0, n0, 0, smem_u, tid);
    CP_COMMIT();
    load_stage64(A, Bm, m0, n0, 64, smem_u + STAGE_B64, tid);
    CP_COMMIT();

#pragma unroll 1
    for (int it = 0; it < NIT; it++) {
        CP_WAIT1();                        // stage `it` resident
        __syncthreads();                   // all threads done with stage it-1
        if (it + 2 < NIT)
            load_stage64(A, Bm, m0, n0, (it + 2) * 64,
                         smem_u + ((it + 2) % 3) * STAGE_B64, tid);
        CP_COMMIT();                       // always commit (empty at tail)
        compute_stage64(smem_u + (it % 3) * STAGE_B64, lane, m_warp, n_warp, acc);
    }
}

// ---- QKV: X @ WaT^T -> scatter fp16 Q/K/V (+bias, Q*0.125*log2e) ----------
__global__ void __launch_bounds__(128, 2)
gemm_qkv_mma(const float* __restrict__ bias)
{
    extern __shared__ char smem[];
    uint32_t smem_u = smem_to_u32(smem);
    const int tid = threadIdx.x;
    const int wid = tid >> 5, lane = tid & 31;
    const int m_warp = (wid >> 1) * 64, n_warp = (wid & 1) * 64;
    const int n0 = blockIdx.x * 128, m0 = blockIdx.y * 128;

    float acc[4][8][4];
#pragma unroll
    for (int i = 0; i < 4; i++)
#pragma unroll
        for (int j = 0; j < 8; j++)
#pragma unroll
            for (int k = 0; k < 4; k++) acc[i][j][k] = 0.f;

    gemm_mainloop_mma(g_X16, g_WaT, m0, n0, smem_u, tid, m_warp, n_warp, acc);

    const int gg = lane >> 2, tig = lane & 3;
#pragma unroll
    for (int mt = 0; mt < 4; mt++) {
#pragma unroll
        for (int nt = 0; nt < 8; nt++) {
            int col = n0 + n_warp + nt * 8 + tig * 2;
            int which = col / C_;
            int c = col - which * C_;
            int h = c >> 6, d = c & 63;
            float bx = bias[col], by = bias[col + 1];
            __half* dst = (which == 0) ? g_Qh : (which == 1) ? g_Kh : g_Vh;
            // fold 1/sqrt(64) * log2(e) into Q for base-2 softmax
            float scl = (which == 0) ? 0.18033688011112042f : 1.0f;
#pragma unroll
            for (int rr = 0; rr < 2; rr++) {
                int m = m0 + m_warp + mt * 16 + gg + rr * 8;
                int b = m >> 10, t = m & 1023;
                float vx = (acc[mt][nt][rr * 2 + 0] + bx) * scl;
                float vy = (acc[mt][nt][rr * 2 + 1] + by) * scl;
                *(uint32_t*)(dst + ((size_t)(b * H_ + h) * T_ + t) * HD_ + d) =
                    pkh2(vx, vy);
            }
        }
    }
}

// ---- Proj: ATT @ WpT^T + b_proj -> out ------------------------------------
__global__ void __launch_bounds__(128, 2)
gemm_proj_mma(const float* __restrict__ bias, float* __restrict__ out)
{
    extern __shared__ char smem[];
    uint32_t smem_u = smem_to_u32(smem);
    const int tid = threadIdx.x;
    const int wid = tid >> 5, lane = tid & 31;
    const int m_warp = (wid >> 1) * 64, n_warp = (wid & 1) * 64;
    const int n0 = blockIdx.x * 128, m0 = blockIdx.y * 128;

    float acc[4][8][4];
#pragma unroll
    for (int i = 0; i < 4; i++)
#pragma unroll
        for (int j = 0; j < 8; j++)
#pragma unroll
            for (int k = 0; k < 4; k++) acc[i][j][k] = 0.f;

    gemm_mainloop_mma(g_ATT, g_WpT, m0, n0, smem_u, tid, m_warp, n_warp, acc);

    const int gg = lane >> 2, tig = lane & 3;
#pragma unroll
    for (int mt = 0; mt < 4; mt++) {
#pragma unroll
        for (int nt = 0; nt < 8; nt++) {
            int col = n0 + n_warp + nt * 8 + tig * 2;
            float bx = bias[col], by = bias[col + 1];
#pragma unroll
            for (int rr = 0; rr < 2; rr++) {
                int m = m0 + m_warp + mt * 16 + gg + rr * 8;
                float2 v;
                v.x = acc[mt][nt][rr * 2 + 0] + bx;
                v.y = acc[mt][nt][rr * 2 + 1] + by;
                *(float2*)(out + (size_t)m * C_ + col) = v;
            }
        }
    }
}

// =====================================================================
// preprocessing: fp32 -> fp16; both weight transposes fused in one launch
// =====================================================================
__global__ void to_half_kernel(const float* __restrict__ X,
                               __half* __restrict__ Y, int n4)
{
    int idx = blockIdx.x * blockDim.x + threadIdx.x;
    if (idx >= n4) return;
    float4 v = ((const float4*)X)[idx];
    __half2* py = (__half2*)(Y + 4 * (size_t)idx);
    py[0] = __floats2half2_rn(v.x, v.y);
    py[1] = __floats2half2_rn(v.z, v.w);
}

// z=0: W_attn [768,2304] -> g_WaT;  z=1: W_proj [768,768] -> g_WpT
__global__ void transpose_both_kernel(const float* __restrict__ Wa,
                                      const float* __restrict__ Wp,
                                      __half* __restrict__ Ta,
                                      __half* __restrict__ Tp)
{
    __shared__ float tile[32][33];
    const int z = blockIdx.z;
    const int N = z ? C_ : N3C;
    if (blockIdx.x * 32 >= N) return;
    const float* W = z ? Wp : Wa;
    __half* Th = z ? Tp : Ta;
    const int K = C_;
    const int nb = blockIdx.x * 32, kb = blockIdx.y * 32;
    const int tx = threadIdx.x, ty = threadIdx.y;  // 32 x 8
#pragma unroll
    for (int i = 0; i < 32; i += 8)
        tile[ty + i][tx] = W[(size_t)(kb + ty + i) * N + nb + tx];
    __syncthreads();
#pragma unroll
    for (int i = 0; i < 32; i += 8) {
        int n = nb + ty + i, k = kb + tx;
        Th[(size_t)n * K + k] = __float2half_rn(tile[tx][ty + i]);
    }
}

// =====================================================================
// meanV (reads fp16 V, fp32 accumulate)
// =====================================================================
__global__ void meanv_kernel()
{
    __shared__ float red[256];
    const int bh = blockIdx.x;
    const int tid = threadIdx.x;
    const int d = tid & 63;
    const int part = tid >> 6;
    const size_t base = (size_t)bh * T_ * HD_;
    float s = 0.f;
    const int t0 = part * 256;
    for (int t = t0; t < t0 + 256; t++)
        s += __half2float(g_Vh[base + (size_t)t * HD_ + d]);
    red[tid] = s;
    __syncthreads();
    if (part == 0)
        g_meanV[bh * HD_ + d] =
            (red[d] + red[d + 64] + red[d + 128] + red[d + 192]) * (1.0f / 1024.0f);
}

// =====================================================================
// Tensor-core flash attention: QT=128, 8 warps, fp16, 3-stage K/V,
// Q fragments hoisted to registers (loop-invariant)
// smem: Q 16KB | 3 stages x {K,V} 16KB = 64KB
// =====================================================================
#define ATTN_SMEM 65536

__device__ __forceinline__ void attn_load_kv(const __half* gk, const __half* gv,
                                             uint32_t uK, uint32_t uV, int tid)
{
#pragma unroll
    for (int i = 0; i < 2; i++) {
        int q = tid + i * 256;        // 512 chunks per 8KB tile
        int row = q >> 3, c = q & 7;
        uint32_t off = qkoff(row, c);
        cp16(uK + off, gk + (size_t)row * 64 + c * 8);
        cp16(uV + off, gv + (size_t)row * 64 + c * 8);
    }
}

__global__ void __launch_bounds__(256, 2)
attn_mma_kernel(const int* __restrict__ mask)
{
    extern __shared__ char smem[];
    const uint32_t su = smem_to_u32(smem);
    const uint32_t uQ = su;
    // stage s: K at 16384 + s*16384, V at 24576 + s*16384

    const int tid = threadIdx.x;
    const int w = tid >> 5, lane = tid & 31;
    const int g = lane >> 2, tig = lane & 3;
    const int qq = (int)gridDim.x - 1 - blockIdx.x;   // heavy tiles first
    const int bh = blockIdx.y;
    const int b = bh / H_, h = bh - b * H_;
    const int q0 = qq * 128;
    const int NK = 2 * qq + 2;

    const __half* gq = g_Qh + ((size_t)bh * T_ + q0) * HD_;
    const __half* gk_bh = g_Kh + (size_t)bh * T_ * HD_;
    const __half* gv_bh = g_Vh + (size_t)bh * T_ * HD_;

    // ---- prologue: Q tile + KV0 (group0), KV1 (group1) ----
#pragma unroll
    for (int i = 0; i < 4; i++) {
        int q = tid + i * 256;
        int row = q >> 3, c = q & 7;
        cp16(uQ + qkoff(row, c), gq + (size_t)row * 64 + c * 8);
    }
    attn_load_kv(gk_bh, gv_bh, su + 16384, su + 24576, tid);
    CP_COMMIT();
    attn_load_kv(gk_bh + 64 * HD_, gv_bh + 64 * HD_,
                 su + 16384 + 16384, su + 24576 + 16384, tid);
    CP_COMMIT();

    float o[8][4];
#pragma unroll
    for (int i = 0; i < 8; i++)
#pragma unroll
        for (int j = 0; j < 4; j++) o[i][j] = 0.f;
    float m0 = -1e30f, m1 = -1e30f, l0 = 0.f, l1 = 0.f;

    const int a_row = w * 16 + (lane & 15);     // Q row 0..127
    const int a_kh = (lane >> 4) & 1;
    const int b_r = (lane & 7) + ((lane >> 4) & 1) * 8;
    const int b_kh = (lane >> 3) & 1;
    // V trans-fragment lane addressing (t-row / d-chunk)
    const int vt_r = (lane & 7) + ((lane >> 3) & 1) * 8;
    const int vd_c = (lane >> 4) & 1;

    // ---- wait group0 (Q + KV0), hoist Q fragments to registers ----
    CP_WAIT1();
    __syncthreads();
    uint32_t qf[4][4];
#pragma unroll
    for (int ks = 0; ks < 4; ks++)
        ldmx4(qf[ks], uQ + qkoff(a_row, ks * 2 + a_kh));

#pragma unroll 1
    for (int kt = 0; kt < NK; kt++) {
        if (kt > 0) {
            CP_WAIT1();        // stage kt resident
            __syncthreads();   // all threads done with stage kt-1
        }
        if (kt + 2 < NK)
            attn_load_kv(gk_bh + (size_t)(kt + 2) * 64 * HD_,
                         gv_bh + (size_t)(kt + 2) * 64 * HD_,
                         su + 16384 + ((kt + 2) % 3) * 16384,
                         su + 24576 + ((kt + 2) % 3) * 16384, tid);
        CP_COMMIT();           // always commit (empty at tail)
        const uint32_t uK = su + 16384 + (kt % 3) * 16384;
        const uint32_t uV = su + 24576 + (kt % 3) * 16384;

        // ---- S = Q K^T (m16 x n64, k=64), Q frags in registers ----
        float s[8][4];
#pragma unroll
        for (int i = 0; i < 8; i++)
#pragma unroll
            for (int j = 0; j < 4; j++) s[i][j] = 0.f;

#pragma unroll
        for (int ks = 0; ks < 4; ks++) {
#pragma unroll
            for (int np = 0; np < 4; np++) {
                uint32_t kb[4];
                ldmx4(kb, uK + qkoff(np * 16 + b_r, ks * 2 + b_kh));
                mma_f16(s[np * 2], qf[ks], kb[0], kb[1]);
                mma_f16(s[np * 2 + 1], qf[ks], kb[2], kb[3]);
            }
        }

        // causal mask when this k-tile crosses the warp's diagonal
        if (kt * 64 + 63 > q0 + w * 16) {
            const int r0 = q0 + w * 16 + g, r1 = r0 + 8;
            const int cb = kt * 64 + tig * 2;
#pragma unroll
            for (int nt = 0; nt < 8; nt++) {
                int c = cb + nt * 8;
                if (c > r0)     s[nt][0] = -1e30f;
                if (c + 1 > r0) s[nt][1] = -1e30f;
                if (c > r1)     s[nt][2] = -1e30f;
                if (c + 1 > r1) s[nt][3] = -1e30f;
            }
        }

        // ---- online softmax (base-2; log2e folded into Q) ----
        float mx0 = -1e30f, mx1 = -1e30f;
#pragma unroll
        for (int nt = 0; nt < 8; nt++) {
            mx0 = fmaxf(mx0, fmaxf(s[nt][0], s[nt][1]));
            mx1 = fmaxf(mx1, fmaxf(s[nt][2], s[nt][3]));
        }
        mx0 = fmaxf(mx0, __shfl_xor_sync(0xffffffffu, mx0, 1));
        mx0 = fmaxf(mx0, __shfl_xor_sync(0xffffffffu, mx0, 2));
        mx1 = fmaxf(mx1, __shfl_xor_sync(0xffffffffu, mx1, 1));
        mx1 = fmaxf(mx1, __shfl_xor_sync(0xffffffffu, mx1, 2));
        float mn0 = fmaxf(m0, mx0), mn1 = fmaxf(m1, mx1);
        float cr0 = ex2f(m0 - mn0), cr1 = ex2f(m1 - mn1);
        m0 = mn0; m1 = mn1;

        float sum0 = 0.f, sum1 = 0.f;
#pragma unroll
        for (int nt = 0; nt < 8; nt++) {
            s[nt][0] = ex2f(s[nt][0] - mn0);
            s[nt][1] = ex2f(s[nt][1] - mn0);
            s[nt][2] = ex2f(s[nt][2] - mn1);
            s[nt][3] = ex2f(s[nt][3] - mn1);
            sum0 += s[nt][0] + s[nt][1];
            sum1 += s[nt][2] + s[nt][3];
        }
        sum0 += __shfl_xor_sync(0xffffffffu, sum0, 1);
        sum0 += __shfl_xor_sync(0xffffffffu, sum0, 2);
        sum1 += __shfl_xor_sync(0xffffffffu, sum1, 1);
        sum1 += __shfl_xor_sync(0xffffffffu, sum1, 2);
        l0 = l0 * cr0 + sum0;
        l1 = l1 * cr1 + sum1;

#pragma unroll
        for (int nt = 0; nt < 8; nt++) {
            o[nt][0] *= cr0; o[nt][1] *= cr0;
            o[nt][2] *= cr1; o[nt][3] *= cr1;
        }

        // ---- O += P V  (V B-frags via ldmatrix.trans on [t][d] tile) ----
#pragma unroll
        for (int kc = 0; kc < 4; kc++) {
            const float* sa = s[2 * kc];
            const float* sb = s[2 * kc + 1];
            uint32_t pah[4];
            pah[0] = pkh2(sa[0], sa[1]);
            pah[1] = pkh2(sa[2], sa[3]);
            pah[2] = pkh2(sb[0], sb[1]);
            pah[3] = pkh2(sb[2], sb[3]);
#pragma unroll
            for (int np = 0; np < 4; np++) {
                uint32_t vb[4];
                ldmx4t(vb, uV + qkoff(kc * 16 + vt_r, np * 2 + vd_c));
                mma_f16(o[np * 2], pah, vb[0], vb[1]);
                mma_f16(o[np * 2 + 1], pah, vb[2], vb[3]);
            }
        }
    }

    // ---- epilogue: normalize, masked-row override, fp16 store ----
    const float il0 = 1.f / l0, il1 = 1.f / l1;
    const int r0g = q0 + w * 16 + g, r1g = r0g + 8;
    const bool mk0 = (mask[b * T_ + r0g] == 0);
    const bool mk1 = (mask[b * T_ + r1g] == 0);
    const size_t ob0 = ((size_t)b * T_ + r0g) * C_ + h * 64;
    const size_t ob1 = ((size_t)b * T_ + r1g) * C_ + h * 64;
#pragma unroll
    for (int nt = 0; nt < 8; nt++) {
        int d = nt * 8 + tig * 2;
        float y0 = o[nt][0] * il0, y1 = o[nt][1] * il0;
        if (mk0) { y0 = g_meanV[bh * 64 + d]; y1 = g_meanV[bh * 64 + d + 1]; }
        *(uint32_t*)(g_ATT + ob0 + d) = pkh2(y0, y1);
        float z0 = o[nt][2] * il1, z1 = o[nt][3] * il1;
        if (mk1) { z0 = g_meanV[bh * 64 + d]; z1 = g_meanV[bh * 64 + d + 1]; }
        *(uint32_t*)(g_ATT + ob1 + d) = pkh2(z0, z1);
    }
}

// =====================================================================
// launcher
// =====================================================================
extern "C" void kernel_launch(void* const* d_in, const int* in_sizes, int n_in,
                              void* d_out, int out_size)
{
    const float* x      = (const float*)d_in[0];
    const int*   mask   = (const int*)d_in[1];
    const float* W_attn = (const float*)d_in[2];
    const float* b_attn = (const float*)d_in[3];
    const float* W_proj = (const float*)d_in[4];
    const float* b_proj = (const float*)d_in[5];
    float* out = (float*)d_out;

    __half *p_X16, *p_WaT, *p_WpT;
    cudaGetSymbolAddress((void**)&p_X16, g_X16);
    cudaGetSymbolAddress((void**)&p_WaT, g_WaT);
    cudaGetSymbolAddress((void**)&p_WpT, g_WpT);

    // 0) fp32 -> fp16 preprocessing (both transposes in one launch)
    to_half_kernel<<<(M_ * C_ / 4 + 255) / 256, 256>>>(x, p_X16, M_ * C_ / 4);
    transpose_both_kernel<<<dim3(N3C / 32, C_ / 32, 2), dim3(32, 8)>>>(
        W_attn, W_proj, p_WaT, p_WpT);

    // 1) QKV projection via mma.sync fp16 (64x64 warp tiles, 3-stage)
    {
        cudaFuncSetAttribute(gemm_qkv_mma,
                             cudaFuncAttributeMaxDynamicSharedMemorySize, GEMM_SMEM);
        dim3 grid(N3C / 128, M_ / 128);
        gemm_qkv_mma<<<grid, 128, GEMM_SMEM>>>(b_attn);
    }
    // 2) per-(b,h) mean of V
    meanv_kernel<<<B_ * H_, 256>>>();
    // 3) causal flash attention (QT=128, Q-frag hoisted, 3-stage K/V)
    {
        cudaFuncSetAttribute(attn_mma_kernel,
                             cudaFuncAttributeMaxDynamicSharedMemorySize, ATTN_SMEM);
        dim3 grid(T_ / 128, B_ * H_);
        attn_mma_kernel<<<grid, 256, ATTN_SMEM>>>(mask);
    }
    // 4) output projection via mma.sync fp16 (64x64 warp tiles, 3-stage)
    {
        cudaFuncSetAttribute(gemm_proj_mma,
                             cudaFuncAttributeMaxDynamicSharedMemorySize, GEMM_SMEM);
        dim3 grid(C_ / 128, M_ / 128);
        gemm_proj_mma<<<grid, 128, GEMM_SMEM>>>(b_proj, out);
    }
}

// round 17
// speedup vs baseline: 6.9029x; 1.0136x over previous
#include <cuda_runtime.h>
#include <cuda_fp16.h>
#include <cstdint>
#include <math.h>

// Problem constants
#define B_   8
#define T_   1024
#define C_   768
#define H_   12
#define HD_  64
#define M_   (B_ * T_)      // 8192
#define N3C  (3 * C_)       // 2304
#define KDIM 768

// ---------------- scratch (device globals; no allocations allowed) ----------
__device__ __half g_Qh[B_ * H_ * T_ * HD_];   // [B,H,T,HD], scaled 0.125*log2e
__device__ __half g_Kh[B_ * H_ * T_ * HD_];
__device__ __half g_Vh[B_ * H_ * T_ * HD_];
__device__ float  g_meanV[B_ * H_ * HD_];     // SUM of V over t (scaled later)

__device__ __half g_X16[M_ * C_];             // x        [8192,768]
__device__ __half g_WaT[N3C * C_];            // W_attn^T [2304,768] (k-contig)
__device__ __half g_WpT[C_ * C_];             // W_proj^T [768,768]
__device__ __half g_ATT[M_ * C_];             // attention out [8192,768]

// =====================================================================
// family-common PTX helpers (NO tcgen05 — ptx target is sm_103 base)
// =====================================================================
__device__ __forceinline__ uint32_t smem_to_u32(const void* p) {
    uint32_t a;
    asm("{ .reg .u64 t; cvta.to.shared.u64 t, %1; cvt.u32.u64 %0, t; }"
        : "=r"(a) : "l"(p));
    return a;
}

__device__ __forceinline__ void cp16(uint32_t saddr, const void* g) {
    asm volatile("cp.async.cg.shared.global [%0], [%1], 16;"
                 :: "r"(saddr), "l"(g));
}
#define CP_COMMIT() asm volatile("cp.async.commit_group;")
#define CP_WAIT0()  asm volatile("cp.async.wait_group 0;")
#define CP_WAIT1()  asm volatile("cp.async.wait_group 1;")

__device__ __forceinline__ void ldmx4(uint32_t* r, uint32_t addr) {
    asm volatile("ldmatrix.sync.aligned.m8n8.x4.shared.b16 {%0,%1,%2,%3}, [%4];"
                 : "=r"(r[0]), "=r"(r[1]), "=r"(r[2]), "=r"(r[3]) : "r"(addr));
}
__device__ __forceinline__ void ldmx4t(uint32_t* r, uint32_t addr) {
    asm volatile("ldmatrix.sync.aligned.m8n8.x4.trans.shared.b16 {%0,%1,%2,%3}, [%4];"
                 : "=r"(r[0]), "=r"(r[1]), "=r"(r[2]), "=r"(r[3]) : "r"(addr));
}

// fp16 MMA, fp32 accumulate
__device__ __forceinline__ void mma_f16(float* d, const uint32_t* a,
                                        uint32_t b0, uint32_t b1) {
    asm volatile(
        "mma.sync.aligned.m16n8k16.row.col.f32.f16.f16.f32 "
        "{%0,%1,%2,%3}, {%4,%5,%6,%7}, {%8,%9}, {%0,%1,%2,%3};"
        : "+f"(d[0]), "+f"(d[1]), "+f"(d[2]), "+f"(d[3])
        : "r"(a[0]), "r"(a[1]), "r"(a[2]), "r"(a[3]), "r"(b0), "r"(b1));
}

__device__ __forceinline__ uint32_t pkh2(float lo, float hi) {
    __half2 t = __floats2half2_rn(lo, hi);
    return *(uint32_t*)&t;
}
__device__ __forceinline__ float ex2f(float x) {
    float r; asm("ex2.approx.f32 %0, %1;" : "=f"(r) : "f"(x)); return r;
}

// 128B-row swizzled tile offset: [rows][64 half] rows of 8 16B chunks
__device__ __forceinline__ uint32_t qkoff(int row, int c) {
    return (uint32_t)(row * 128 + ((c ^ (row & 7)) * 16));
}

// =====================================================================
// GEMM: 128x128 CTA tile, 64x64 warp tile (4 warps), BK=64, 3-stage
// =====================================================================
#define TILE_B64 16384                     // 128 rows x 64 half (128B rows)
#define STAGE_B64 (2 * TILE_B64)           // A + B = 32 KB
#define GEMM_SMEM (3 * STAGE_B64)          // 98304

__device__ __forceinline__ void load_stage64(
    const __half* A, const __half* Bm,
    int m0, int n0, int k0, uint32_t sbase, int tid)
{
#pragma unroll
    for (int i = 0; i < 8; i++) {
        int q = tid + i * 128;             // 1024 chunks per tile
        int row = q >> 3;
        int c = q & 7;
        uint32_t so = qkoff(row, c);
        cp16(sbase + so, A + (size_t)(m0 + row) * KDIM + k0 + c * 8);
        cp16(sbase + TILE_B64 + so, Bm + (size_t)(n0 + row) * KDIM + k0 + c * 8);
    }
}

__device__ __forceinline__ void compute_stage64(uint32_t sbase, int lane,
                                                int m_warp, int n_warp,
                                                float acc[4][8][4])
{
    const uint32_t aBase = sbase;
    const uint32_t bBase = sbase + TILE_B64;

    const int a_r  = lane & 15;
    const int a_kh = (lane >> 4) & 1;
    const int b_r  = (lane & 7) + ((lane >> 4) & 1) * 8;
    const int b_kh = (lane >> 3) & 1;

#pragma unroll
    for (int s = 0; s < 4; s++) {          // four k16 steps
        uint32_t bh[16];
#pragma unroll
        for (int p = 0; p < 4; p++) {
            int rn = n_warp + p * 16 + b_r;
            ldmx4(&bh[p * 4], bBase + qkoff(rn, s * 2 + b_kh));
        }
#pragma unroll
        for (int mt = 0; mt < 4; mt++) {
            int rm = m_warp + mt * 16 + a_r;
            uint32_t ah[4];
            ldmx4(ah, aBase + qkoff(rm, s * 2 + a_kh));
#pragma unroll
            for (int nt = 0; nt < 8; nt++)
                mma_f16(acc[mt][nt], ah, bh[nt * 2], bh[nt * 2 + 1]);
        }
    }
}

__device__ __forceinline__ void gemm_mainloop_mma(
    const __half* A, const __half* Bm,
    int m0, int n0, uint32_t smem_u, int tid,
    int m_warp, int n_warp, float acc[4][8][4])
{
    const int lane = tid & 31;
    const int NIT = KDIM / 64;             // 12

    load_stage64(A, Bm, m0, n0, 0, smem_u, tid);
    CP_COMMIT();
    load_stage64(A, Bm, m0, n0, 64, smem_u + STAGE_B64, tid);
    CP_COMMIT();

#pragma unroll 1
    for (int it = 0; it < NIT; it++) {
        CP_WAIT1();                        // stage `it` resident
        __syncthreads();                   // all threads done with stage it-1
        if (it + 2 < NIT)
            load_stage64(A, Bm, m0, n0, (it + 2) * 64,
                         smem_u + ((it + 2) % 3) * STAGE_B64, tid);
        CP_COMMIT();                       // always commit (empty at tail)
        compute_stage64(smem_u + (it % 3) * STAGE_B64, lane, m_warp, n_warp, acc);
    }
}

// ---- QKV: X @ WaT^T -> scatter fp16 Q/K/V (+bias, Q*0.125*log2e) ----------
//      V blocks additionally reduce their column sums into g_meanV (atomics)
__global__ void __launch_bounds__(128, 2)
gemm_qkv_mma(const float* __restrict__ bias)
{
    extern __shared__ char smem[];
    uint32_t smem_u = smem_to_u32(smem);
    const int tid = threadIdx.x;
    const int wid = tid >> 5, lane = tid & 31;
    const int m_warp = (wid >> 1) * 64, n_warp = (wid & 1) * 64;
    const int n0 = blockIdx.x * 128, m0 = blockIdx.y * 128;

    float acc[4][8][4];
#pragma unroll
    for (int i = 0; i < 4; i++)
#pragma unroll
        for (int j = 0; j < 8; j++)
#pragma unroll
            for (int k = 0; k < 4; k++) acc[i][j][k] = 0.f;

    gemm_mainloop_mma(g_X16, g_WaT, m0, n0, smem_u, tid, m_warp, n_warp, acc);

    const int gg = lane >> 2, tig = lane & 3;
#pragma unroll
    for (int mt = 0; mt < 4; mt++) {
#pragma unroll
        for (int nt = 0; nt < 8; nt++) {
            int col = n0 + n_warp + nt * 8 + tig * 2;
            int which = col / C_;
            int c = col - which * C_;
            int h = c >> 6, d = c & 63;
            float bx = bias[col], by = bias[col + 1];
            __half* dst = (which == 0) ? g_Qh : (which == 1) ? g_Kh : g_Vh;
            // fold 1/sqrt(64) * log2(e) into Q for base-2 softmax
            float scl = (which == 0) ? 0.18033688011112042f : 1.0f;
#pragma unroll
            for (int rr = 0; rr < 2; rr++) {
                int m = m0 + m_warp + mt * 16 + gg + rr * 8;
                int b = m >> 10, t = m & 1023;
                float vx = (acc[mt][nt][rr * 2 + 0] + bx) * scl;
                float vy = (acc[mt][nt][rr * 2 + 1] + by) * scl;
                *(uint32_t*)(dst + ((size_t)(b * H_ + h) * T_ + t) * HD_ + d) =
                    pkh2(vx, vy);
            }
        }
    }

    // ---- fused meanV partial reduction (V blocks only; n0 uniform) ----
    if (n0 >= 2 * C_) {
        const int b = m0 >> 10;   // whole block inside one batch (128 | 1024)
#pragma unroll
        for (int nt = 0; nt < 8; nt++) {
#pragma unroll
            for (int j = 0; j < 2; j++) {
                float ssum = 0.f;
#pragma unroll
                for (int mt = 0; mt < 4; mt++)
#pragma unroll
                    for (int rr = 0; rr < 2; rr++)
                        ssum += acc[mt][nt][rr * 2 + j];
                int col = n0 + n_warp + nt * 8 + tig * 2 + j;
                ssum += 8.0f * bias[col];          // 8 rows per thread-column
                // reduce over gg lanes (same tig): lane bits 2..4
                ssum += __shfl_xor_sync(0xffffffffu, ssum, 4);
                ssum += __shfl_xor_sync(0xffffffffu, ssum, 8);
                ssum += __shfl_xor_sync(0xffffffffu, ssum, 16);
                if (gg == 0) {
                    int c = col - 2 * C_;
                    int h = c >> 6, d = c & 63;
                    atomicAdd(&g_meanV[(b * H_ + h) * HD_ + d], ssum);
                }
            }
        }
    }
}

// ---- Proj: ATT @ WpT^T + b_proj -> out ------------------------------------
__global__ void __launch_bounds__(128, 2)
gemm_proj_mma(const float* __restrict__ bias, float* __restrict__ out)
{
    extern __shared__ char smem[];
    uint32_t smem_u = smem_to_u32(smem);
    const int tid = threadIdx.x;
    const int wid = tid >> 5, lane = tid & 31;
    const int m_warp = (wid >> 1) * 64, n_warp = (wid & 1) * 64;
    const int n0 = blockIdx.x * 128, m0 = blockIdx.y * 128;

    float acc[4][8][4];
#pragma unroll
    for (int i = 0; i < 4; i++)
#pragma unroll
        for (int j = 0; j < 8; j++)
#pragma unroll
            for (int k = 0; k < 4; k++) acc[i][j][k] = 0.f;

    gemm_mainloop_mma(g_ATT, g_WpT, m0, n0, smem_u, tid, m_warp, n_warp, acc);

    const int gg = lane >> 2, tig = lane & 3;
#pragma unroll
    for (int mt = 0; mt < 4; mt++) {
#pragma unroll
        for (int nt = 0; nt < 8; nt++) {
            int col = n0 + n_warp + nt * 8 + tig * 2;
            float bx = bias[col], by = bias[col + 1];
#pragma unroll
            for (int rr = 0; rr < 2; rr++) {
                int m = m0 + m_warp + mt * 16 + gg + rr * 8;
                float2 v;
                v.x = acc[mt][nt][rr * 2 + 0] + bx;
                v.y = acc[mt][nt][rr * 2 + 1] + by;
                *(float2*)(out + (size_t)m * C_ + col) = v;
            }
        }
    }
}

// =====================================================================
// preprocessing: fp32 -> fp16; also zeroes g_meanV for the fused reduction
// =====================================================================
__global__ void to_half_kernel(const float* __restrict__ X,
                               __half* __restrict__ Y, int n4)
{
    int idx = blockIdx.x * blockDim.x + threadIdx.x;
    if (idx < B_ * H_ * HD_ / 4)
        *(float4*)(g_meanV + 4 * idx) = make_float4(0.f, 0.f, 0.f, 0.f);
    if (idx >= n4) return;
    float4 v = ((const float4*)X)[idx];
    __half2* py = (__half2*)(Y + 4 * (size_t)idx);
    py[0] = __floats2half2_rn(v.x, v.y);
    py[1] = __floats2half2_rn(v.z, v.w);
}

// z=0: W_attn [768,2304] -> g_WaT;  z=1: W_proj [768,768] -> g_WpT
__global__ void transpose_both_kernel(const float* __restrict__ Wa,
                                      const float* __restrict__ Wp,
                                      __half* __restrict__ Ta,
                                      __half* __restrict__ Tp)
{
    __shared__ float tile[32][33];
    const int z = blockIdx.z;
    const int N = z ? C_ : N3C;
    if (blockIdx.x * 32 >= N) return;
    const float* W = z ? Wp : Wa;
    __half* Th = z ? Tp : Ta;
    const int K = C_;
    const int nb = blockIdx.x * 32, kb = blockIdx.y * 32;
    const int tx = threadIdx.x, ty = threadIdx.y;  // 32 x 8
#pragma unroll
    for (int i = 0; i < 32; i += 8)
        tile[ty + i][tx] = W[(size_t)(kb + ty + i) * N + nb + tx];
    __syncthreads();
#pragma unroll
    for (int i = 0; i < 32; i += 8) {
        int n = nb + ty + i, k = kb + tx;
        Th[(size_t)n * K + k] = __float2half_rn(tile[tx][ty + i]);
    }
}

// =====================================================================
// Tensor-core flash attention: QT=128, 8 warps, fp16, 3-stage K/V,
// Q fragments hoisted to registers (loop-invariant)
// smem: Q 16KB | 3 stages x {K,V} 16KB = 64KB
// =====================================================================
#define ATTN_SMEM 65536

__device__ __forceinline__ void attn_load_kv(const __half* gk, const __half* gv,
                                             uint32_t uK, uint32_t uV, int tid)
{
#pragma unroll
    for (int i = 0; i < 2; i++) {
        int q = tid + i * 256;        // 512 chunks per 8KB tile
        int row = q >> 3, c = q & 7;
        uint32_t off = qkoff(row, c);
        cp16(uK + off, gk + (size_t)row * 64 + c * 8);
        cp16(uV + off, gv + (size_t)row * 64 + c * 8);
    }
}

__global__ void __launch_bounds__(256, 2)
attn_mma_kernel(const int* __restrict__ mask)
{
    extern __shared__ char smem[];
    const uint32_t su = smem_to_u32(smem);
    const uint32_t uQ = su;
    // stage s: K at 16384 + s*16384, V at 24576 + s*16384

    const int tid = threadIdx.x;
    const int w = tid >> 5, lane = tid & 31;
    const int g = lane >> 2, tig = lane & 3;
    const int qq = (int)gridDim.x - 1 - blockIdx.x;   // heavy tiles first
    const int bh = blockIdx.y;
    const int b = bh / H_, h = bh - b * H_;
    const int q0 = qq * 128;
    const int NK = 2 * qq + 2;

    const __half* gq = g_Qh + ((size_t)bh * T_ + q0) * HD_;
    const __half* gk_bh = g_Kh + (size_t)bh * T_ * HD_;
    const __half* gv_bh = g_Vh + (size_t)bh * T_ * HD_;

    // ---- prologue: Q tile + KV0 (group0), KV1 (group1) ----
#pragma unroll
    for (int i = 0; i < 4; i++) {
        int q = tid + i * 256;
        int row = q >> 3, c = q & 7;
        cp16(uQ + qkoff(row, c), gq + (size_t)row * 64 + c * 8);
    }
    attn_load_kv(gk_bh, gv_bh, su + 16384, su + 24576, tid);
    CP_COMMIT();
    attn_load_kv(gk_bh + 64 * HD_, gv_bh + 64 * HD_,
                 su + 16384 + 16384, su + 24576 + 16384, tid);
    CP_COMMIT();

    float o[8][4];
#pragma unroll
    for (int i = 0; i < 8; i++)
#pragma unroll
        for (int j = 0; j < 4; j++) o[i][j] = 0.f;
    float m0 = -1e30f, m1 = -1e30f, l0 = 0.f, l1 = 0.f;

    const int a_row = w * 16 + (lane & 15);     // Q row 0..127
    const int a_kh = (lane >> 4) & 1;
    const int b_r = (lane & 7) + ((lane >> 4) & 1) * 8;
    const int b_kh = (lane >> 3) & 1;
    // V trans-fragment lane addressing (t-row / d-chunk)
    const int vt_r = (lane & 7) + ((lane >> 3) & 1) * 8;
    const int vd_c = (lane >> 4) & 1;

    // ---- wait group0 (Q + KV0), hoist Q fragments to registers ----
    CP_WAIT1();
    __syncthreads();
    uint32_t qf[4][4];
#pragma unroll
    for (int ks = 0; ks < 4; ks++)
        ldmx4(qf[ks], uQ + qkoff(a_row, ks * 2 + a_kh));

#pragma unroll 1
    for (int kt = 0; kt < NK; kt++) {
        if (kt > 0) {
            CP_WAIT1();        // stage kt resident
            __syncthreads();   // all threads done with stage kt-1
        }
        if (kt + 2 < NK)
            attn_load_kv(gk_bh + (size_t)(kt + 2) * 64 * HD_,
                         gv_bh + (size_t)(kt + 2) * 64 * HD_,
                         su + 16384 + ((kt + 2) % 3) * 16384,
                         su + 24576 + ((kt + 2) % 3) * 16384, tid);
        CP_COMMIT();           // always commit (empty at tail)
        const uint32_t uK = su + 16384 + (kt % 3) * 16384;
        const uint32_t uV = su + 24576 + (kt % 3) * 16384;

        // ---- S = Q K^T (m16 x n64, k=64), Q frags in registers ----
        float s[8][4];
#pragma unroll
        for (int i = 0; i < 8; i++)
#pragma unroll
            for (int j = 0; j < 4; j++) s[i][j] = 0.f;

#pragma unroll
        for (int ks = 0; ks < 4; ks++) {
#pragma unroll
            for (int np = 0; np < 4; np++) {
                uint32_t kb[4];
                ldmx4(kb, uK + qkoff(np * 16 + b_r, ks * 2 + b_kh));
                mma_f16(s[np * 2], qf[ks], kb[0], kb[1]);
                mma_f16(s[np * 2 + 1], qf[ks], kb[2], kb[3]);
            }
        }

        // causal mask when this k-tile crosses the warp's diagonal
        if (kt * 64 + 63 > q0 + w * 16) {
            const int r0 = q0 + w * 16 + g, r1 = r0 + 8;
            const int cb = kt * 64 + tig * 2;
#pragma unroll
            for (int nt = 0; nt < 8; nt++) {
                int c = cb + nt * 8;
                if (c > r0)     s[nt][0] = -1e30f;
                if (c + 1 > r0) s[nt][1] = -1e30f;
                if (c > r1)     s[nt][2] = -1e30f;
                if (c + 1 > r1) s[nt][3] = -1e30f;
            }
        }

        // ---- online softmax (base-2; log2e folded into Q) ----
        float mx0 = -1e30f, mx1 = -1e30f;
#pragma unroll
        for (int nt = 0; nt < 8; nt++) {
            mx0 = fmaxf(mx0, fmaxf(s[nt][0], s[nt][1]));
            mx1 = fmaxf(mx1, fmaxf(s[nt][2], s[nt][3]));
        }
        mx0 = fmaxf(mx0, __shfl_xor_sync(0xffffffffu, mx0, 1));
        mx0 = fmaxf(mx0, __shfl_xor_sync(0xffffffffu, mx0, 2));
        mx1 = fmaxf(mx1, __shfl_xor_sync(0xffffffffu, mx1, 1));
        mx1 = fmaxf(mx1, __shfl_xor_sync(0xffffffffu, mx1, 2));
        float mn0 = fmaxf(m0, mx0), mn1 = fmaxf(m1, mx1);
        float cr0 = ex2f(m0 - mn0), cr1 = ex2f(m1 - mn1);
        m0 = mn0; m1 = mn1;

        float sum0 = 0.f, sum1 = 0.f;
#pragma unroll
        for (int nt = 0; nt < 8; nt++) {
            s[nt][0] = ex2f(s[nt][0] - mn0);
            s[nt][1] = ex2f(s[nt][1] - mn0);
            s[nt][2] = ex2f(s[nt][2] - mn1);
            s[nt][3] = ex2f(s[nt][3] - mn1);
            sum0 += s[nt][0] + s[nt][1];
            sum1 += s[nt][2] + s[nt][3];
        }
        sum0 += __shfl_xor_sync(0xffffffffu, sum0, 1);
        sum0 += __shfl_xor_sync(0xffffffffu, sum0, 2);
        sum1 += __shfl_xor_sync(0xffffffffu, sum1, 1);
        sum1 += __shfl_xor_sync(0xffffffffu, sum1, 2);
        l0 = l0 * cr0 + sum0;
        l1 = l1 * cr1 + sum1;

#pragma unroll
        for (int nt = 0; nt < 8; nt++) {
            o[nt][0] *= cr0; o[nt][1] *= cr0;
            o[nt][2] *= cr1; o[nt][3] *= cr1;
        }

        // ---- O += P V  (V B-frags via ldmatrix.trans on [t][d] tile) ----
#pragma unroll
        for (int kc = 0; kc < 4; kc++) {
            const float* sa = s[2 * kc];
            const float* sb = s[2 * kc + 1];
            uint32_t pah[4];
            pah[0] = pkh2(sa[0], sa[1]);
            pah[1] = pkh2(sa[2], sa[3]);
            pah[2] = pkh2(sb[0], sb[1]);
            pah[3] = pkh2(sb[2], sb[3]);
#pragma unroll
            for (int np = 0; np < 4; np++) {
                uint32_t vb[4];
                ldmx4t(vb, uV + qkoff(kc * 16 + vt_r, np * 2 + vd_c));
                mma_f16(o[np * 2], pah, vb[0], vb[1]);
                mma_f16(o[np * 2 + 1], pah, vb[2], vb[3]);
            }
        }
    }

    // ---- epilogue: normalize, masked-row override (meanV sum/1024), store --
    const float il0 = 1.f / l0, il1 = 1.f / l1;
    const float MEAN_SCL = 1.0f / 1024.0f;
    const int r0g = q0 + w * 16 + g, r1g = r0g + 8;
    const bool mk0 = (mask[b * T_ + r0g] == 0);
    const bool mk1 = (mask[b * T_ + r1g] == 0);
    const size_t ob0 = ((size_t)b * T_ + r0g) * C_ + h * 64;
    const size_t ob1 = ((size_t)b * T_ + r1g) * C_ + h * 64;
#pragma unroll
    for (int nt = 0; nt < 8; nt++) {
        int d = nt * 8 + tig * 2;
        float y0 = o[nt][0] * il0, y1 = o[nt][1] * il0;
        if (mk0) {
            y0 = g_meanV[bh * 64 + d] * MEAN_SCL;
            y1 = g_meanV[bh * 64 + d + 1] * MEAN_SCL;
        }
        *(uint32_t*)(g_ATT + ob0 + d) = pkh2(y0, y1);
        float z0 = o[nt][2] * il1, z1 = o[nt][3] * il1;
        if (mk1) {
            z0 = g_meanV[bh * 64 + d] * MEAN_SCL;
            z1 = g_meanV[bh * 64 + d + 1] * MEAN_SCL;
        }
        *(uint32_t*)(g_ATT + ob1 + d) = pkh2(z0, z1);
    }
}

// =====================================================================
// launcher
// =====================================================================
extern "C" void kernel_launch(void* const* d_in, const int* in_sizes, int n_in,
                              void* d_out, int out_size)
{
    const float* x      = (const float*)d_in[0];
    const int*   mask   = (const int*)d_in[1];
    const float* W_attn = (const float*)d_in[2];
    const float* b_attn = (const float*)d_in[3];
    const float* W_proj = (const float*)d_in[4];
    const float* b_proj = (const float*)d_in[5];
    float* out = (float*)d_out;

    __half *p_X16, *p_WaT, *p_WpT;
    cudaGetSymbolAddress((void**)&p_X16, g_X16);
    cudaGetSymbolAddress((void**)&p_WaT, g_WaT);
    cudaGetSymbolAddress((void**)&p_WpT, g_WpT);

    // 0) fp32 -> fp16 preprocessing (+ meanV zeroing; both transposes fused)
    to_half_kernel<<<(M_ * C_ / 4 + 255) / 256, 256>>>(x, p_X16, M_ * C_ / 4);
    transpose_both_kernel<<<dim3(N3C / 32, C_ / 32, 2), dim3(32, 8)>>>(
        W_attn, W_proj, p_WaT, p_WpT);

    // 1) QKV projection (64x64 warp tiles, 3-stage) + fused meanV reduction
    {
        cudaFuncSetAttribute(gemm_qkv_mma,
                             cudaFuncAttributeMaxDynamicSharedMemorySize, GEMM_SMEM);
        dim3 grid(N3C / 128, M_ / 128);
        gemm_qkv_mma<<<grid, 128, GEMM_SMEM>>>(b_attn);
    }
    // 2) causal flash attention (QT=128, Q-frag hoisted, 3-stage K/V)
    {
        cudaFuncSetAttribute(attn_mma_kernel,
                             cudaFuncAttributeMaxDynamicSharedMemorySize, ATTN_SMEM);
        dim3 grid(T_ / 128, B_ * H_);
        attn_mma_kernel<<<grid, 256, ATTN_SMEM>>>(mask);
    }
    // 3) output projection via mma.sync fp16 (64x64 warp tiles, 3-stage)
    {
        cudaFuncSetAttribute(gemm_proj_mma,
                             cudaFuncAttributeMaxDynamicSharedMemorySize, GEMM_SMEM);
        dim3 grid(C_ / 128, M_ / 128);
        gemm_proj_mma<<<grid, 128, GEMM_SMEM>>>(b_proj, out);
    }
}